// round 1
// baseline (speedup 1.0000x reference)
#include <cuda_runtime.h>

#define NN 10000
#define NE 160000
#define NP 20000
#define DIN 256
#define DH  512
#define DOUT 512
#define DX  1024
#define DZ  2048
#define NC  40
#define EPSV 1e-5f

// ---------------- static scratch ----------------
#define OF_A1   0L
#define OF_W1   (OF_A1  + (long)NN*DH)       // a1cat [NN,512]
#define OF_H    (OF_W1  + (long)DH*DH)       // w1cat [512,512]
#define OF_HBN  (OF_H   + (long)NN*DH)       // h     [NN,512]
#define OF_A2   (OF_HBN + (long)NN*DH)       // hbn   [NN,512]
#define OF_W2   (OF_A2  + (long)NN*DX)       // a2cat [NN,1024]
#define OF_BNX  (OF_W2  + (long)DOUT*DX)     // w2cat [512,1024]
#define OF_ZW   (OF_BNX + (long)NN*DOUT)     // bnx   [NN,512]
#define OF_Z2   (OF_ZW  + (long)NP*DZ)       // zw    [NP,2048]
#define OF_WPE  (OF_Z2  + (long)NP*DZ)       // z2    [NP,2048]
#define OF_BPE  (OF_WPE + 42L*DZ)
#define OF_HEADS (OF_BPE + 64L)
#define OF_T    (OF_HEADS + (long)NP*42)     // heads [NP,42]
#define OF_X1R  (OF_T   + (long)NN*DOUT)
#define OF_SC1  (OF_X1R + (long)NN*DOUT)
#define OF_SH1  (OF_SC1 + 512L)
#define OF_SC2  (OF_SH1 + 512L)
#define OF_SH2  (OF_SC2 + 512L)
#define F_TOTAL (OF_SH2 + 512L)

__device__ __align__(256) float g_f[F_TOTAL];

#define OI_DEG 0
#define OI_OFF 10016
#define OI_CUR 20032
#define OI_CSR 30048
#define OI_LS  190048
#define OI_LD  200048
#define I_TOTAL 210064
__device__ __align__(256) int g_i[I_TOTAL];

// ---------------- small utility kernels ----------------
__global__ void k_init(int* deg, int* ls, int* ld) {
    int i = blockIdx.x * blockDim.x + threadIdx.x;
    if (i < NN) { deg[i] = 0; ls[i] = -1; ld[i] = -1; }
}

__global__ void k_deg(const int* __restrict__ dst, int* deg) {
    int e = blockIdx.x * blockDim.x + threadIdx.x;
    if (e < NE) atomicAdd(&deg[dst[e]], 1);
}

__global__ void k_scan(const int* __restrict__ deg, int* off, int* cur) {
    __shared__ int s[1024];
    __shared__ int carry;
    int tid = threadIdx.x;
    if (tid == 0) carry = 0;
    __syncthreads();
    for (int base = 0; base < NN; base += 1024) {
        int i = base + tid;
        int v = (i < NN) ? deg[i] : 0;
        s[tid] = v;
        __syncthreads();
        for (int o = 1; o < 1024; o <<= 1) {
            int t = (tid >= o) ? s[tid - o] : 0;
            __syncthreads();
            s[tid] += t;
            __syncthreads();
        }
        int excl = s[tid] - v;
        int c0 = carry;
        if (i < NN) { off[i] = c0 + excl; cur[i] = c0 + excl; }
        __syncthreads();
        if (tid == 0) carry = c0 + s[1023];
        __syncthreads();
    }
    if (tid == 0) off[NN] = carry;
}

__global__ void k_fill(const int* __restrict__ src, const int* __restrict__ dst,
                       int* cur, int* csr) {
    int e = blockIdx.x * blockDim.x + threadIdx.x;
    if (e < NE) {
        int slot = atomicAdd(&cur[dst[e]], 1);
        csr[slot] = src[e];
    }
}

__global__ void k_lastidx(const int* __restrict__ ps, const int* __restrict__ pd,
                          int* ls, int* ld) {
    int i = blockIdx.x * blockDim.x + threadIdx.x;
    if (i < NP) { atomicMax(&ls[ps[i]], i); atomicMax(&ld[pd[i]], i); }
}

// per-node neighbor max + optional self-copy into [agg | self] layout
__global__ void k_agg(const float* __restrict__ X, int D, const int* __restrict__ off,
                      const int* __restrict__ csr, float* __restrict__ out, int ldo,
                      int copyself) {
    int n = blockIdx.x;
    int s = off[n], e = off[n + 1];
    int nv = D >> 2;
    const float4* X4 = (const float4*)X;
    for (int c = threadIdx.x; c < nv; c += blockDim.x) {
        float4 m = make_float4(0.f, 0.f, 0.f, 0.f);
        if (e > s) {
            m = __ldg(&X4[(long)csr[s] * nv + c]);
            for (int i = s + 1; i < e; i++) {
                float4 v = __ldg(&X4[(long)csr[i] * nv + c]);
                m.x = fmaxf(m.x, v.x); m.y = fmaxf(m.y, v.y);
                m.z = fmaxf(m.z, v.z); m.w = fmaxf(m.w, v.w);
            }
        }
        ((float4*)(out + (long)n * ldo))[c] = m;
        if (copyself)
            ((float4*)(out + (long)n * ldo + D))[c] = __ldg(&X4[(long)n * nv + c]);
    }
}

__global__ void k_cat(const float* __restrict__ A, const float* __restrict__ B,
                      float* __restrict__ D, int rows, int ka, int kb) {
    int kc = ka + kb;
    int total = rows * kc;
    for (int idx = blockIdx.x * blockDim.x + threadIdx.x; idx < total;
         idx += gridDim.x * blockDim.x) {
        int r = idx / kc, c = idx % kc;
        D[idx] = (c < ka) ? A[(long)r * ka + c] : B[(long)r * kb + (c - ka)];
    }
}

__global__ void k_wpe(const float* __restrict__ Wpc, const float* __restrict__ bpc,
                      const float* __restrict__ We, const float* __restrict__ be,
                      float* wpe, float* bpe) {
    for (int idx = blockIdx.x * blockDim.x + threadIdx.x; idx < 42 * DZ;
         idx += gridDim.x * blockDim.x) {
        int r = idx / DZ, k = idx % DZ;
        wpe[idx] = (r < 40) ? Wpc[(long)r * DZ + k] : We[(long)(r - 40) * DZ + k];
        if (idx < 42) bpe[idx] = (idx < 40) ? bpc[idx] : be[idx - 40];
    }
}

// ---------------- reductions / norms ----------------
__device__ __forceinline__ float blk_sum(float v, float* sm) {
    __syncthreads();
    int lane = threadIdx.x & 31, w = threadIdx.x >> 5;
#pragma unroll
    for (int o = 16; o; o >>= 1) v += __shfl_down_sync(0xffffffffu, v, o);
    if (lane == 0) sm[w] = v;
    __syncthreads();
    if (w == 0) {
        int nw = (blockDim.x + 31) >> 5;
        float t = (lane < nw) ? sm[lane] : 0.f;
#pragma unroll
        for (int o = 16; o; o >>= 1) t += __shfl_down_sync(0xffffffffu, t, o);
        if (lane == 0) sm[0] = t;
    }
    __syncthreads();
    return sm[0];
}

__global__ void k_bnstats(const float* __restrict__ H, int M, int C,
                          const float* __restrict__ g, const float* __restrict__ b,
                          float* scale, float* shift) {
    __shared__ float sm[32];
    int c = blockIdx.x;
    float s = 0.f;
    for (int r = threadIdx.x; r < M; r += blockDim.x) s += H[(long)r * C + c];
    float mu = blk_sum(s, sm) / (float)M;
    float q = 0.f;
    for (int r = threadIdx.x; r < M; r += blockDim.x) {
        float d = H[(long)r * C + c] - mu;
        q += d * d;
    }
    float var = blk_sum(q, sm) / (float)M;
    if (threadIdx.x == 0) {
        float sc = g[c] * rsqrtf(var + EPSV);
        scale[c] = sc;
        shift[c] = b[c] - mu * sc;
    }
}

__global__ void k_bnapply(const float* __restrict__ H, const float* __restrict__ scale,
                          const float* __restrict__ shift, float* __restrict__ out,
                          float* __restrict__ out2, int M, int C, int ldo2) {
    int total = M * C;
    for (int idx = blockIdx.x * blockDim.x + threadIdx.x; idx < total;
         idx += gridDim.x * blockDim.x) {
        int c = idx % C;
        float v = H[idx] * scale[c] + shift[c];
        out[idx] = v;
        if (out2) out2[(long)(idx / C) * ldo2 + c] = v;
    }
}

__global__ void k_buildx(const float* __restrict__ bnx, const float* __restrict__ h1c,
                         const float* __restrict__ h2c, const int* __restrict__ ls,
                         const int* __restrict__ ld, float* __restrict__ xout) {
    int total = NN * (DOUT / 4);
    for (int idx = blockIdx.x * blockDim.x + threadIdx.x; idx < total;
         idx += gridDim.x * blockDim.x) {
        int n = idx >> 7;
        int c4 = idx & 127;
        float4 sec = ((const float4*)(bnx + (long)n * DOUT))[c4];
        float4 fir;
        int li = ld[n];
        if (li >= 0) fir = ((const float4*)(h2c + (long)li * DOUT))[c4];
        else {
            int si = ls[n];
            fir = (si >= 0) ? ((const float4*)(h1c + (long)si * DOUT))[c4] : sec;
        }
        ((float4*)(xout + (long)n * DX))[c4] = fir;
        ((float4*)(xout + (long)n * DX + DOUT))[c4] = sec;
    }
}

// ---------------- GEMM: C[M,N] = A[M,K] @ B[N,K]^T + bias ----------------
// 128x128 block tile, BK=8, 8x8 per-thread microtile, 256 threads.
// GATHER variant: row m of A is x[gs[m]] (k<1024) | x[gd[m]] (k>=1024), x rows = DX wide.
template <bool GATHER>
__global__ void __launch_bounds__(256)
k_gemm(const float* __restrict__ A, const int* __restrict__ gs,
       const int* __restrict__ gd, const float* __restrict__ B,
       const float* __restrict__ bias, float* __restrict__ C,
       int M, int N, int K, int ldc) {
    __shared__ float As[8][128];
    __shared__ float Bs[8][128];
    int tid = threadIdx.x;
    int arow = tid >> 1;
    int acol = (tid & 1) << 2;
    int tr = tid >> 4;
    int tc = tid & 15;
    long gm = (long)blockIdx.y * 128 + arow;
    long gn = (long)blockIdx.x * 128 + arow;
    float acc[8][8];
#pragma unroll
    for (int i = 0; i < 8; i++)
#pragma unroll
        for (int j = 0; j < 8; j++) acc[i][j] = 0.f;

    for (int k0 = 0; k0 < K; k0 += 8) {
        float4 av = make_float4(0.f, 0.f, 0.f, 0.f);
        float4 bv = make_float4(0.f, 0.f, 0.f, 0.f);
        if (gm < M) {
            const float* ap;
            if (GATHER) {
                int row = (k0 < 1024) ? gs[gm] : gd[gm];
                int kk = (k0 < 1024) ? k0 : (k0 - 1024);
                ap = A + (long)row * DX + kk + acol;
            } else {
                ap = A + gm * K + k0 + acol;
            }
            av = *(const float4*)ap;
        }
        if (gn < N) bv = *(const float4*)(B + gn * K + k0 + acol);
        __syncthreads();
        As[acol + 0][arow] = av.x; As[acol + 1][arow] = av.y;
        As[acol + 2][arow] = av.z; As[acol + 3][arow] = av.w;
        Bs[acol + 0][arow] = bv.x; Bs[acol + 1][arow] = bv.y;
        Bs[acol + 2][arow] = bv.z; Bs[acol + 3][arow] = bv.w;
        __syncthreads();
#pragma unroll
        for (int k = 0; k < 8; k++) {
            float4 a0 = *(const float4*)&As[k][tr * 8];
            float4 a1 = *(const float4*)&As[k][tr * 8 + 4];
            float4 b0 = *(const float4*)&Bs[k][tc * 8];
            float4 b1 = *(const float4*)&Bs[k][tc * 8 + 4];
            float ra[8] = {a0.x, a0.y, a0.z, a0.w, a1.x, a1.y, a1.z, a1.w};
            float rb[8] = {b0.x, b0.y, b0.z, b0.w, b1.x, b1.y, b1.z, b1.w};
#pragma unroll
            for (int i = 0; i < 8; i++)
#pragma unroll
                for (int j = 0; j < 8; j++) acc[i][j] += ra[i] * rb[j];
        }
    }
    int mb = blockIdx.y * 128 + tr * 8;
    int nb = blockIdx.x * 128 + tc * 8;
#pragma unroll
    for (int i = 0; i < 8; i++) {
        int m = mb + i;
        if (m < M) {
#pragma unroll
            for (int j = 0; j < 8; j++) {
                int n = nb + j;
                if (n < N) C[(long)m * ldc + n] = acc[i][j] + bias[n];
            }
        }
    }
}

// ---------------- LayerNorm + ReLU (row-wise) ----------------
__global__ void __launch_bounds__(256)
k_pairln(const float* __restrict__ ZW, const float* __restrict__ g,
         const float* __restrict__ b, float* __restrict__ Z2) {
    __shared__ float sm[32];
    long r = blockIdx.x;
    const float4* row = (const float4*)(ZW + r * DZ);
    int t = threadIdx.x;
    float4 v0 = row[t], v1 = row[t + 256];
    float s = v0.x + v0.y + v0.z + v0.w + v1.x + v1.y + v1.z + v1.w;
    float mu = blk_sum(s, sm) * (1.0f / DZ);
    float q = (v0.x - mu) * (v0.x - mu) + (v0.y - mu) * (v0.y - mu) +
              (v0.z - mu) * (v0.z - mu) + (v0.w - mu) * (v0.w - mu) +
              (v1.x - mu) * (v1.x - mu) + (v1.y - mu) * (v1.y - mu) +
              (v1.z - mu) * (v1.z - mu) + (v1.w - mu) * (v1.w - mu);
    float var = blk_sum(q, sm) * (1.0f / DZ);
    float rs = rsqrtf(var + EPSV);
    const float4* g4 = (const float4*)g;
    const float4* b4 = (const float4*)b;
    float4* o = (float4*)(Z2 + r * DZ);
    float4 gg = g4[t], bb = b4[t], w;
    w.x = fmaxf((v0.x - mu) * rs * gg.x + bb.x, 0.f);
    w.y = fmaxf((v0.y - mu) * rs * gg.y + bb.y, 0.f);
    w.z = fmaxf((v0.z - mu) * rs * gg.z + bb.z, 0.f);
    w.w = fmaxf((v0.w - mu) * rs * gg.w + bb.w, 0.f);
    o[t] = w;
    gg = g4[t + 256]; bb = b4[t + 256];
    w.x = fmaxf((v1.x - mu) * rs * gg.x + bb.x, 0.f);
    w.y = fmaxf((v1.y - mu) * rs * gg.y + bb.y, 0.f);
    w.z = fmaxf((v1.z - mu) * rs * gg.z + bb.z, 0.f);
    w.w = fmaxf((v1.w - mu) * rs * gg.w + bb.w, 0.f);
    o[t + 256] = w;
}

__global__ void __launch_bounds__(128)
k_nodeln(const float* __restrict__ T, const float* __restrict__ g,
         const float* __restrict__ b, float* __restrict__ O) {
    __shared__ float sm[32];
    long r = blockIdx.x;
    const float4* row = (const float4*)(T + r * DOUT);
    int t = threadIdx.x;
    float4 v = row[t];
    float s = v.x + v.y + v.z + v.w;
    float mu = blk_sum(s, sm) * (1.0f / DOUT);
    float q = (v.x - mu) * (v.x - mu) + (v.y - mu) * (v.y - mu) +
              (v.z - mu) * (v.z - mu) + (v.w - mu) * (v.w - mu);
    float var = blk_sum(q, sm) * (1.0f / DOUT);
    float rs = rsqrtf(var + EPSV);
    float4 gg = ((const float4*)g)[t], bb = ((const float4*)b)[t], w;
    w.x = fmaxf((v.x - mu) * rs * gg.x + bb.x, 0.f);
    w.y = fmaxf((v.y - mu) * rs * gg.y + bb.y, 0.f);
    w.z = fmaxf((v.z - mu) * rs * gg.z + bb.z, 0.f);
    w.w = fmaxf((v.w - mu) * rs * gg.w + bb.w, 0.f);
    ((float4*)(O + r * DOUT))[t] = w;
}

__global__ void k_split(const float* __restrict__ heads, float* __restrict__ pl,
                        float* __restrict__ pc) {
    int total = NP * 42;
    for (int idx = blockIdx.x * blockDim.x + threadIdx.x; idx < total;
         idx += gridDim.x * blockDim.x) {
        int r = idx / 42, c = idx % 42;
        float v = heads[idx];
        if (c < 40) pl[(long)r * 40 + c] = v;
        else pc[(long)r * 2 + (c - 40)] = v;
    }
}

// ---------------- host ----------------
extern "C" void kernel_launch(void* const* d_in, const int* in_sizes, int n_in,
                              void* d_out, int out_size) {
    const float* x_feat = (const float*)d_in[0];
    const int*   eidx   = (const int*)d_in[1];
    const int*   pidx   = (const int*)d_in[2];
    const float* h1c = (const float*)d_in[3];
    const float* h2c = (const float*)d_in[4];
    const float* W1l = (const float*)d_in[5];
    const float* b1l = (const float*)d_in[6];
    const float* W1r = (const float*)d_in[7];
    const float* bn1g = (const float*)d_in[8];
    const float* bn1b = (const float*)d_in[9];
    const float* W2l = (const float*)d_in[10];
    const float* b2l = (const float*)d_in[11];
    const float* W2r = (const float*)d_in[12];
    const float* bng = (const float*)d_in[13];
    const float* bnb = (const float*)d_in[14];
    const float* Wp  = (const float*)d_in[15];
    const float* bp  = (const float*)d_in[16];
    const float* plng = (const float*)d_in[17];
    const float* plnb = (const float*)d_in[18];
    const float* Wpc = (const float*)d_in[19];
    const float* bpc = (const float*)d_in[20];
    const float* We  = (const float*)d_in[21];
    const float* be  = (const float*)d_in[22];
    const float* Wnm = (const float*)d_in[23];
    const float* bnm = (const float*)d_in[24];
    const float* nlng = (const float*)d_in[25];
    const float* nlnb = (const float*)d_in[26];
    const float* Wnc = (const float*)d_in[27];
    const float* bnc = (const float*)d_in[28];

    float* out = (float*)d_out;
    float* out_node = out;                       // [NN,40]
    float* out_pl   = out + (long)NN * NC;       // [NP,40]
    float* out_pc   = out_pl + (long)NP * NC;    // [NP,2]
    float* out_x    = out_pc + (long)NP * 2;     // [NN,1024]
    float* out_gnn  = out_x + (long)NN * DX;     // [NN,512]

    float* F; int* I;
    cudaGetSymbolAddress((void**)&F, g_f);
    cudaGetSymbolAddress((void**)&I, g_i);
    float* a1   = F + OF_A1;
    float* w1   = F + OF_W1;
    float* h    = F + OF_H;
    float* hbn  = F + OF_HBN;
    float* a2   = F + OF_A2;
    float* w2   = F + OF_W2;
    float* bnx  = F + OF_BNX;
    float* zw   = F + OF_ZW;
    float* z2   = F + OF_Z2;
    float* wpe  = F + OF_WPE;
    float* bpe  = F + OF_BPE;
    float* heads = F + OF_HEADS;
    float* tbuf = F + OF_T;
    float* x1r  = F + OF_X1R;
    float* sc1  = F + OF_SC1;
    float* sh1  = F + OF_SH1;
    float* sc2  = F + OF_SC2;
    float* sh2  = F + OF_SH2;
    int* deg = I + OI_DEG;
    int* off = I + OI_OFF;
    int* cur = I + OI_CUR;
    int* csr = I + OI_CSR;
    int* ls  = I + OI_LS;
    int* ld  = I + OI_LD;
    const int* esrc = eidx;
    const int* edst = eidx + NE;
    const int* psrc = pidx;
    const int* pdst = pidx + NP;

    // CSR build + scatter-last-index
    k_init<<<(NN + 255) / 256, 256>>>(deg, ls, ld);
    k_deg<<<(NE + 255) / 256, 256>>>(edst, deg);
    k_scan<<<1, 1024>>>(deg, off, cur);
    k_fill<<<(NE + 255) / 256, 256>>>(esrc, edst, cur, csr);
    k_lastidx<<<(NP + 255) / 256, 256>>>(psrc, pdst, ls, ld);

    // weight concats
    k_cat<<<512, 256>>>(W1l, W1r, w1, DH, DIN, DIN);
    k_cat<<<1024, 256>>>(W2l, W2r, w2, DOUT, DH, DH);
    k_wpe<<<336, 256>>>(Wpc, bpc, We, be, wpe, bpe);

    // layer 1: agg + gemm + bn
    k_agg<<<NN, 64>>>(x_feat, DIN, off, csr, a1, DH, 1);
    {
        dim3 g(DH / 128, (NN + 127) / 128);
        k_gemm<false><<<g, 256>>>(a1, nullptr, nullptr, w1, b1l, h, NN, DH, DH, DH);
    }
    k_bnstats<<<DH, 256>>>(h, NN, DH, bn1g, bn1b, sc1, sh1);
    k_bnapply<<<2048, 256>>>(h, sc1, sh1, hbn, a2 + DH, NN, DH, DX);

    // layer 2: agg + gemm (-> gnn_x output) + bn
    k_agg<<<NN, 128>>>(hbn, DH, off, csr, a2, DX, 0);
    {
        dim3 g(DOUT / 128, (NN + 127) / 128);
        k_gemm<false><<<g, 256>>>(a2, nullptr, nullptr, w2, b2l, out_gnn, NN, DOUT, DX, DOUT);
    }
    k_bnstats<<<DOUT, 256>>>(out_gnn, NN, DOUT, bng, bnb, sc2, sh2);
    k_bnapply<<<2048, 256>>>(out_gnn, sc2, sh2, bnx, nullptr, NN, DOUT, 0);

    // x with compensate scatter (-> x output)
    k_buildx<<<2048, 256>>>(bnx, h1c, h2c, ls, ld, out_x);

    // pair branch: big gathered GEMM -> LN+relu -> heads
    {
        dim3 g(DZ / 128, (NP + 127) / 128);
        k_gemm<true><<<g, 256>>>(out_x, psrc, pdst, Wp, bp, zw, NP, DZ, DZ, DZ);
    }
    k_pairln<<<NP, 256>>>(zw, plng, plnb, z2);
    {
        dim3 g(1, (NP + 127) / 128);
        k_gemm<false><<<g, 256>>>(z2, nullptr, nullptr, wpe, bpe, heads, NP, 42, DZ, 42);
    }
    k_split<<<2048, 256>>>(heads, out_pl, out_pc);

    // node branch
    {
        dim3 g(DOUT / 128, (NN + 127) / 128);
        k_gemm<false><<<g, 256>>>(out_x, nullptr, nullptr, Wnm, bnm, tbuf, NN, DOUT, DX, DOUT);
    }
    k_nodeln<<<NN, 128>>>(tbuf, nlng, nlnb, x1r);
    {
        dim3 g(1, (NN + 127) / 128);
        k_gemm<false><<<g, 256>>>(x1r, nullptr, nullptr, Wnc, bnc, out_node, NN, NC, DOUT, NC);
    }
}

// round 2
// speedup vs baseline: 1.7458x; 1.7458x over previous
#include <cuda_runtime.h>

#define NN 10000
#define NE 160000
#define NP 20000
#define DIN 256
#define DH  512
#define DOUT 512
#define DX  1024
#define DZ  2048
#define NC  40
#define EPSV 1e-5f
#define NCHUNK 40
#define CHROWS 250

// ---------------- static scratch ----------------
#define OF_A1   0L
#define OF_W1   (OF_A1  + (long)NN*DH)
#define OF_H    (OF_W1  + (long)DH*DH)
#define OF_HBN  (OF_H   + (long)NN*DH)
#define OF_A2   (OF_HBN + (long)NN*DH)
#define OF_W2   (OF_A2  + (long)NN*DX)
#define OF_BNX  (OF_W2  + (long)DOUT*DX)
#define OF_BC   (OF_BNX + (long)NN*DOUT)     // bcat [4096,1024]
#define OF_U    (OF_BC  + 4096L*DX)          // U    [NN,4096]
#define OF_Z2   (OF_U   + (long)NN*4096)     // z2   [NP,2048]
#define OF_WPE  (OF_Z2  + (long)NP*DZ)
#define OF_BPE  (OF_WPE + 42L*DZ)
#define OF_HEADS (OF_BPE + 64L)
#define OF_T    (OF_HEADS + (long)NP*48)
#define OF_X1R  (OF_T   + (long)NN*DOUT)
#define OF_PART (OF_X1R + (long)NN*DOUT)     // [NCHUNK,512,2]
#define OF_SC1  (OF_PART + 41984L)
#define OF_SH1  (OF_SC1 + 512L)
#define OF_SC2  (OF_SH1 + 512L)
#define OF_SH2  (OF_SC2 + 512L)
#define F_TOTAL (OF_SH2 + 512L)

__device__ __align__(256) float g_f[F_TOTAL];

#define OI_DEG 0
#define OI_OFF 10016
#define OI_CUR 20032
#define OI_CSR 30048
#define OI_LS  190048
#define OI_LD  200048
#define I_TOTAL 210064
__device__ __align__(256) int g_i[I_TOTAL];

// ---------------- small utility kernels ----------------
__global__ void k_init(int* deg, int* ls, int* ld) {
    int i = blockIdx.x * blockDim.x + threadIdx.x;
    if (i < NN) { deg[i] = 0; ls[i] = -1; ld[i] = -1; }
}

__global__ void k_deg(const int* __restrict__ dst, int* deg) {
    int e = blockIdx.x * blockDim.x + threadIdx.x;
    if (e < NE) atomicAdd(&deg[dst[e]], 1);
}

__global__ void k_scan(const int* __restrict__ deg, int* off, int* cur) {
    __shared__ int s[1024];
    __shared__ int carry;
    int tid = threadIdx.x;
    if (tid == 0) carry = 0;
    __syncthreads();
    for (int base = 0; base < NN; base += 1024) {
        int i = base + tid;
        int v = (i < NN) ? deg[i] : 0;
        s[tid] = v;
        __syncthreads();
        for (int o = 1; o < 1024; o <<= 1) {
            int t = (tid >= o) ? s[tid - o] : 0;
            __syncthreads();
            s[tid] += t;
            __syncthreads();
        }
        int excl = s[tid] - v;
        int c0 = carry;
        if (i < NN) { off[i] = c0 + excl; cur[i] = c0 + excl; }
        __syncthreads();
        if (tid == 0) carry = c0 + s[1023];
        __syncthreads();
    }
    if (tid == 0) off[NN] = carry;
}

__global__ void k_fill(const int* __restrict__ src, const int* __restrict__ dst,
                       int* cur, int* csr) {
    int e = blockIdx.x * blockDim.x + threadIdx.x;
    if (e < NE) {
        int slot = atomicAdd(&cur[dst[e]], 1);
        csr[slot] = src[e];
    }
}

__global__ void k_lastidx(const int* __restrict__ ps, const int* __restrict__ pd,
                          int* ls, int* ld) {
    int i = blockIdx.x * blockDim.x + threadIdx.x;
    if (i < NP) { atomicMax(&ls[ps[i]], i); atomicMax(&ld[pd[i]], i); }
}

// per-node neighbor max + optional self-copy into [agg | self] layout
__global__ void k_agg(const float* __restrict__ X, int D, const int* __restrict__ off,
                      const int* __restrict__ csr, float* __restrict__ out, int ldo,
                      int copyself) {
    int n = blockIdx.x;
    int s = off[n], e = off[n + 1];
    int nv = D >> 2;
    const float4* X4 = (const float4*)X;
    for (int c = threadIdx.x; c < nv; c += blockDim.x) {
        float4 m = make_float4(0.f, 0.f, 0.f, 0.f);
        if (e > s) {
            m = __ldg(&X4[(long)csr[s] * nv + c]);
            for (int i = s + 1; i < e; i++) {
                float4 v = __ldg(&X4[(long)csr[i] * nv + c]);
                m.x = fmaxf(m.x, v.x); m.y = fmaxf(m.y, v.y);
                m.z = fmaxf(m.z, v.z); m.w = fmaxf(m.w, v.w);
            }
        }
        ((float4*)(out + (long)n * ldo))[c] = m;
        if (copyself)
            ((float4*)(out + (long)n * ldo + D))[c] = __ldg(&X4[(long)n * nv + c]);
    }
}

__global__ void k_cat(const float* __restrict__ A, const float* __restrict__ B,
                      float* __restrict__ D, int rows, int ka, int kb) {
    int kc = ka + kb;
    int total = rows * kc;
    for (int idx = blockIdx.x * blockDim.x + threadIdx.x; idx < total;
         idx += gridDim.x * blockDim.x) {
        int r = idx / kc, c = idx % kc;
        D[idx] = (c < ka) ? A[(long)r * ka + c] : B[(long)r * kb + (c - ka)];
    }
}

__global__ void k_wpe(const float* __restrict__ Wpc, const float* __restrict__ bpc,
                      const float* __restrict__ We, const float* __restrict__ be,
                      float* wpe, float* bpe) {
    for (int idx = blockIdx.x * blockDim.x + threadIdx.x; idx < 42 * DZ;
         idx += gridDim.x * blockDim.x) {
        int r = idx / DZ, k = idx % DZ;
        wpe[idx] = (r < 40) ? Wpc[(long)r * DZ + k] : We[(long)(r - 40) * DZ + k];
        if (idx < 42) bpe[idx] = (idx < 40) ? bpc[idx] : be[idx - 40];
    }
}

// Bcat[4096,1024]: rows 0..2047 = Wp[n, 0:1024]; rows 2048.. = Wp[n-2048, 1024:2048]
__global__ void k_bcat(const float* __restrict__ Wp, float* __restrict__ Bc) {
    int total = 4096 * DX;
    for (int idx = blockIdx.x * blockDim.x + threadIdx.x; idx < total;
         idx += gridDim.x * blockDim.x) {
        int n = idx >> 10, k = idx & 1023;
        Bc[idx] = (n < 2048) ? Wp[(long)n * DZ + k]
                             : Wp[(long)(n - 2048) * DZ + 1024 + k];
    }
}

// ---------------- BN: coalesced chunked stats ----------------
__global__ void k_bnsum(const float* __restrict__ H, int M, int C,
                        float* __restrict__ part) {
    int c = blockIdx.x * blockDim.x + threadIdx.x;   // column
    int r0 = blockIdx.y * CHROWS;
    int r1 = min(r0 + CHROWS, M);
    float s = 0.f, q = 0.f;
    for (int r = r0; r < r1; r++) {
        float v = H[(long)r * C + c];
        s += v; q += v * v;
    }
    part[((long)blockIdx.y * C + c) * 2 + 0] = s;
    part[((long)blockIdx.y * C + c) * 2 + 1] = q;
}

__global__ void k_bnfin(const float* __restrict__ part, const float* __restrict__ g,
                        const float* __restrict__ b, float* scale, float* shift,
                        int M, int C) {
    int c = blockIdx.x * blockDim.x + threadIdx.x;
    if (c >= C) return;
    float s = 0.f, q = 0.f;
    for (int ch = 0; ch < NCHUNK; ch++) {
        s += part[((long)ch * C + c) * 2 + 0];
        q += part[((long)ch * C + c) * 2 + 1];
    }
    float mu = s / (float)M;
    float var = q / (float)M - mu * mu;
    float sc = g[c] * rsqrtf(var + EPSV);
    scale[c] = sc;
    shift[c] = b[c] - mu * sc;
}

__global__ void k_bnapply(const float* __restrict__ H, const float* __restrict__ scale,
                          const float* __restrict__ shift, float* __restrict__ out,
                          float* __restrict__ out2, int M, int C, int ldo2) {
    int total = M * C;
    for (int idx = blockIdx.x * blockDim.x + threadIdx.x; idx < total;
         idx += gridDim.x * blockDim.x) {
        int c = idx % C;
        float v = H[idx] * scale[c] + shift[c];
        out[idx] = v;
        if (out2) out2[(long)(idx / C) * ldo2 + c] = v;
    }
}

__global__ void k_buildx(const float* __restrict__ bnx, const float* __restrict__ h1c,
                         const float* __restrict__ h2c, const int* __restrict__ ls,
                         const int* __restrict__ ld, float* __restrict__ xout) {
    int total = NN * (DOUT / 4);
    for (int idx = blockIdx.x * blockDim.x + threadIdx.x; idx < total;
         idx += gridDim.x * blockDim.x) {
        int n = idx >> 7;
        int c4 = idx & 127;
        float4 sec = ((const float4*)(bnx + (long)n * DOUT))[c4];
        float4 fir;
        int li = ld[n];
        if (li >= 0) fir = ((const float4*)(h2c + (long)li * DOUT))[c4];
        else {
            int si = ls[n];
            fir = (si >= 0) ? ((const float4*)(h1c + (long)si * DOUT))[c4] : sec;
        }
        ((float4*)(xout + (long)n * DX))[c4] = fir;
        ((float4*)(xout + (long)n * DX + DOUT))[c4] = sec;
    }
}

// ---------------- GEMM: C[M,N] = A[M,K] @ B[N,K]^T (+bias) ----------------
// 128x128 tile, BK=8, 8x8 microtile, 256 threads, double-buffered smem.
__global__ void __launch_bounds__(256)
k_gemm(const float* __restrict__ A, const float* __restrict__ B,
       const float* __restrict__ bias, float* __restrict__ C,
       int M, int N, int K, int ldc) {
    __shared__ float As[2][8][128];
    __shared__ float Bs[2][8][128];
    int tid = threadIdx.x;
    int arow = tid >> 1;
    int acol = (tid & 1) << 2;
    int tr = tid >> 4;
    int tc = tid & 15;
    long gm = (long)blockIdx.y * 128 + arow;
    long gn = (long)blockIdx.x * 128 + arow;
    bool okm = gm < M, okn = gn < N;
    const float* Ap = A + gm * K + acol;
    const float* Bp = B + gn * K + acol;
    float4 z4 = make_float4(0.f, 0.f, 0.f, 0.f);

    float acc[8][8];
#pragma unroll
    for (int i = 0; i < 8; i++)
#pragma unroll
        for (int j = 0; j < 8; j++) acc[i][j] = 0.f;

    float4 av = okm ? *(const float4*)Ap : z4;
    float4 bv = okn ? *(const float4*)Bp : z4;
    As[0][acol + 0][arow] = av.x; As[0][acol + 1][arow] = av.y;
    As[0][acol + 2][arow] = av.z; As[0][acol + 3][arow] = av.w;
    Bs[0][acol + 0][arow] = bv.x; Bs[0][acol + 1][arow] = bv.y;
    Bs[0][acol + 2][arow] = bv.z; Bs[0][acol + 3][arow] = bv.w;
    __syncthreads();

    int buf = 0;
    for (int k0 = 8; k0 < K; k0 += 8) {
        float4 av2 = okm ? *(const float4*)(Ap + k0) : z4;
        float4 bv2 = okn ? *(const float4*)(Bp + k0) : z4;
#pragma unroll
        for (int k = 0; k < 8; k++) {
            float4 a0 = *(const float4*)&As[buf][k][tr * 8];
            float4 a1 = *(const float4*)&As[buf][k][tr * 8 + 4];
            float4 b0 = *(const float4*)&Bs[buf][k][tc * 8];
            float4 b1 = *(const float4*)&Bs[buf][k][tc * 8 + 4];
            float ra[8] = {a0.x, a0.y, a0.z, a0.w, a1.x, a1.y, a1.z, a1.w};
            float rb[8] = {b0.x, b0.y, b0.z, b0.w, b1.x, b1.y, b1.z, b1.w};
#pragma unroll
            for (int i = 0; i < 8; i++)
#pragma unroll
                for (int j = 0; j < 8; j++) acc[i][j] += ra[i] * rb[j];
        }
        int nb2 = buf ^ 1;
        As[nb2][acol + 0][arow] = av2.x; As[nb2][acol + 1][arow] = av2.y;
        As[nb2][acol + 2][arow] = av2.z; As[nb2][acol + 3][arow] = av2.w;
        Bs[nb2][acol + 0][arow] = bv2.x; Bs[nb2][acol + 1][arow] = bv2.y;
        Bs[nb2][acol + 2][arow] = bv2.z; Bs[nb2][acol + 3][arow] = bv2.w;
        __syncthreads();
        buf = nb2;
    }
#pragma unroll
    for (int k = 0; k < 8; k++) {
        float4 a0 = *(const float4*)&As[buf][k][tr * 8];
        float4 a1 = *(const float4*)&As[buf][k][tr * 8 + 4];
        float4 b0 = *(const float4*)&Bs[buf][k][tc * 8];
        float4 b1 = *(const float4*)&Bs[buf][k][tc * 8 + 4];
        float ra[8] = {a0.x, a0.y, a0.z, a0.w, a1.x, a1.y, a1.z, a1.w};
        float rb[8] = {b0.x, b0.y, b0.z, b0.w, b1.x, b1.y, b1.z, b1.w};
#pragma unroll
        for (int i = 0; i < 8; i++)
#pragma unroll
            for (int j = 0; j < 8; j++) acc[i][j] += ra[i] * rb[j];
    }

    int mb = blockIdx.y * 128 + tr * 8;
    int nb = blockIdx.x * 128 + tc * 8;
#pragma unroll
    for (int i = 0; i < 8; i++) {
        int m = mb + i;
        if (m < M) {
#pragma unroll
            for (int j = 0; j < 8; j++) {
                int n = nb + j;
                if (n < N) {
                    float bi = bias ? bias[n] : 0.f;
                    C[(long)m * ldc + n] = acc[i][j] + bi;
                }
            }
        }
    }
}

// ---------------- skinny-N GEMM: 128 x <=48 tile, BK=16 ----------------
__global__ void __launch_bounds__(256)
k_gemm_sk(const float* __restrict__ A, const float* __restrict__ B,
          const float* __restrict__ bias, float* __restrict__ C,
          int M, int N, int K, int ldc) {
    __shared__ float As[16][128];
    __shared__ float Bs[16][48];
    int tid = threadIdx.x;
    int tr = tid >> 4;          // 0..15 -> rows tr*8
    int tc = tid & 15;          // 0..15 -> cols tc*3
    int arow = tid >> 1;        // 0..127
    int acol = (tid & 1) << 3;  // 0 or 8
    long gm = (long)blockIdx.y * 128 + arow;
    bool okm = gm < M;
    const float* Ap = A + gm * K + acol;
    int bn = tid >> 2;          // 0..63 (use <48)
    int bk = (tid & 3) << 2;    // 0,4,8,12
    bool okb = (tid < 192) && (bn < N);
    const float* Bp = B + (long)bn * K + bk;
    float4 z4 = make_float4(0.f, 0.f, 0.f, 0.f);

    float acc[8][3];
#pragma unroll
    for (int i = 0; i < 8; i++)
#pragma unroll
        for (int j = 0; j < 3; j++) acc[i][j] = 0.f;

    for (int k0 = 0; k0 < K; k0 += 16) {
        float4 a0 = okm ? *(const float4*)(Ap + k0) : z4;
        float4 a1 = okm ? *(const float4*)(Ap + k0 + 4) : z4;
        float4 bvv = okb ? *(const float4*)(Bp + k0) : z4;
        __syncthreads();
        As[acol + 0][arow] = a0.x; As[acol + 1][arow] = a0.y;
        As[acol + 2][arow] = a0.z; As[acol + 3][arow] = a0.w;
        As[acol + 4][arow] = a1.x; As[acol + 5][arow] = a1.y;
        As[acol + 6][arow] = a1.z; As[acol + 7][arow] = a1.w;
        if (tid < 192) {
            Bs[bk + 0][bn] = bvv.x; Bs[bk + 1][bn] = bvv.y;
            Bs[bk + 2][bn] = bvv.z; Bs[bk + 3][bn] = bvv.w;
        }
        __syncthreads();
#pragma unroll
        for (int k = 0; k < 16; k++) {
            float4 r0 = *(const float4*)&As[k][tr * 8];
            float4 r1 = *(const float4*)&As[k][tr * 8 + 4];
            float ra[8] = {r0.x, r0.y, r0.z, r0.w, r1.x, r1.y, r1.z, r1.w};
            float b0 = Bs[k][tc * 3 + 0];
            float b1 = Bs[k][tc * 3 + 1];
            float b2 = Bs[k][tc * 3 + 2];
#pragma unroll
            for (int i = 0; i < 8; i++) {
                acc[i][0] += ra[i] * b0;
                acc[i][1] += ra[i] * b1;
                acc[i][2] += ra[i] * b2;
            }
        }
    }
    int mb = blockIdx.y * 128 + tr * 8;
    int nb = tc * 3;
#pragma unroll
    for (int i = 0; i < 8; i++) {
        int m = mb + i;
        if (m < M) {
#pragma unroll
            for (int j = 0; j < 3; j++) {
                int n = nb + j;
                if (n < N) C[(long)m * ldc + n] = acc[i][j] + bias[n];
            }
        }
    }
}

// ---------------- reductions / norms ----------------
__device__ __forceinline__ float blk_sum(float v, float* sm) {
    __syncthreads();
    int lane = threadIdx.x & 31, w = threadIdx.x >> 5;
#pragma unroll
    for (int o = 16; o; o >>= 1) v += __shfl_down_sync(0xffffffffu, v, o);
    if (lane == 0) sm[w] = v;
    __syncthreads();
    if (w == 0) {
        int nw = (blockDim.x + 31) >> 5;
        float t = (lane < nw) ? sm[lane] : 0.f;
#pragma unroll
        for (int o = 16; o; o >>= 1) t += __shfl_down_sync(0xffffffffu, t, o);
        if (lane == 0) sm[0] = t;
    }
    __syncthreads();
    return sm[0];
}

__device__ __forceinline__ float4 f4add(float4 a, float4 b) {
    return make_float4(a.x + b.x, a.y + b.y, a.z + b.z, a.w + b.w);
}

// fused: zw[p] = U[src, 0:2048] + U[dst, 2048:4096] + bp ; LN ; ReLU -> Z2
__global__ void __launch_bounds__(256)
k_pairln_g(const float* __restrict__ U, const int* __restrict__ ps,
           const int* __restrict__ pd, const float* __restrict__ bp,
           const float* __restrict__ g, const float* __restrict__ b,
           float* __restrict__ Z2) {
    __shared__ float sm[32];
    int p = blockIdx.x;
    long bs = (long)ps[p] * 1024;        // float4 units (row stride 4096 floats)
    long bd = (long)pd[p] * 1024 + 512;
    int t = threadIdx.x;
    const float4* U4 = (const float4*)U;
    const float4* bp4 = (const float4*)bp;
    float4 v0 = f4add(f4add(U4[bs + t], U4[bd + t]), bp4[t]);
    float4 v1 = f4add(f4add(U4[bs + t + 256], U4[bd + t + 256]), bp4[t + 256]);
    float s = v0.x + v0.y + v0.z + v0.w + v1.x + v1.y + v1.z + v1.w;
    float mu = blk_sum(s, sm) * (1.0f / DZ);
    float q = (v0.x - mu) * (v0.x - mu) + (v0.y - mu) * (v0.y - mu) +
              (v0.z - mu) * (v0.z - mu) + (v0.w - mu) * (v0.w - mu) +
              (v1.x - mu) * (v1.x - mu) + (v1.y - mu) * (v1.y - mu) +
              (v1.z - mu) * (v1.z - mu) + (v1.w - mu) * (v1.w - mu);
    float var = blk_sum(q, sm) * (1.0f / DZ);
    float rs = rsqrtf(var + EPSV);
    const float4* g4 = (const float4*)g;
    const float4* b4 = (const float4*)b;
    float4* o = (float4*)(Z2 + (long)p * DZ);
    float4 gg = g4[t], bb = b4[t], w;
    w.x = fmaxf((v0.x - mu) * rs * gg.x + bb.x, 0.f);
    w.y = fmaxf((v0.y - mu) * rs * gg.y + bb.y, 0.f);
    w.z = fmaxf((v0.z - mu) * rs * gg.z + bb.z, 0.f);
    w.w = fmaxf((v0.w - mu) * rs * gg.w + bb.w, 0.f);
    o[t] = w;
    gg = g4[t + 256]; bb = b4[t + 256];
    w.x = fmaxf((v1.x - mu) * rs * gg.x + bb.x, 0.f);
    w.y = fmaxf((v1.y - mu) * rs * gg.y + bb.y, 0.f);
    w.z = fmaxf((v1.z - mu) * rs * gg.z + bb.z, 0.f);
    w.w = fmaxf((v1.w - mu) * rs * gg.w + bb.w, 0.f);
    o[t + 256] = w;
}

__global__ void __launch_bounds__(128)
k_nodeln(const float* __restrict__ T, const float* __restrict__ g,
         const float* __restrict__ b, float* __restrict__ O) {
    __shared__ float sm[32];
    long r = blockIdx.x;
    const float4* row = (const float4*)(T + r * DOUT);
    int t = threadIdx.x;
    float4 v = row[t];
    float s = v.x + v.y + v.z + v.w;
    float mu = blk_sum(s, sm) * (1.0f / DOUT);
    float q = (v.x - mu) * (v.x - mu) + (v.y - mu) * (v.y - mu) +
              (v.z - mu) * (v.z - mu) + (v.w - mu) * (v.w - mu);
    float var = blk_sum(q, sm) * (1.0f / DOUT);
    float rs = rsqrtf(var + EPSV);
    float4 gg = ((const float4*)g)[t], bb = ((const float4*)b)[t], w;
    w.x = fmaxf((v.x - mu) * rs * gg.x + bb.x, 0.f);
    w.y = fmaxf((v.y - mu) * rs * gg.y + bb.y, 0.f);
    w.z = fmaxf((v.z - mu) * rs * gg.z + bb.z, 0.f);
    w.w = fmaxf((v.w - mu) * rs * gg.w + bb.w, 0.f);
    ((float4*)(O + r * DOUT))[t] = w;
}

__global__ void k_split(const float* __restrict__ heads, float* __restrict__ pl,
                        float* __restrict__ pc) {
    int total = NP * 42;
    for (int idx = blockIdx.x * blockDim.x + threadIdx.x; idx < total;
         idx += gridDim.x * blockDim.x) {
        int r = idx / 42, c = idx % 42;
        float v = heads[(long)r * 42 + c];
        if (c < 40) pl[(long)r * 40 + c] = v;
        else pc[(long)r * 2 + (c - 40)] = v;
    }
}

// ---------------- host ----------------
extern "C" void kernel_launch(void* const* d_in, const int* in_sizes, int n_in,
                              void* d_out, int out_size) {
    const float* x_feat = (const float*)d_in[0];
    const int*   eidx   = (const int*)d_in[1];
    const int*   pidx   = (const int*)d_in[2];
    const float* h1c = (const float*)d_in[3];
    const float* h2c = (const float*)d_in[4];
    const float* W1l = (const float*)d_in[5];
    const float* b1l = (const float*)d_in[6];
    const float* W1r = (const float*)d_in[7];
    const float* bn1g = (const float*)d_in[8];
    const float* bn1b = (const float*)d_in[9];
    const float* W2l = (const float*)d_in[10];
    const float* b2l = (const float*)d_in[11];
    const float* W2r = (const float*)d_in[12];
    const float* bng = (const float*)d_in[13];
    const float* bnb = (const float*)d_in[14];
    const float* Wp  = (const float*)d_in[15];
    const float* bp  = (const float*)d_in[16];
    const float* plng = (const float*)d_in[17];
    const float* plnb = (const float*)d_in[18];
    const float* Wpc = (const float*)d_in[19];
    const float* bpc = (const float*)d_in[20];
    const float* We  = (const float*)d_in[21];
    const float* be  = (const float*)d_in[22];
    const float* Wnm = (const float*)d_in[23];
    const float* bnm = (const float*)d_in[24];
    const float* nlng = (const float*)d_in[25];
    const float* nlnb = (const float*)d_in[26];
    const float* Wnc = (const float*)d_in[27];
    const float* bnc = (const float*)d_in[28];

    float* out = (float*)d_out;
    float* out_node = out;                       // [NN,40]
    float* out_pl   = out + (long)NN * NC;       // [NP,40]
    float* out_pc   = out_pl + (long)NP * NC;    // [NP,2]
    float* out_x    = out_pc + (long)NP * 2;     // [NN,1024]
    float* out_gnn  = out_x + (long)NN * DX;     // [NN,512]

    float* F; int* I;
    cudaGetSymbolAddress((void**)&F, g_f);
    cudaGetSymbolAddress((void**)&I, g_i);
    float* a1   = F + OF_A1;
    float* w1   = F + OF_W1;
    float* h    = F + OF_H;
    float* hbn  = F + OF_HBN;
    float* a2   = F + OF_A2;
    float* w2   = F + OF_W2;
    float* bnx  = F + OF_BNX;
    float* bcat = F + OF_BC;
    float* U    = F + OF_U;
    float* z2   = F + OF_Z2;
    float* wpe  = F + OF_WPE;
    float* bpe  = F + OF_BPE;
    float* heads = F + OF_HEADS;
    float* tbuf = F + OF_T;
    float* x1r  = F + OF_X1R;
    float* part = F + OF_PART;
    float* sc1  = F + OF_SC1;
    float* sh1  = F + OF_SH1;
    float* sc2  = F + OF_SC2;
    float* sh2  = F + OF_SH2;
    int* deg = I + OI_DEG;
    int* off = I + OI_OFF;
    int* cur = I + OI_CUR;
    int* csr = I + OI_CSR;
    int* ls  = I + OI_LS;
    int* ld  = I + OI_LD;
    const int* esrc = eidx;
    const int* edst = eidx + NE;
    const int* psrc = pidx;
    const int* pdst = pidx + NP;

    // CSR build + scatter-last-index
    k_init<<<(NN + 255) / 256, 256>>>(deg, ls, ld);
    k_deg<<<(NE + 255) / 256, 256>>>(edst, deg);
    k_scan<<<1, 1024>>>(deg, off, cur);
    k_fill<<<(NE + 255) / 256, 256>>>(esrc, edst, cur, csr);
    k_lastidx<<<(NP + 255) / 256, 256>>>(psrc, pdst, ls, ld);

    // weight preprocessing
    k_cat<<<512, 256>>>(W1l, W1r, w1, DH, DIN, DIN);
    k_cat<<<1024, 256>>>(W2l, W2r, w2, DOUT, DH, DH);
    k_wpe<<<336, 256>>>(Wpc, bpc, We, be, wpe, bpe);
    k_bcat<<<2048, 256>>>(Wp, bcat);

    // layer 1: agg + gemm + bn
    k_agg<<<NN, 64>>>(x_feat, DIN, off, csr, a1, DH, 1);
    {
        dim3 g(DH / 128, (NN + 127) / 128);
        k_gemm<<<g, 256>>>(a1, w1, b1l, h, NN, DH, DH, DH);
    }
    k_bnsum<<<dim3(DH / 256, NCHUNK), 256>>>(h, NN, DH, part);
    k_bnfin<<<2, 256>>>(part, bn1g, bn1b, sc1, sh1, NN, DH);
    k_bnapply<<<2048, 256>>>(h, sc1, sh1, hbn, a2 + DH, NN, DH, DX);

    // layer 2: agg + gemm (-> gnn_x output) + bn
    k_agg<<<NN, 128>>>(hbn, DH, off, csr, a2, DX, 0);
    {
        dim3 g(DOUT / 128, (NN + 127) / 128);
        k_gemm<<<g, 256>>>(a2, w2, b2l, out_gnn, NN, DOUT, DX, DOUT);
    }
    k_bnsum<<<dim3(DOUT / 256, NCHUNK), 256>>>(out_gnn, NN, DOUT, part);
    k_bnfin<<<2, 256>>>(part, bng, bnb, sc2, sh2, NN, DOUT);
    k_bnapply<<<2048, 256>>>(out_gnn, sc2, sh2, bnx, nullptr, NN, DOUT, 0);

    // x with compensate scatter (-> x output)
    k_buildx<<<2048, 256>>>(bnx, h1c, h2c, ls, ld, out_x);

    // pair branch: U = x @ bcat^T over unique nodes (84 GF instead of 168)
    {
        dim3 g(4096 / 128, (NN + 127) / 128);
        k_gemm<<<g, 256>>>(out_x, bcat, nullptr, U, NN, 4096, DX, 4096);
    }
    // fused gather + bias + LN + ReLU
    k_pairln_g<<<NP, 256>>>(U, psrc, pdst, bp, plng, plnb, z2);
    // heads (skinny N=42)
    {
        dim3 g(1, (NP + 127) / 128);
        k_gemm_sk<<<g, 256>>>(z2, wpe, bpe, heads, NP, 42, DZ, 42);
    }
    k_split<<<2048, 256>>>(heads, out_pl, out_pc);

    // node branch
    {
        dim3 g(DOUT / 128, (NN + 127) / 128);
        k_gemm<<<g, 256>>>(out_x, Wnm, bnm, tbuf, NN, DOUT, DX, DOUT);
    }
    k_nodeln<<<NN, 128>>>(tbuf, nlng, nlnb, x1r);
    {
        dim3 g(1, (NN + 127) / 128);
        k_gemm_sk<<<g, 256>>>(x1r, Wnc, bnc, out_node, NN, NC, DOUT, NC);
    }
}

// round 3
// speedup vs baseline: 3.2005x; 1.8333x over previous
#include <cuda_runtime.h>
#include <cuda_bf16.h>
#include <cstdint>

#define NN 10000
#define NE 160000
#define NP 20000
#define DIN 256
#define DH  512
#define DOUT 512
#define DX  1024
#define DZ  2048
#define NC  40
#define EPSV 1e-5f
#define NCHUNK 40
#define CHROWS 250

// ---------------- static scratch ----------------
#define OF_A1   0L
#define OF_W1   (OF_A1  + (long)NN*DH)
#define OF_H    (OF_W1  + (long)DH*DH)
#define OF_HBN  (OF_H   + (long)NN*DH)
#define OF_A2   (OF_HBN + (long)NN*DH)
#define OF_W2   (OF_A2  + (long)NN*DX)
#define OF_BNX  (OF_W2  + (long)DOUT*DX)
#define OF_BC   (OF_BNX + (long)NN*DOUT)     // bcat [4096,1024]
#define OF_U    (OF_BC  + 4096L*DX)          // U    [NN,4096]
#define OF_Z2   (OF_U   + (long)NN*4096)     // z2   [NP,2048]
#define OF_WPE  (OF_Z2  + (long)NP*DZ)
#define OF_BPE  (OF_WPE + 42L*DZ)
#define OF_HEADS (OF_BPE + 64L)
#define OF_T    (OF_HEADS + (long)NP*48)
#define OF_X1R  (OF_T   + (long)NN*DOUT)
#define OF_PART (OF_X1R + (long)NN*DOUT)     // [NCHUNK,512,2]
#define OF_SC1  (OF_PART + 41984L)
#define OF_SH1  (OF_SC1 + 512L)
#define OF_SC2  (OF_SH1 + 512L)
#define OF_SH2  (OF_SC2 + 512L)
#define F_TOTAL (OF_SH2 + 512L)

__device__ __align__(256) float g_f[F_TOTAL];

#define OI_DEG 0
#define OI_OFF 10016
#define OI_CUR 20032
#define OI_CSR 30048
#define OI_LS  190048
#define OI_LD  200048
#define I_TOTAL 210064
__device__ __align__(256) int g_i[I_TOTAL];

// ---------------- small utility kernels ----------------
__global__ void k_init(int* deg, int* ls, int* ld) {
    int i = blockIdx.x * blockDim.x + threadIdx.x;
    if (i < NN) { deg[i] = 0; ls[i] = -1; ld[i] = -1; }
}

__global__ void k_deg(const int* __restrict__ dst, int* deg) {
    int e = blockIdx.x * blockDim.x + threadIdx.x;
    if (e < NE) atomicAdd(&deg[dst[e]], 1);
}

__global__ void k_scan(const int* __restrict__ deg, int* off, int* cur) {
    __shared__ int s[1024];
    __shared__ int carry;
    int tid = threadIdx.x;
    if (tid == 0) carry = 0;
    __syncthreads();
    for (int base = 0; base < NN; base += 1024) {
        int i = base + tid;
        int v = (i < NN) ? deg[i] : 0;
        s[tid] = v;
        __syncthreads();
        for (int o = 1; o < 1024; o <<= 1) {
            int t = (tid >= o) ? s[tid - o] : 0;
            __syncthreads();
            s[tid] += t;
            __syncthreads();
        }
        int excl = s[tid] - v;
        int c0 = carry;
        if (i < NN) { off[i] = c0 + excl; cur[i] = c0 + excl; }
        __syncthreads();
        if (tid == 0) carry = c0 + s[1023];
        __syncthreads();
    }
    if (tid == 0) off[NN] = carry;
}

__global__ void k_fill(const int* __restrict__ src, const int* __restrict__ dst,
                       int* cur, int* csr) {
    int e = blockIdx.x * blockDim.x + threadIdx.x;
    if (e < NE) {
        int slot = atomicAdd(&cur[dst[e]], 1);
        csr[slot] = src[e];
    }
}

__global__ void k_lastidx(const int* __restrict__ ps, const int* __restrict__ pd,
                          int* ls, int* ld) {
    int i = blockIdx.x * blockDim.x + threadIdx.x;
    if (i < NP) { atomicMax(&ls[ps[i]], i); atomicMax(&ld[pd[i]], i); }
}

// per-node neighbor max + optional self-copy into [agg | self] layout
__global__ void k_agg(const float* __restrict__ X, int D, const int* __restrict__ off,
                      const int* __restrict__ csr, float* __restrict__ out, int ldo,
                      int copyself) {
    int n = blockIdx.x;
    int s = off[n], e = off[n + 1];
    int nv = D >> 2;
    const float4* X4 = (const float4*)X;
    for (int c = threadIdx.x; c < nv; c += blockDim.x) {
        float4 m = make_float4(0.f, 0.f, 0.f, 0.f);
        if (e > s) {
            m = __ldg(&X4[(long)csr[s] * nv + c]);
            for (int i = s + 1; i < e; i++) {
                float4 v = __ldg(&X4[(long)csr[i] * nv + c]);
                m.x = fmaxf(m.x, v.x); m.y = fmaxf(m.y, v.y);
                m.z = fmaxf(m.z, v.z); m.w = fmaxf(m.w, v.w);
            }
        }
        ((float4*)(out + (long)n * ldo))[c] = m;
        if (copyself)
            ((float4*)(out + (long)n * ldo + D))[c] = __ldg(&X4[(long)n * nv + c]);
    }
}

__global__ void k_cat(const float* __restrict__ A, const float* __restrict__ B,
                      float* __restrict__ D, int rows, int ka, int kb) {
    int kc = ka + kb;
    int total = rows * kc;
    for (int idx = blockIdx.x * blockDim.x + threadIdx.x; idx < total;
         idx += gridDim.x * blockDim.x) {
        int r = idx / kc, c = idx % kc;
        D[idx] = (c < ka) ? A[(long)r * ka + c] : B[(long)r * kb + (c - ka)];
    }
}

__global__ void k_wpe(const float* __restrict__ Wpc, const float* __restrict__ bpc,
                      const float* __restrict__ We, const float* __restrict__ be,
                      float* wpe, float* bpe) {
    for (int idx = blockIdx.x * blockDim.x + threadIdx.x; idx < 42 * DZ;
         idx += gridDim.x * blockDim.x) {
        int r = idx / DZ, k = idx % DZ;
        wpe[idx] = (r < 40) ? Wpc[(long)r * DZ + k] : We[(long)(r - 40) * DZ + k];
        if (idx < 42) bpe[idx] = (idx < 40) ? bpc[idx] : be[idx - 40];
    }
}

// Bcat[4096,1024]: rows 0..2047 = Wp[n, 0:1024]; rows 2048.. = Wp[n-2048, 1024:2048]
__global__ void k_bcat(const float* __restrict__ Wp, float* __restrict__ Bc) {
    int total = 4096 * DX;
    for (int idx = blockIdx.x * blockDim.x + threadIdx.x; idx < total;
         idx += gridDim.x * blockDim.x) {
        int n = idx >> 10, k = idx & 1023;
        Bc[idx] = (n < 2048) ? Wp[(long)n * DZ + k]
                             : Wp[(long)(n - 2048) * DZ + 1024 + k];
    }
}

// ---------------- BN: coalesced chunked stats ----------------
__global__ void k_bnsum(const float* __restrict__ H, int M, int C,
                        float* __restrict__ part) {
    int c = blockIdx.x * blockDim.x + threadIdx.x;   // column
    int r0 = blockIdx.y * CHROWS;
    int r1 = min(r0 + CHROWS, M);
    float s = 0.f, q = 0.f;
    for (int r = r0; r < r1; r++) {
        float v = H[(long)r * C + c];
        s += v; q += v * v;
    }
    part[((long)blockIdx.y * C + c) * 2 + 0] = s;
    part[((long)blockIdx.y * C + c) * 2 + 1] = q;
}

__global__ void k_bnfin(const float* __restrict__ part, const float* __restrict__ g,
                        const float* __restrict__ b, float* scale, float* shift,
                        int M, int C) {
    int c = blockIdx.x * blockDim.x + threadIdx.x;
    if (c >= C) return;
    float s = 0.f, q = 0.f;
    for (int ch = 0; ch < NCHUNK; ch++) {
        s += part[((long)ch * C + c) * 2 + 0];
        q += part[((long)ch * C + c) * 2 + 1];
    }
    float mu = s / (float)M;
    float var = q / (float)M - mu * mu;
    float sc = g[c] * rsqrtf(var + EPSV);
    scale[c] = sc;
    shift[c] = b[c] - mu * sc;
}

__global__ void k_bnapply(const float* __restrict__ H, const float* __restrict__ scale,
                          const float* __restrict__ shift, float* __restrict__ out,
                          float* __restrict__ out2, int M, int C, int ldo2) {
    int total = M * C;
    for (int idx = blockIdx.x * blockDim.x + threadIdx.x; idx < total;
         idx += gridDim.x * blockDim.x) {
        int c = idx % C;
        float v = H[idx] * scale[c] + shift[c];
        out[idx] = v;
        if (out2) out2[(long)(idx / C) * ldo2 + c] = v;
    }
}

__global__ void k_buildx(const float* __restrict__ bnx, const float* __restrict__ h1c,
                         const float* __restrict__ h2c, const int* __restrict__ ls,
                         const int* __restrict__ ld, float* __restrict__ xout) {
    int total = NN * (DOUT / 4);
    for (int idx = blockIdx.x * blockDim.x + threadIdx.x; idx < total;
         idx += gridDim.x * blockDim.x) {
        int n = idx >> 7;
        int c4 = idx & 127;
        float4 sec = ((const float4*)(bnx + (long)n * DOUT))[c4];
        float4 fir;
        int li = ld[n];
        if (li >= 0) fir = ((const float4*)(h2c + (long)li * DOUT))[c4];
        else {
            int si = ls[n];
            fir = (si >= 0) ? ((const float4*)(h1c + (long)si * DOUT))[c4] : sec;
        }
        ((float4*)(xout + (long)n * DX))[c4] = fir;
        ((float4*)(xout + (long)n * DX + DOUT))[c4] = sec;
    }
}

// ================= bf16x3 tensor-core GEMM =================
// C[M,N] = A[M,K] @ B[N,K]^T (+bias). N % 128 == 0, K % 16 == 0.
// 128x128 CTA tile, BK=16, 8 warps (2x4), warp tile 64x32.
// fp32 -> (hi, lo) bf16 split; D += Ah*Bh + Ah*Bl + Al*Bh.
#define SPAD 18

#define MMA_BF16(d, a, b)                                                      \
    asm volatile(                                                              \
        "mma.sync.aligned.m16n8k16.row.col.f32.bf16.bf16.f32 "                 \
        "{%0,%1,%2,%3}, {%4,%5,%6,%7}, {%8,%9}, {%0,%1,%2,%3};"                \
        : "+f"(d[0]), "+f"(d[1]), "+f"(d[2]), "+f"(d[3])                       \
        : "r"(a[0]), "r"(a[1]), "r"(a[2]), "r"(a[3]), "r"(b[0]), "r"(b[1]))

__global__ void __launch_bounds__(256)
k_gemm_mma(const float* __restrict__ A, const float* __restrict__ B,
           const float* __restrict__ bias, float* __restrict__ C,
           int M, int N, int K, int ldc) {
    __shared__ __align__(16) __nv_bfloat16 sA[2][2][128][SPAD];
    __shared__ __align__(16) __nv_bfloat16 sB[2][2][128][SPAD];

    int tid = threadIdx.x;
    int wid = tid >> 5, lane = tid & 31;
    int wm = wid >> 2, wn = wid & 3;          // 2 x 4 warp grid
    int lrow = lane >> 2, lcol = (lane & 3) << 1;

    int arow = tid >> 1;
    int ahalf = (tid & 1) << 3;
    long gm = (long)blockIdx.y * 128 + arow;
    long gn = (long)blockIdx.x * 128 + arow;
    bool okm = gm < M;
    bool okn = gn < N;
    const float* Ap = A + gm * K + ahalf;
    const float* Bp = B + gn * K + ahalf;
    float4 z4 = make_float4(0.f, 0.f, 0.f, 0.f);

    float acc[4][4][4];
#pragma unroll
    for (int mi = 0; mi < 4; mi++)
#pragma unroll
        for (int ni = 0; ni < 4; ni++)
#pragma unroll
            for (int r = 0; r < 4; r++) acc[mi][ni][r] = 0.f;

    // ---- stage k-tile 0 into buf 0 ----
    {
        float4 a0 = okm ? *(const float4*)(Ap) : z4;
        float4 a1 = okm ? *(const float4*)(Ap + 4) : z4;
        float4 b0 = okn ? *(const float4*)(Bp) : z4;
        float4 b1 = okn ? *(const float4*)(Bp + 4) : z4;
        float va[8] = {a0.x, a0.y, a0.z, a0.w, a1.x, a1.y, a1.z, a1.w};
        float vb[8] = {b0.x, b0.y, b0.z, b0.w, b1.x, b1.y, b1.z, b1.w};
#pragma unroll
        for (int i = 0; i < 8; i += 2) {
            __nv_bfloat162 h, l;
            h.x = __float2bfloat16_rn(va[i]);
            l.x = __float2bfloat16_rn(va[i] - __bfloat162float(h.x));
            h.y = __float2bfloat16_rn(va[i + 1]);
            l.y = __float2bfloat16_rn(va[i + 1] - __bfloat162float(h.y));
            *(__nv_bfloat162*)&sA[0][0][arow][ahalf + i] = h;
            *(__nv_bfloat162*)&sA[0][1][arow][ahalf + i] = l;
            h.x = __float2bfloat16_rn(vb[i]);
            l.x = __float2bfloat16_rn(vb[i] - __bfloat162float(h.x));
            h.y = __float2bfloat16_rn(vb[i + 1]);
            l.y = __float2bfloat16_rn(vb[i + 1] - __bfloat162float(h.y));
            *(__nv_bfloat162*)&sB[0][0][arow][ahalf + i] = h;
            *(__nv_bfloat162*)&sB[0][1][arow][ahalf + i] = l;
        }
    }
    __syncthreads();

    int nk = K >> 4;
    for (int kt = 0; kt < nk; kt++) {
        int buf = kt & 1;
        // prefetch next tile (gmem -> regs)
        float4 pa0, pa1, pb0, pb1;
        bool more = (kt + 1) < nk;
        if (more) {
            int k0 = (kt + 1) << 4;
            pa0 = okm ? *(const float4*)(Ap + k0) : z4;
            pa1 = okm ? *(const float4*)(Ap + k0 + 4) : z4;
            pb0 = okn ? *(const float4*)(Bp + k0) : z4;
            pb1 = okn ? *(const float4*)(Bp + k0 + 4) : z4;
        }

        // ---- load fragments & MMA ----
        uint32_t ah[4][4], al[4][4], bh[4][2], bl[4][2];
#pragma unroll
        for (int mi = 0; mi < 4; mi++) {
            int r0 = wm * 64 + mi * 16 + lrow;
            ah[mi][0] = *(const uint32_t*)&sA[buf][0][r0][lcol];
            ah[mi][1] = *(const uint32_t*)&sA[buf][0][r0 + 8][lcol];
            ah[mi][2] = *(const uint32_t*)&sA[buf][0][r0][lcol + 8];
            ah[mi][3] = *(const uint32_t*)&sA[buf][0][r0 + 8][lcol + 8];
            al[mi][0] = *(const uint32_t*)&sA[buf][1][r0][lcol];
            al[mi][1] = *(const uint32_t*)&sA[buf][1][r0 + 8][lcol];
            al[mi][2] = *(const uint32_t*)&sA[buf][1][r0][lcol + 8];
            al[mi][3] = *(const uint32_t*)&sA[buf][1][r0 + 8][lcol + 8];
        }
#pragma unroll
        for (int ni = 0; ni < 4; ni++) {
            int r0 = wn * 32 + ni * 8 + lrow;
            bh[ni][0] = *(const uint32_t*)&sB[buf][0][r0][lcol];
            bh[ni][1] = *(const uint32_t*)&sB[buf][0][r0][lcol + 8];
            bl[ni][0] = *(const uint32_t*)&sB[buf][1][r0][lcol];
            bl[ni][1] = *(const uint32_t*)&sB[buf][1][r0][lcol + 8];
        }
#pragma unroll
        for (int mi = 0; mi < 4; mi++)
#pragma unroll
            for (int ni = 0; ni < 4; ni++) {
                MMA_BF16(acc[mi][ni], ah[mi], bh[ni]);
                MMA_BF16(acc[mi][ni], ah[mi], bl[ni]);
                MMA_BF16(acc[mi][ni], al[mi], bh[ni]);
            }

        if (more) {
            int nb = buf ^ 1;
            float va[8] = {pa0.x, pa0.y, pa0.z, pa0.w, pa1.x, pa1.y, pa1.z, pa1.w};
            float vb[8] = {pb0.x, pb0.y, pb0.z, pb0.w, pb1.x, pb1.y, pb1.z, pb1.w};
#pragma unroll
            for (int i = 0; i < 8; i += 2) {
                __nv_bfloat162 h, l;
                h.x = __float2bfloat16_rn(va[i]);
                l.x = __float2bfloat16_rn(va[i] - __bfloat162float(h.x));
                h.y = __float2bfloat16_rn(va[i + 1]);
                l.y = __float2bfloat16_rn(va[i + 1] - __bfloat162float(h.y));
                *(__nv_bfloat162*)&sA[nb][0][arow][ahalf + i] = h;
                *(__nv_bfloat162*)&sA[nb][1][arow][ahalf + i] = l;
                h.x = __float2bfloat16_rn(vb[i]);
                l.x = __float2bfloat16_rn(vb[i] - __bfloat162float(h.x));
                h.y = __float2bfloat16_rn(vb[i + 1]);
                l.y = __float2bfloat16_rn(vb[i + 1] - __bfloat162float(h.y));
                *(__nv_bfloat162*)&sB[nb][0][arow][ahalf + i] = h;
                *(__nv_bfloat162*)&sB[nb][1][arow][ahalf + i] = l;
            }
        }
        __syncthreads();
    }

    // ---- epilogue ----
    int mbase = blockIdx.y * 128 + wm * 64 + lrow;
    int nbase = blockIdx.x * 128 + wn * 32 + lcol;
#pragma unroll
    for (int mi = 0; mi < 4; mi++) {
        int m0 = mbase + mi * 16;
#pragma unroll
        for (int ni = 0; ni < 4; ni++) {
            int n0 = nbase + ni * 8;
            float b0v = bias ? bias[n0] : 0.f;
            float b1v = bias ? bias[n0 + 1] : 0.f;
            if (m0 < M) {
                C[(long)m0 * ldc + n0] = acc[mi][ni][0] + b0v;
                C[(long)m0 * ldc + n0 + 1] = acc[mi][ni][1] + b1v;
            }
            if (m0 + 8 < M) {
                C[(long)(m0 + 8) * ldc + n0] = acc[mi][ni][2] + b0v;
                C[(long)(m0 + 8) * ldc + n0 + 1] = acc[mi][ni][3] + b1v;
            }
        }
    }
}

// ---------------- skinny-N GEMM: 128 x <=48 tile, BK=16 ----------------
__global__ void __launch_bounds__(256)
k_gemm_sk(const float* __restrict__ A, const float* __restrict__ B,
          const float* __restrict__ bias, float* __restrict__ C,
          int M, int N, int K, int ldc) {
    __shared__ float As[16][128];
    __shared__ float Bs[16][48];
    int tid = threadIdx.x;
    int tr = tid >> 4;
    int tc = tid & 15;
    int arow = tid >> 1;
    int acol = (tid & 1) << 3;
    long gm = (long)blockIdx.y * 128 + arow;
    bool okm = gm < M;
    const float* Ap = A + gm * K + acol;
    int bn = tid >> 2;
    int bk = (tid & 3) << 2;
    bool okb = (tid < 192) && (bn < N);
    const float* Bp = B + (long)bn * K + bk;
    float4 z4 = make_float4(0.f, 0.f, 0.f, 0.f);

    float acc[8][3];
#pragma unroll
    for (int i = 0; i < 8; i++)
#pragma unroll
        for (int j = 0; j < 3; j++) acc[i][j] = 0.f;

    for (int k0 = 0; k0 < K; k0 += 16) {
        float4 a0 = okm ? *(const float4*)(Ap + k0) : z4;
        float4 a1 = okm ? *(const float4*)(Ap + k0 + 4) : z4;
        float4 bvv = okb ? *(const float4*)(Bp + k0) : z4;
        __syncthreads();
        As[acol + 0][arow] = a0.x; As[acol + 1][arow] = a0.y;
        As[acol + 2][arow] = a0.z; As[acol + 3][arow] = a0.w;
        As[acol + 4][arow] = a1.x; As[acol + 5][arow] = a1.y;
        As[acol + 6][arow] = a1.z; As[acol + 7][arow] = a1.w;
        if (tid < 192) {
            Bs[bk + 0][bn] = bvv.x; Bs[bk + 1][bn] = bvv.y;
            Bs[bk + 2][bn] = bvv.z; Bs[bk + 3][bn] = bvv.w;
        }
        __syncthreads();
#pragma unroll
        for (int k = 0; k < 16; k++) {
            float4 r0 = *(const float4*)&As[k][tr * 8];
            float4 r1 = *(const float4*)&As[k][tr * 8 + 4];
            float ra[8] = {r0.x, r0.y, r0.z, r0.w, r1.x, r1.y, r1.z, r1.w};
            float b0 = Bs[k][tc * 3 + 0];
            float b1 = Bs[k][tc * 3 + 1];
            float b2 = Bs[k][tc * 3 + 2];
#pragma unroll
            for (int i = 0; i < 8; i++) {
                acc[i][0] += ra[i] * b0;
                acc[i][1] += ra[i] * b1;
                acc[i][2] += ra[i] * b2;
            }
        }
    }
    int mb = blockIdx.y * 128 + tr * 8;
    int nb = tc * 3;
#pragma unroll
    for (int i = 0; i < 8; i++) {
        int m = mb + i;
        if (m < M) {
#pragma unroll
            for (int j = 0; j < 3; j++) {
                int n = nb + j;
                if (n < N) C[(long)m * ldc + n] = acc[i][j] + bias[n];
            }
        }
    }
}

// ---------------- reductions / norms ----------------
__device__ __forceinline__ float blk_sum(float v, float* sm) {
    __syncthreads();
    int lane = threadIdx.x & 31, w = threadIdx.x >> 5;
#pragma unroll
    for (int o = 16; o; o >>= 1) v += __shfl_down_sync(0xffffffffu, v, o);
    if (lane == 0) sm[w] = v;
    __syncthreads();
    if (w == 0) {
        int nw = (blockDim.x + 31) >> 5;
        float t = (lane < nw) ? sm[lane] : 0.f;
#pragma unroll
        for (int o = 16; o; o >>= 1) t += __shfl_down_sync(0xffffffffu, t, o);
        if (lane == 0) sm[0] = t;
    }
    __syncthreads();
    return sm[0];
}

__device__ __forceinline__ float4 f4add(float4 a, float4 b) {
    return make_float4(a.x + b.x, a.y + b.y, a.z + b.z, a.w + b.w);
}

// fused: zw[p] = U[src, 0:2048] + U[dst, 2048:4096] + bp ; LN ; ReLU -> Z2
__global__ void __launch_bounds__(256)
k_pairln_g(const float* __restrict__ U, const int* __restrict__ ps,
           const int* __restrict__ pd, const float* __restrict__ bp,
           const float* __restrict__ g, const float* __restrict__ b,
           float* __restrict__ Z2) {
    __shared__ float sm[32];
    int p = blockIdx.x;
    long bs = (long)ps[p] * 1024;
    long bd = (long)pd[p] * 1024 + 512;
    int t = threadIdx.x;
    const float4* U4 = (const float4*)U;
    const float4* bp4 = (const float4*)bp;
    float4 v0 = f4add(f4add(U4[bs + t], U4[bd + t]), bp4[t]);
    float4 v1 = f4add(f4add(U4[bs + t + 256], U4[bd + t + 256]), bp4[t + 256]);
    float s = v0.x + v0.y + v0.z + v0.w + v1.x + v1.y + v1.z + v1.w;
    float mu = blk_sum(s, sm) * (1.0f / DZ);
    float q = (v0.x - mu) * (v0.x - mu) + (v0.y - mu) * (v0.y - mu) +
              (v0.z - mu) * (v0.z - mu) + (v0.w - mu) * (v0.w - mu) +
              (v1.x - mu) * (v1.x - mu) + (v1.y - mu) * (v1.y - mu) +
              (v1.z - mu) * (v1.z - mu) + (v1.w - mu) * (v1.w - mu);
    float var = blk_sum(q, sm) * (1.0f / DZ);
    float rs = rsqrtf(var + EPSV);
    const float4* g4 = (const float4*)g;
    const float4* b4 = (const float4*)b;
    float4* o = (float4*)(Z2 + (long)p * DZ);
    float4 gg = g4[t], bb = b4[t], w;
    w.x = fmaxf((v0.x - mu) * rs * gg.x + bb.x, 0.f);
    w.y = fmaxf((v0.y - mu) * rs * gg.y + bb.y, 0.f);
    w.z = fmaxf((v0.z - mu) * rs * gg.z + bb.z, 0.f);
    w.w = fmaxf((v0.w - mu) * rs * gg.w + bb.w, 0.f);
    o[t] = w;
    gg = g4[t + 256]; bb = b4[t + 256];
    w.x = fmaxf((v1.x - mu) * rs * gg.x + bb.x, 0.f);
    w.y = fmaxf((v1.y - mu) * rs * gg.y + bb.y, 0.f);
    w.z = fmaxf((v1.z - mu) * rs * gg.z + bb.z, 0.f);
    w.w = fmaxf((v1.w - mu) * rs * gg.w + bb.w, 0.f);
    o[t + 256] = w;
}

__global__ void __launch_bounds__(128)
k_nodeln(const float* __restrict__ T, const float* __restrict__ g,
         const float* __restrict__ b, float* __restrict__ O) {
    __shared__ float sm[32];
    long r = blockIdx.x;
    const float4* row = (const float4*)(T + r * DOUT);
    int t = threadIdx.x;
    float4 v = row[t];
    float s = v.x + v.y + v.z + v.w;
    float mu = blk_sum(s, sm) * (1.0f / DOUT);
    float q = (v.x - mu) * (v.x - mu) + (v.y - mu) * (v.y - mu) +
              (v.z - mu) * (v.z - mu) + (v.w - mu) * (v.w - mu);
    float var = blk_sum(q, sm) * (1.0f / DOUT);
    float rs = rsqrtf(var + EPSV);
    float4 gg = ((const float4*)g)[t], bb = ((const float4*)b)[t], w;
    w.x = fmaxf((v.x - mu) * rs * gg.x + bb.x, 0.f);
    w.y = fmaxf((v.y - mu) * rs * gg.y + bb.y, 0.f);
    w.z = fmaxf((v.z - mu) * rs * gg.z + bb.z, 0.f);
    w.w = fmaxf((v.w - mu) * rs * gg.w + bb.w, 0.f);
    ((float4*)(O + r * DOUT))[t] = w;
}

__global__ void k_split(const float* __restrict__ heads, float* __restrict__ pl,
                        float* __restrict__ pc) {
    int total = NP * 42;
    for (int idx = blockIdx.x * blockDim.x + threadIdx.x; idx < total;
         idx += gridDim.x * blockDim.x) {
        int r = idx / 42, c = idx % 42;
        float v = heads[(long)r * 42 + c];
        if (c < 40) pl[(long)r * 40 + c] = v;
        else pc[(long)r * 2 + (c - 40)] = v;
    }
}

// ---------------- host ----------------
extern "C" void kernel_launch(void* const* d_in, const int* in_sizes, int n_in,
                              void* d_out, int out_size) {
    const float* x_feat = (const float*)d_in[0];
    const int*   eidx   = (const int*)d_in[1];
    const int*   pidx   = (const int*)d_in[2];
    const float* h1c = (const float*)d_in[3];
    const float* h2c = (const float*)d_in[4];
    const float* W1l = (const float*)d_in[5];
    const float* b1l = (const float*)d_in[6];
    const float* W1r = (const float*)d_in[7];
    const float* bn1g = (const float*)d_in[8];
    const float* bn1b = (const float*)d_in[9];
    const float* W2l = (const float*)d_in[10];
    const float* b2l = (const float*)d_in[11];
    const float* W2r = (const float*)d_in[12];
    const float* bng = (const float*)d_in[13];
    const float* bnb = (const float*)d_in[14];
    const float* Wp  = (const float*)d_in[15];
    const float* bp  = (const float*)d_in[16];
    const float* plng = (const float*)d_in[17];
    const float* plnb = (const float*)d_in[18];
    const float* Wpc = (const float*)d_in[19];
    const float* bpc = (const float*)d_in[20];
    const float* We  = (const float*)d_in[21];
    const float* be  = (const float*)d_in[22];
    const float* Wnm = (const float*)d_in[23];
    const float* bnm = (const float*)d_in[24];
    const float* nlng = (const float*)d_in[25];
    const float* nlnb = (const float*)d_in[26];
    const float* Wnc = (const float*)d_in[27];
    const float* bnc = (const float*)d_in[28];

    float* out = (float*)d_out;
    float* out_node = out;                       // [NN,40]
    float* out_pl   = out + (long)NN * NC;       // [NP,40]
    float* out_pc   = out_pl + (long)NP * NC;    // [NP,2]
    float* out_x    = out_pc + (long)NP * 2;     // [NN,1024]
    float* out_gnn  = out_x + (long)NN * DX;     // [NN,512]

    float* F; int* I;
    cudaGetSymbolAddress((void**)&F, g_f);
    cudaGetSymbolAddress((void**)&I, g_i);
    float* a1   = F + OF_A1;
    float* w1   = F + OF_W1;
    float* h    = F + OF_H;
    float* hbn  = F + OF_HBN;
    float* a2   = F + OF_A2;
    float* w2   = F + OF_W2;
    float* bnx  = F + OF_BNX;
    float* bcat = F + OF_BC;
    float* U    = F + OF_U;
    float* z2   = F + OF_Z2;
    float* wpe  = F + OF_WPE;
    float* bpe  = F + OF_BPE;
    float* heads = F + OF_HEADS;
    float* tbuf = F + OF_T;
    float* x1r  = F + OF_X1R;
    float* part = F + OF_PART;
    float* sc1  = F + OF_SC1;
    float* sh1  = F + OF_SH1;
    float* sc2  = F + OF_SC2;
    float* sh2  = F + OF_SH2;
    int* deg = I + OI_DEG;
    int* off = I + OI_OFF;
    int* cur = I + OI_CUR;
    int* csr = I + OI_CSR;
    int* ls  = I + OI_LS;
    int* ld  = I + OI_LD;
    const int* esrc = eidx;
    const int* edst = eidx + NE;
    const int* psrc = pidx;
    const int* pdst = pidx + NP;

    // CSR build + scatter-last-index
    k_init<<<(NN + 255) / 256, 256>>>(deg, ls, ld);
    k_deg<<<(NE + 255) / 256, 256>>>(edst, deg);
    k_scan<<<1, 1024>>>(deg, off, cur);
    k_fill<<<(NE + 255) / 256, 256>>>(esrc, edst, cur, csr);
    k_lastidx<<<(NP + 255) / 256, 256>>>(psrc, pdst, ls, ld);

    // weight preprocessing
    k_cat<<<512, 256>>>(W1l, W1r, w1, DH, DIN, DIN);
    k_cat<<<1024, 256>>>(W2l, W2r, w2, DOUT, DH, DH);
    k_wpe<<<336, 256>>>(Wpc, bpc, We, be, wpe, bpe);
    k_bcat<<<2048, 256>>>(Wp, bcat);

    // layer 1: agg + gemm + bn
    k_agg<<<NN, 64>>>(x_feat, DIN, off, csr, a1, DH, 1);
    {
        dim3 g(DH / 128, (NN + 127) / 128);
        k_gemm_mma<<<g, 256>>>(a1, w1, b1l, h, NN, DH, DH, DH);
    }
    k_bnsum<<<dim3(DH / 256, NCHUNK), 256>>>(h, NN, DH, part);
    k_bnfin<<<2, 256>>>(part, bn1g, bn1b, sc1, sh1, NN, DH);
    k_bnapply<<<2048, 256>>>(h, sc1, sh1, hbn, a2 + DH, NN, DH, DX);

    // layer 2: agg + gemm (-> gnn_x output) + bn
    k_agg<<<NN, 128>>>(hbn, DH, off, csr, a2, DX, 0);
    {
        dim3 g(DOUT / 128, (NN + 127) / 128);
        k_gemm_mma<<<g, 256>>>(a2, w2, b2l, out_gnn, NN, DOUT, DX, DOUT);
    }
    k_bnsum<<<dim3(DOUT / 256, NCHUNK), 256>>>(out_gnn, NN, DOUT, part);
    k_bnfin<<<2, 256>>>(part, bng, bnb, sc2, sh2, NN, DOUT);
    k_bnapply<<<2048, 256>>>(out_gnn, sc2, sh2, bnx, nullptr, NN, DOUT, 0);

    // x with compensate scatter (-> x output)
    k_buildx<<<2048, 256>>>(bnx, h1c, h2c, ls, ld, out_x);

    // pair branch: U = x @ bcat^T over unique nodes
    {
        dim3 g(4096 / 128, (NN + 127) / 128);
        k_gemm_mma<<<g, 256>>>(out_x, bcat, nullptr, U, NN, 4096, DX, 4096);
    }
    // fused gather + bias + LN + ReLU
    k_pairln_g<<<NP, 256>>>(U, psrc, pdst, bp, plng, plnb, z2);
    // heads (skinny N=42)
    {
        dim3 g(1, (NP + 127) / 128);
        k_gemm_sk<<<g, 256>>>(z2, wpe, bpe, heads, NP, 42, DZ, 42);
    }
    k_split<<<2048, 256>>>(heads, out_pl, out_pc);

    // node branch
    {
        dim3 g(DOUT / 128, (NN + 127) / 128);
        k_gemm_mma<<<g, 256>>>(out_x, Wnm, bnm, tbuf, NN, DOUT, DX, DOUT);
    }
    k_nodeln<<<NN, 128>>>(tbuf, nlng, nlnb, x1r);
    {
        dim3 g(1, (NN + 127) / 128);
        k_gemm_sk<<<g, 256>>>(x1r, Wnc, bnc, out_node, NN, NC, DOUT, NC);
    }
}

// round 5
// speedup vs baseline: 3.3343x; 1.0418x over previous
#include <cuda_runtime.h>
#include <cuda_bf16.h>
#include <cstdint>

#define NN 10000
#define NE 160000
#define NP 20000
#define DIN 256
#define DH  512
#define DOUT 512
#define DX  1024
#define DZ  2048
#define NC  40
#define EPSV 1e-5f
#define NCHUNK 40
#define CHROWS 250

// ---------------- static scratch (fp32) ----------------
#define OF_H    0L
#define OF_HBN  (OF_H   + (long)NN*DH)
#define OF_BNX  (OF_HBN + (long)NN*DH)
#define OF_U    (OF_BNX + (long)NN*DOUT)     // U  [NN,4096]
#define OF_Z2   (OF_U   + (long)NN*4096)     // z2 [NP,2048]
#define OF_WPE  (OF_Z2  + (long)NP*DZ)
#define OF_BPE  (OF_WPE + 42L*DZ)
#define OF_HEADS (OF_BPE + 64L)
#define OF_T    (OF_HEADS + (long)NP*48)
#define OF_X1R  (OF_T   + (long)NN*DOUT)
#define OF_PART (OF_X1R + (long)NN*DOUT)
#define OF_SC1  (OF_PART + 41984L)
#define OF_SH1  (OF_SC1 + 512L)
#define OF_SC2  (OF_SH1 + 512L)
#define OF_SH2  (OF_SC2 + 512L)
#define F_TOTAL (OF_SH2 + 512L)

__device__ __align__(256) float g_f[F_TOTAL];

// ---------------- static scratch (bf16 hi/lo planes) ----------------
#define OB_A1H  0L
#define OB_A1L  (OB_A1H + (long)NN*DH)
#define OB_A2H  (OB_A1L + (long)NN*DH)
#define OB_A2L  (OB_A2H + (long)NN*DX)
#define OB_XH   (OB_A2L + (long)NN*DX)
#define OB_XL   (OB_XH  + (long)NN*DX)
#define OB_W1H  (OB_XL  + (long)NN*DX)
#define OB_W1L  (OB_W1H + (long)DH*DH)
#define OB_W2H  (OB_W1L + (long)DH*DH)
#define OB_W2L  (OB_W2H + (long)DOUT*DX)
#define OB_BCH  (OB_W2L + (long)DOUT*DX)
#define OB_BCL  (OB_BCH + 4096L*DX)
#define OB_WNH  (OB_BCL + 4096L*DX)
#define OB_WNL  (OB_WNH + (long)DOUT*DX)
#define B_TOTAL (OB_WNL + (long)DOUT*DX)

__device__ __align__(256) __nv_bfloat16 g_b[B_TOTAL];

#define OI_DEG 0
#define OI_OFF 10016
#define OI_CUR 20032
#define OI_CSR 30048
#define OI_LS  190048
#define OI_LD  200048
#define I_TOTAL 210064
__device__ __align__(256) int g_i[I_TOTAL];

// ---------------- bf16 split helpers ----------------
__device__ __forceinline__ uint32_t pack_bf2(float lo_el, float hi_el) {
    uint32_t r;
    asm("cvt.rn.bf16x2.f32 %0, %1, %2;" : "=r"(r) : "f"(hi_el), "f"(lo_el));
    return r;
}
__device__ __forceinline__ float bfl(uint32_t p) { return __uint_as_float(p << 16); }
__device__ __forceinline__ float bfh(uint32_t p) { return __uint_as_float(p & 0xffff0000u); }

__device__ __forceinline__ void split4(float4 v, uint2& h, uint2& l) {
    uint32_t h0 = pack_bf2(v.x, v.y);
    uint32_t h1 = pack_bf2(v.z, v.w);
    uint32_t l0 = pack_bf2(v.x - bfl(h0), v.y - bfh(h0));
    uint32_t l1 = pack_bf2(v.z - bfl(h1), v.w - bfh(h1));
    h = make_uint2(h0, h1);
    l = make_uint2(l0, l1);
}

// ---------------- small utility kernels ----------------
__global__ void k_init(int* deg, int* ls, int* ld) {
    int i = blockIdx.x * blockDim.x + threadIdx.x;
    if (i < NN) { deg[i] = 0; ls[i] = -1; ld[i] = -1; }
}

__global__ void k_deg(const int* __restrict__ dst, int* deg) {
    int e = blockIdx.x * blockDim.x + threadIdx.x;
    if (e < NE) atomicAdd(&deg[dst[e]], 1);
}

__global__ void k_scan(const int* __restrict__ deg, int* off, int* cur) {
    __shared__ int s[1024];
    __shared__ int carry;
    int tid = threadIdx.x;
    if (tid == 0) carry = 0;
    __syncthreads();
    for (int base = 0; base < NN; base += 1024) {
        int i = base + tid;
        int v = (i < NN) ? deg[i] : 0;
        s[tid] = v;
        __syncthreads();
        for (int o = 1; o < 1024; o <<= 1) {
            int t = (tid >= o) ? s[tid - o] : 0;
            __syncthreads();
            s[tid] += t;
            __syncthreads();
        }
        int excl = s[tid] - v;
        int c0 = carry;
        if (i < NN) { off[i] = c0 + excl; cur[i] = c0 + excl; }
        __syncthreads();
        if (tid == 0) carry = c0 + s[1023];
        __syncthreads();
    }
    if (tid == 0) off[NN] = carry;
}

__global__ void k_fill(const int* __restrict__ src, const int* __restrict__ dst,
                       int* cur, int* csr) {
    int e = blockIdx.x * blockDim.x + threadIdx.x;
    if (e < NE) {
        int slot = atomicAdd(&cur[dst[e]], 1);
        csr[slot] = src[e];
    }
}

__global__ void k_lastidx(const int* __restrict__ ps, const int* __restrict__ pd,
                          int* ls, int* ld) {
    int i = blockIdx.x * blockDim.x + threadIdx.x;
    if (i < NP) { atomicMax(&ls[ps[i]], i); atomicMax(&ld[pd[i]], i); }
}

// neighbor max + optional self-copy, emitting hi/lo bf16 planes
__global__ void k_agg_b(const float* __restrict__ X, int D, const int* __restrict__ off,
                        const int* __restrict__ csr, __nv_bfloat16* __restrict__ oh,
                        __nv_bfloat16* __restrict__ ol, int ldo, int copyself) {
    int n = blockIdx.x;
    int s = off[n], e = off[n + 1];
    int nv = D >> 2;
    const float4* X4 = (const float4*)X;
    for (int c = threadIdx.x; c < nv; c += blockDim.x) {
        float4 m = make_float4(0.f, 0.f, 0.f, 0.f);
        if (e > s) {
            m = __ldg(&X4[(long)csr[s] * nv + c]);
            for (int i = s + 1; i < e; i++) {
                float4 v = __ldg(&X4[(long)csr[i] * nv + c]);
                m.x = fmaxf(m.x, v.x); m.y = fmaxf(m.y, v.y);
                m.z = fmaxf(m.z, v.z); m.w = fmaxf(m.w, v.w);
            }
        }
        uint2 h, l;
        split4(m, h, l);
        *(uint2*)(oh + (long)n * ldo + 4 * c) = h;
        *(uint2*)(ol + (long)n * ldo + 4 * c) = l;
        if (copyself) {
            float4 sv = __ldg(&X4[(long)n * nv + c]);
            split4(sv, h, l);
            *(uint2*)(oh + (long)n * ldo + D + 4 * c) = h;
            *(uint2*)(ol + (long)n * ldo + D + 4 * c) = l;
        }
    }
}

// concat two [rows,ka]/[rows,kb] fp32 weights into hi/lo bf16 planes [rows, ka+kb]
__global__ void k_cat_b(const float* __restrict__ A, const float* __restrict__ B,
                        __nv_bfloat16* __restrict__ dh, __nv_bfloat16* __restrict__ dl,
                        int rows, int ka, int kb) {
    int kc = ka + kb;
    int cq = kc >> 2;
    int total = rows * cq;
    for (int idx = blockIdx.x * blockDim.x + threadIdx.x; idx < total;
         idx += gridDim.x * blockDim.x) {
        int r = idx / cq, c = (idx % cq) * 4;
        float4 v = (c < ka) ? *(const float4*)(A + (long)r * ka + c)
                            : *(const float4*)(B + (long)r * kb + (c - ka));
        uint2 h, l;
        split4(v, h, l);
        *(uint2*)(dh + (long)r * kc + c) = h;
        *(uint2*)(dl + (long)r * kc + c) = l;
    }
}

// fp32 matrix -> hi/lo bf16 planes
__global__ void k_cvt_b(const float* __restrict__ W, __nv_bfloat16* __restrict__ dh,
                        __nv_bfloat16* __restrict__ dl, int total4) {
    for (int idx = blockIdx.x * blockDim.x + threadIdx.x; idx < total4;
         idx += gridDim.x * blockDim.x) {
        float4 v = ((const float4*)W)[idx];
        uint2 h, l;
        split4(v, h, l);
        ((uint2*)dh)[idx] = h;
        ((uint2*)dl)[idx] = l;
    }
}

// Bcat[4096,1024] hi/lo planes from Wp[2048,2048]
__global__ void k_bcat_b(const float* __restrict__ Wp, __nv_bfloat16* __restrict__ dh,
                         __nv_bfloat16* __restrict__ dl) {
    int total = 4096 * (DX >> 2);
    for (int idx = blockIdx.x * blockDim.x + threadIdx.x; idx < total;
         idx += gridDim.x * blockDim.x) {
        int n = idx >> 8, k = (idx & 255) * 4;
        const float* src = (n < 2048) ? Wp + (long)n * DZ + k
                                      : Wp + (long)(n - 2048) * DZ + 1024 + k;
        float4 v = *(const float4*)src;
        uint2 h, l;
        split4(v, h, l);
        *(uint2*)(dh + (long)n * DX + k) = h;
        *(uint2*)(dl + (long)n * DX + k) = l;
    }
}

__global__ void k_wpe(const float* __restrict__ Wpc, const float* __restrict__ bpc,
                      const float* __restrict__ We, const float* __restrict__ be,
                      float* wpe, float* bpe) {
    for (int idx = blockIdx.x * blockDim.x + threadIdx.x; idx < 42 * DZ;
         idx += gridDim.x * blockDim.x) {
        int r = idx / DZ, k = idx % DZ;
        wpe[idx] = (r < 40) ? Wpc[(long)r * DZ + k] : We[(long)(r - 40) * DZ + k];
        if (idx < 42) bpe[idx] = (idx < 40) ? bpc[idx] : be[idx - 40];
    }
}

// ---------------- BN ----------------
__global__ void k_bnsum(const float* __restrict__ H, int M, int C,
                        float* __restrict__ part) {
    int c = blockIdx.x * blockDim.x + threadIdx.x;
    int r0 = blockIdx.y * CHROWS;
    int r1 = min(r0 + CHROWS, M);
    float s = 0.f, q = 0.f;
    for (int r = r0; r < r1; r++) {
        float v = H[(long)r * C + c];
        s += v; q += v * v;
    }
    part[((long)blockIdx.y * C + c) * 2 + 0] = s;
    part[((long)blockIdx.y * C + c) * 2 + 1] = q;
}

__global__ void k_bnfin(const float* __restrict__ part, const float* __restrict__ g,
                        const float* __restrict__ b, float* scale, float* shift,
                        int M, int C) {
    int c = blockIdx.x * blockDim.x + threadIdx.x;
    if (c >= C) return;
    float s = 0.f, q = 0.f;
    for (int ch = 0; ch < NCHUNK; ch++) {
        s += part[((long)ch * C + c) * 2 + 0];
        q += part[((long)ch * C + c) * 2 + 1];
    }
    float mu = s / (float)M;
    float var = q / (float)M - mu * mu;
    float sc = g[c] * rsqrtf(var + EPSV);
    scale[c] = sc;
    shift[c] = b[c] - mu * sc;
}

// BN apply: fp32 out, optional bf16 hi/lo plane copy at column offset coff
__global__ void k_bnapply_b(const float* __restrict__ H, const float* __restrict__ scale,
                            const float* __restrict__ shift, float* __restrict__ out,
                            __nv_bfloat16* __restrict__ o2h, __nv_bfloat16* __restrict__ o2l,
                            int M, int C, int ldo2, int coff) {
    int cq = C >> 2;
    int total = M * cq;
    for (int idx = blockIdx.x * blockDim.x + threadIdx.x; idx < total;
         idx += gridDim.x * blockDim.x) {
        int r = idx / cq, c4 = idx % cq;
        float4 v = ((const float4*)H)[idx];
        float4 sc = ((const float4*)scale)[c4];
        float4 sh = ((const float4*)shift)[c4];
        v.x = v.x * sc.x + sh.x;
        v.y = v.y * sc.y + sh.y;
        v.z = v.z * sc.z + sh.z;
        v.w = v.w * sc.w + sh.w;
        ((float4*)out)[idx] = v;
        if (o2h) {
            uint2 h, l;
            split4(v, h, l);
            *(uint2*)(o2h + (long)r * ldo2 + coff + 4 * c4) = h;
            *(uint2*)(o2l + (long)r * ldo2 + coff + 4 * c4) = l;
        }
    }
}

// build x (fp32 output) + hi/lo planes
__global__ void k_buildx(const float* __restrict__ bnx, const float* __restrict__ h1c,
                         const float* __restrict__ h2c, const int* __restrict__ ls,
                         const int* __restrict__ ld, float* __restrict__ xout,
                         __nv_bfloat16* __restrict__ xh, __nv_bfloat16* __restrict__ xl) {
    int total = NN * (DOUT / 4);
    for (int idx = blockIdx.x * blockDim.x + threadIdx.x; idx < total;
         idx += gridDim.x * blockDim.x) {
        int n = idx >> 7;
        int c4 = idx & 127;
        float4 sec = ((const float4*)(bnx + (long)n * DOUT))[c4];
        float4 fir;
        int li = ld[n];
        if (li >= 0) fir = ((const float4*)(h2c + (long)li * DOUT))[c4];
        else {
            int si = ls[n];
            fir = (si >= 0) ? ((const float4*)(h1c + (long)si * DOUT))[c4] : sec;
        }
        ((float4*)(xout + (long)n * DX))[c4] = fir;
        ((float4*)(xout + (long)n * DX + DOUT))[c4] = sec;
        uint2 h, l;
        split4(fir, h, l);
        *(uint2*)(xh + (long)n * DX + 4 * c4) = h;
        *(uint2*)(xl + (long)n * DX + 4 * c4) = l;
        split4(sec, h, l);
        *(uint2*)(xh + (long)n * DX + DOUT + 4 * c4) = h;
        *(uint2*)(xl + (long)n * DX + DOUT + 4 * c4) = l;
    }
}

// ================= bf16x3 tensor-core GEMM (pre-split planes) =================
// C[M,N] = A[M,K] @ B[N,K]^T (+bias). N % 128 == 0, K % 16 == 0.
// 128x128 CTA tile, BK=16, 8 warps (2x4), warp tile 64x32.
#define SPAD2 24

#define MMA_BF16(d, a, b)                                                      \
    asm volatile(                                                              \
        "mma.sync.aligned.m16n8k16.row.col.f32.bf16.bf16.f32 "                 \
        "{%0,%1,%2,%3}, {%4,%5,%6,%7}, {%8,%9}, {%0,%1,%2,%3};"                \
        : "+f"(d[0]), "+f"(d[1]), "+f"(d[2]), "+f"(d[3])                       \
        : "r"(a[0]), "r"(a[1]), "r"(a[2]), "r"(a[3]), "r"(b[0]), "r"(b[1]))

__global__ void __launch_bounds__(256)
k_gemm_bb(const __nv_bfloat16* __restrict__ Ah, const __nv_bfloat16* __restrict__ Al,
          const __nv_bfloat16* __restrict__ Bh, const __nv_bfloat16* __restrict__ Bl,
          const float* __restrict__ bias, float* __restrict__ C,
          int M, int N, int K, int ldc) {
    __shared__ __align__(16) __nv_bfloat16 sA[2][2][128][SPAD2];
    __shared__ __align__(16) __nv_bfloat16 sB[2][2][128][SPAD2];

    int tid = threadIdx.x;
    int wid = tid >> 5, lane = tid & 31;
    int wm = wid >> 2, wn = wid & 3;
    int lrow = lane >> 2, lcol = (lane & 3) << 1;

    int arow = tid >> 1;
    int ahalf = (tid & 1) << 3;
    long gm = (long)blockIdx.y * 128 + arow;
    long gn = (long)blockIdx.x * 128 + arow;
    bool okm = gm < M;
    bool okn = gn < N;
    const __nv_bfloat16* Aph = Ah + gm * K + ahalf;
    const __nv_bfloat16* Apl = Al + gm * K + ahalf;
    const __nv_bfloat16* Bph = Bh + gn * K + ahalf;
    const __nv_bfloat16* Bpl = Bl + gn * K + ahalf;
    uint4 zu = make_uint4(0, 0, 0, 0);

    float acc[4][4][4];
#pragma unroll
    for (int mi = 0; mi < 4; mi++)
#pragma unroll
        for (int ni = 0; ni < 4; ni++)
#pragma unroll
            for (int r = 0; r < 4; r++) acc[mi][ni][r] = 0.f;

    // stage k-tile 0
    {
        uint4 vah = okm ? *(const uint4*)Aph : zu;
        uint4 val = okm ? *(const uint4*)Apl : zu;
        uint4 vbh = okn ? *(const uint4*)Bph : zu;
        uint4 vbl = okn ? *(const uint4*)Bpl : zu;
        *(uint4*)&sA[0][0][arow][ahalf] = vah;
        *(uint4*)&sA[0][1][arow][ahalf] = val;
        *(uint4*)&sB[0][0][arow][ahalf] = vbh;
        *(uint4*)&sB[0][1][arow][ahalf] = vbl;
    }
    __syncthreads();

    int nk = K >> 4;
    for (int kt = 0; kt < nk; kt++) {
        int buf = kt & 1;
        uint4 vah, val, vbh, vbl;
        bool more = (kt + 1) < nk;
        if (more) {
            int k0 = (kt + 1) << 4;
            vah = okm ? *(const uint4*)(Aph + k0) : zu;
            val = okm ? *(const uint4*)(Apl + k0) : zu;
            vbh = okn ? *(const uint4*)(Bph + k0) : zu;
            vbl = okn ? *(const uint4*)(Bpl + k0) : zu;
        }

        uint32_t ah[4][4], al[4][4], bh[4][2], bl[4][2];
#pragma unroll
        for (int mi = 0; mi < 4; mi++) {
            int r0 = wm * 64 + mi * 16 + lrow;
            ah[mi][0] = *(const uint32_t*)&sA[buf][0][r0][lcol];
            ah[mi][1] = *(const uint32_t*)&sA[buf][0][r0 + 8][lcol];
            ah[mi][2] = *(const uint32_t*)&sA[buf][0][r0][lcol + 8];
            ah[mi][3] = *(const uint32_t*)&sA[buf][0][r0 + 8][lcol + 8];
            al[mi][0] = *(const uint32_t*)&sA[buf][1][r0][lcol];
            al[mi][1] = *(const uint32_t*)&sA[buf][1][r0 + 8][lcol];
            al[mi][2] = *(const uint32_t*)&sA[buf][1][r0][lcol + 8];
            al[mi][3] = *(const uint32_t*)&sA[buf][1][r0 + 8][lcol + 8];
        }
#pragma unroll
        for (int ni = 0; ni < 4; ni++) {
            int r0 = wn * 32 + ni * 8 + lrow;
            bh[ni][0] = *(const uint32_t*)&sB[buf][0][r0][lcol];
            bh[ni][1] = *(const uint32_t*)&sB[buf][0][r0][lcol + 8];
            bl[ni][0] = *(const uint32_t*)&sB[buf][1][r0][lcol];
            bl[ni][1] = *(const uint32_t*)&sB[buf][1][r0][lcol + 8];
        }
#pragma unroll
        for (int mi = 0; mi < 4; mi++)
#pragma unroll
            for (int ni = 0; ni < 4; ni++) {
                MMA_BF16(acc[mi][ni], ah[mi], bh[ni]);
                MMA_BF16(acc[mi][ni], ah[mi], bl[ni]);
                MMA_BF16(acc[mi][ni], al[mi], bh[ni]);
            }

        if (more) {
            int nb = buf ^ 1;
            *(uint4*)&sA[nb][0][arow][ahalf] = vah;
            *(uint4*)&sA[nb][1][arow][ahalf] = val;
            *(uint4*)&sB[nb][0][arow][ahalf] = vbh;
            *(uint4*)&sB[nb][1][arow][ahalf] = vbl;
        }
        __syncthreads();
    }

    int mbase = blockIdx.y * 128 + wm * 64 + lrow;
    int nbase = blockIdx.x * 128 + wn * 32 + lcol;
#pragma unroll
    for (int mi = 0; mi < 4; mi++) {
        int m0 = mbase + mi * 16;
#pragma unroll
        for (int ni = 0; ni < 4; ni++) {
            int n0 = nbase + ni * 8;
            float b0v = bias ? bias[n0] : 0.f;
            float b1v = bias ? bias[n0 + 1] : 0.f;
            if (m0 < M) {
                C[(long)m0 * ldc + n0] = acc[mi][ni][0] + b0v;
                C[(long)m0 * ldc + n0 + 1] = acc[mi][ni][1] + b1v;
            }
            if (m0 + 8 < M) {
                C[(long)(m0 + 8) * ldc + n0] = acc[mi][ni][2] + b0v;
                C[(long)(m0 + 8) * ldc + n0 + 1] = acc[mi][ni][3] + b1v;
            }
        }
    }
}

// ---------------- skinny-N GEMM: 128 x <=48 tile, BK=16 ----------------
__global__ void __launch_bounds__(256)
k_gemm_sk(const float* __restrict__ A, const float* __restrict__ B,
          const float* __restrict__ bias, float* __restrict__ C,
          int M, int N, int K, int ldc) {
    __shared__ float As[16][128];
    __shared__ float Bs[16][48];
    int tid = threadIdx.x;
    int tr = tid >> 4;
    int tc = tid & 15;
    int arow = tid >> 1;
    int acol = (tid & 1) << 3;
    long gm = (long)blockIdx.y * 128 + arow;
    bool okm = gm < M;
    const float* Ap = A + gm * K + acol;
    int bn = tid >> 2;
    int bk = (tid & 3) << 2;
    bool okb = (tid < 192) && (bn < N);
    const float* Bp = B + (long)bn * K + bk;
    float4 z4 = make_float4(0.f, 0.f, 0.f, 0.f);

    float acc[8][3];
#pragma unroll
    for (int i = 0; i < 8; i++)
#pragma unroll
        for (int j = 0; j < 3; j++) acc[i][j] = 0.f;

    for (int k0 = 0; k0 < K; k0 += 16) {
        float4 a0 = okm ? *(const float4*)(Ap + k0) : z4;
        float4 a1 = okm ? *(const float4*)(Ap + k0 + 4) : z4;
        float4 bvv = okb ? *(const float4*)(Bp + k0) : z4;
        __syncthreads();
        As[acol + 0][arow] = a0.x; As[acol + 1][arow] = a0.y;
        As[acol + 2][arow] = a0.z; As[acol + 3][arow] = a0.w;
        As[acol + 4][arow] = a1.x; As[acol + 5][arow] = a1.y;
        As[acol + 6][arow] = a1.z; As[acol + 7][arow] = a1.w;
        if (tid < 192) {
            Bs[bk + 0][bn] = bvv.x; Bs[bk + 1][bn] = bvv.y;
            Bs[bk + 2][bn] = bvv.z; Bs[bk + 3][bn] = bvv.w;
        }
        __syncthreads();
#pragma unroll
        for (int k = 0; k < 16; k++) {
            float4 r0 = *(const float4*)&As[k][tr * 8];
            float4 r1 = *(const float4*)&As[k][tr * 8 + 4];
            float ra[8] = {r0.x, r0.y, r0.z, r0.w, r1.x, r1.y, r1.z, r1.w};
            float b0 = Bs[k][tc * 3 + 0];
            float b1 = Bs[k][tc * 3 + 1];
            float b2 = Bs[k][tc * 3 + 2];
#pragma unroll
            for (int i = 0; i < 8; i++) {
                acc[i][0] += ra[i] * b0;
                acc[i][1] += ra[i] * b1;
                acc[i][2] += ra[i] * b2;
            }
        }
    }
    int mb = blockIdx.y * 128 + tr * 8;
    int nb = tc * 3;
#pragma unroll
    for (int i = 0; i < 8; i++) {
        int m = mb + i;
        if (m < M) {
#pragma unroll
            for (int j = 0; j < 3; j++) {
                int n = nb + j;
                if (n < N) C[(long)m * ldc + n] = acc[i][j] + bias[n];
            }
        }
    }
}

// ---------------- reductions / norms ----------------
__device__ __forceinline__ float blk_sum(float v, float* sm) {
    __syncthreads();
    int lane = threadIdx.x & 31, w = threadIdx.x >> 5;
#pragma unroll
    for (int o = 16; o; o >>= 1) v += __shfl_down_sync(0xffffffffu, v, o);
    if (lane == 0) sm[w] = v;
    __syncthreads();
    if (w == 0) {
        int nw = (blockDim.x + 31) >> 5;
        float t = (lane < nw) ? sm[lane] : 0.f;
#pragma unroll
        for (int o = 16; o; o >>= 1) t += __shfl_down_sync(0xffffffffu, t, o);
        if (lane == 0) sm[0] = t;
    }
    __syncthreads();
    return sm[0];
}

__device__ __forceinline__ float4 f4add(float4 a, float4 b) {
    return make_float4(a.x + b.x, a.y + b.y, a.z + b.z, a.w + b.w);
}

__global__ void __launch_bounds__(256)
k_pairln_g(const float* __restrict__ U, const int* __restrict__ ps,
           const int* __restrict__ pd, const float* __restrict__ bp,
           const float* __restrict__ g, const float* __restrict__ b,
           float* __restrict__ Z2) {
    __shared__ float sm[32];
    int p = blockIdx.x;
    long bs = (long)ps[p] * 1024;
    long bd = (long)pd[p] * 1024 + 512;
    int t = threadIdx.x;
    const float4* U4 = (const float4*)U;
    const float4* bp4 = (const float4*)bp;
    float4 v0 = f4add(f4add(U4[bs + t], U4[bd + t]), bp4[t]);
    float4 v1 = f4add(f4add(U4[bs + t + 256], U4[bd + t + 256]), bp4[t + 256]);
    float s = v0.x + v0.y + v0.z + v0.w + v1.x + v1.y + v1.z + v1.w;
    float mu = blk_sum(s, sm) * (1.0f / DZ);
    float q = (v0.x - mu) * (v0.x - mu) + (v0.y - mu) * (v0.y - mu) +
              (v0.z - mu) * (v0.z - mu) + (v0.w - mu) * (v0.w - mu) +
              (v1.x - mu) * (v1.x - mu) + (v1.y - mu) * (v1.y - mu) +
              (v1.z - mu) * (v1.z - mu) + (v1.w - mu) * (v1.w - mu);
    float var = blk_sum(q, sm) * (1.0f / DZ);
    float rs = rsqrtf(var + EPSV);
    const float4* g4 = (const float4*)g;
    const float4* b4 = (const float4*)b;
    float4* o = (float4*)(Z2 + (long)p * DZ);
    float4 gg = g4[t], bb = b4[t], w;
    w.x = fmaxf((v0.x - mu) * rs * gg.x + bb.x, 0.f);
    w.y = fmaxf((v0.y - mu) * rs * gg.y + bb.y, 0.f);
    w.z = fmaxf((v0.z - mu) * rs * gg.z + bb.z, 0.f);
    w.w = fmaxf((v0.w - mu) * rs * gg.w + bb.w, 0.f);
    o[t] = w;
    gg = g4[t + 256]; bb = b4[t + 256];
    w.x = fmaxf((v1.x - mu) * rs * gg.x + bb.x, 0.f);
    w.y = fmaxf((v1.y - mu) * rs * gg.y + bb.y, 0.f);
    w.z = fmaxf((v1.z - mu) * rs * gg.z + bb.z, 0.f);
    w.w = fmaxf((v1.w - mu) * rs * gg.w + bb.w, 0.f);
    o[t + 256] = w;
}

__global__ void __launch_bounds__(128)
k_nodeln(const float* __restrict__ T, const float* __restrict__ g,
         const float* __restrict__ b, float* __restrict__ O) {
    __shared__ float sm[32];
    long r = blockIdx.x;
    const float4* row = (const float4*)(T + r * DOUT);
    int t = threadIdx.x;
    float4 v = row[t];
    float s = v.x + v.y + v.z + v.w;
    float mu = blk_sum(s, sm) * (1.0f / DOUT);
    float q = (v.x - mu) * (v.x - mu) + (v.y - mu) * (v.y - mu) +
              (v.z - mu) * (v.z - mu) + (v.w - mu) * (v.w - mu);
    float var = blk_sum(q, sm) * (1.0f / DOUT);
    float rs = rsqrtf(var + EPSV);
    float4 gg = ((const float4*)g)[t], bb = ((const float4*)b)[t], w;
    w.x = fmaxf((v.x - mu) * rs * gg.x + bb.x, 0.f);
    w.y = fmaxf((v.y - mu) * rs * gg.y + bb.y, 0.f);
    w.z = fmaxf((v.z - mu) * rs * gg.z + bb.z, 0.f);
    w.w = fmaxf((v.w - mu) * rs * gg.w + bb.w, 0.f);
    ((float4*)(O + r * DOUT))[t] = w;
}

__global__ void k_split(const float* __restrict__ heads, float* __restrict__ pl,
                        float* __restrict__ pc) {
    int total = NP * 42;
    for (int idx = blockIdx.x * blockDim.x + threadIdx.x; idx < total;
         idx += gridDim.x * blockDim.x) {
        int r = idx / 42, c = idx % 42;
        float v = heads[(long)r * 42 + c];
        if (c < 40) pl[(long)r * 40 + c] = v;
        else pc[(long)r * 2 + (c - 40)] = v;
    }
}

// ---------------- host ----------------
extern "C" void kernel_launch(void* const* d_in, const int* in_sizes, int n_in,
                              void* d_out, int out_size) {
    const float* x_feat = (const float*)d_in[0];
    const int*   eidx   = (const int*)d_in[1];
    const int*   pidx   = (const int*)d_in[2];
    const float* h1c = (const float*)d_in[3];
    const float* h2c = (const float*)d_in[4];
    const float* W1l = (const float*)d_in[5];
    const float* b1l = (const float*)d_in[6];
    const float* W1r = (const float*)d_in[7];
    const float* bn1g = (const float*)d_in[8];
    const float* bn1b = (const float*)d_in[9];
    const float* W2l = (const float*)d_in[10];
    const float* b2l = (const float*)d_in[11];
    const float* W2r = (const float*)d_in[12];
    const float* bng = (const float*)d_in[13];
    const float* bnb = (const float*)d_in[14];
    const float* Wp  = (const float*)d_in[15];
    const float* bp  = (const float*)d_in[16];
    const float* plng = (const float*)d_in[17];
    const float* plnb = (const float*)d_in[18];
    const float* Wpc = (const float*)d_in[19];
    const float* bpc = (const float*)d_in[20];
    const float* We  = (const float*)d_in[21];
    const float* be  = (const float*)d_in[22];
    const float* Wnm = (const float*)d_in[23];
    const float* bnm = (const float*)d_in[24];
    const float* nlng = (const float*)d_in[25];
    const float* nlnb = (const float*)d_in[26];
    const float* Wnc = (const float*)d_in[27];
    const float* bnc = (const float*)d_in[28];

    float* out = (float*)d_out;
    float* out_node = out;
    float* out_pl   = out + (long)NN * NC;
    float* out_pc   = out_pl + (long)NP * NC;
    float* out_x    = out_pc + (long)NP * 2;
    float* out_gnn  = out_x + (long)NN * DX;

    float* F; int* I; __nv_bfloat16* Bb;
    cudaGetSymbolAddress((void**)&F, g_f);
    cudaGetSymbolAddress((void**)&I, g_i);
    cudaGetSymbolAddress((void**)&Bb, g_b);
    float* h    = F + OF_H;
    float* hbn  = F + OF_HBN;
    float* bnx  = F + OF_BNX;
    float* U    = F + OF_U;
    float* z2   = F + OF_Z2;
    float* wpe  = F + OF_WPE;
    float* bpe  = F + OF_BPE;
    float* heads = F + OF_HEADS;
    float* tbuf = F + OF_T;
    float* x1r  = F + OF_X1R;
    float* part = F + OF_PART;
    float* sc1  = F + OF_SC1;
    float* sh1  = F + OF_SH1;
    float* sc2  = F + OF_SC2;
    float* sh2  = F + OF_SH2;
    __nv_bfloat16* a1h = Bb + OB_A1H;
    __nv_bfloat16* a1l = Bb + OB_A1L;
    __nv_bfloat16* a2h = Bb + OB_A2H;
    __nv_bfloat16* a2l = Bb + OB_A2L;
    __nv_bfloat16* xh  = Bb + OB_XH;
    __nv_bfloat16* xl  = Bb + OB_XL;
    __nv_bfloat16* w1h = Bb + OB_W1H;
    __nv_bfloat16* w1l = Bb + OB_W1L;
    __nv_bfloat16* w2h = Bb + OB_W2H;
    __nv_bfloat16* w2l = Bb + OB_W2L;
    __nv_bfloat16* bch = Bb + OB_BCH;
    __nv_bfloat16* bcl = Bb + OB_BCL;
    __nv_bfloat16* wnh = Bb + OB_WNH;
    __nv_bfloat16* wnl = Bb + OB_WNL;
    int* deg = I + OI_DEG;
    int* off = I + OI_OFF;
    int* cur = I + OI_CUR;
    int* csr = I + OI_CSR;
    int* ls  = I + OI_LS;
    int* ld  = I + OI_LD;
    const int* esrc = eidx;
    const int* edst = eidx + NE;
    const int* psrc = pidx;
    const int* pdst = pidx + NP;

    // CSR build + scatter-last-index
    k_init<<<(NN + 255) / 256, 256>>>(deg, ls, ld);
    k_deg<<<(NE + 255) / 256, 256>>>(edst, deg);
    k_scan<<<1, 1024>>>(deg, off, cur);
    k_fill<<<(NE + 255) / 256, 256>>>(esrc, edst, cur, csr);
    k_lastidx<<<(NP + 255) / 256, 256>>>(psrc, pdst, ls, ld);

    // weight preprocessing (fp32 -> bf16 hi/lo planes)
    k_cat_b<<<256, 256>>>(W1l, W1r, w1h, w1l, DH, DIN, DIN);
    k_cat_b<<<512, 256>>>(W2l, W2r, w2h, w2l, DOUT, DH, DH);
    k_wpe<<<336, 256>>>(Wpc, bpc, We, be, wpe, bpe);
    k_bcat_b<<<2048, 256>>>(Wp, bch, bcl);
    k_cvt_b<<<512, 256>>>(Wnm, wnh, wnl, DOUT * DX / 4);

    // layer 1
    k_agg_b<<<NN, 64>>>(x_feat, DIN, off, csr, a1h, a1l, DH, 1);
    {
        dim3 g(DH / 128, (NN + 127) / 128);
        k_gemm_bb<<<g, 256>>>(a1h, a1l, w1h, w1l, b1l, h, NN, DH, DH, DH);
    }
    k_bnsum<<<dim3(DH / 256, NCHUNK), 256>>>(h, NN, DH, part);
    k_bnfin<<<2, 256>>>(part, bn1g, bn1b, sc1, sh1, NN, DH);
    k_bnapply_b<<<2048, 256>>>(h, sc1, sh1, hbn, a2h, a2l, NN, DH, DX, DH);

    // layer 2
    k_agg_b<<<NN, 128>>>(hbn, DH, off, csr, a2h, a2l, DX, 0);
    {
        dim3 g(DOUT / 128, (NN + 127) / 128);
        k_gemm_bb<<<g, 256>>>(a2h, a2l, w2h, w2l, b2l, out_gnn, NN, DOUT, DX, DOUT);
    }
    k_bnsum<<<dim3(DOUT / 256, NCHUNK), 256>>>(out_gnn, NN, DOUT, part);
    k_bnfin<<<2, 256>>>(part, bng, bnb, sc2, sh2, NN, DOUT);
    k_bnapply_b<<<2048, 256>>>(out_gnn, sc2, sh2, bnx, (__nv_bfloat16*)nullptr,
                               (__nv_bfloat16*)nullptr, NN, DOUT, 0, 0);

    // x with compensate scatter (fp32 output + planes)
    k_buildx<<<2048, 256>>>(bnx, h1c, h2c, ls, ld, out_x, xh, xl);

    // pair branch
    {
        dim3 g(4096 / 128, (NN + 127) / 128);
        k_gemm_bb<<<g, 256>>>(xh, xl, bch, bcl, nullptr, U, NN, 4096, DX, 4096);
    }
    k_pairln_g<<<NP, 256>>>(U, psrc, pdst, bp, plng, plnb, z2);
    {
        dim3 g(1, (NP + 127) / 128);
        k_gemm_sk<<<g, 256>>>(z2, wpe, bpe, heads, NP, 42, DZ, 42);
    }
    k_split<<<2048, 256>>>(heads, out_pl, out_pc);

    // node branch
    {
        dim3 g(DOUT / 128, (NN + 127) / 128);
        k_gemm_bb<<<g, 256>>>(xh, xl, wnh, wnl, bnm, tbuf, NN, DOUT, DX, DOUT);
    }
    k_nodeln<<<NN, 128>>>(tbuf, nlng, nlnb, x1r);
    {
        dim3 g(1, (NN + 127) / 128);
        k_gemm_sk<<<g, 256>>>(x1r, Wnc, bnc, out_node, NN, NC, DOUT, NC);
    }
}

// round 6
// speedup vs baseline: 4.1232x; 1.2366x over previous
#include <cuda_runtime.h>
#include <cuda_fp16.h>
#include <cstdint>

#define NN 10000
#define NE 160000
#define NP 20000
#define DIN 256
#define DH  512
#define DOUT 512
#define DX  1024
#define DZ  2048
#define NC  40
#define EPSV 1e-5f
#define NCHUNK 40
#define CHROWS 250

// ---------------- static scratch (fp32) ----------------
#define OF_H    0L
#define OF_HBN  (OF_H   + (long)NN*DH)
#define OF_U    (OF_HBN + (long)NN*DH)       // U  [NN,4096]
#define OF_Z2   (OF_U   + (long)NN*4096)     // z2 [NP,2048]
#define OF_WPE  (OF_Z2  + (long)NP*DZ)
#define OF_BPE  (OF_WPE + 42L*DZ)
#define OF_T    (OF_BPE + 64L)
#define OF_X1R  (OF_T   + (long)NN*DOUT)
#define OF_PART (OF_X1R + (long)NN*DOUT)
#define OF_SC1  (OF_PART + 41984L)
#define OF_SH1  (OF_SC1 + 512L)
#define OF_SC2  (OF_SH1 + 512L)
#define OF_SH2  (OF_SC2 + 512L)
#define F_TOTAL (OF_SH2 + 512L)

__device__ __align__(256) float g_f[F_TOTAL];

// ---------------- static scratch (fp16 hi/lo planes) ----------------
#define OB_A1H  0L
#define OB_A1L  (OB_A1H + (long)NN*DH)
#define OB_A2H  (OB_A1L + (long)NN*DH)
#define OB_A2L  (OB_A2H + (long)NN*DX)
#define OB_XH   (OB_A2L + (long)NN*DX)
#define OB_XL   (OB_XH  + (long)NN*DX)
#define OB_W1H  (OB_XL  + (long)NN*DX)
#define OB_W1L  (OB_W1H + (long)DH*DH)
#define OB_W2H  (OB_W1L + (long)DH*DH)
#define OB_W2L  (OB_W2H + (long)DOUT*DX)
#define OB_BCH  (OB_W2L + (long)DOUT*DX)
#define OB_WNH  (OB_BCH + 4096L*DX)
#define B_TOTAL (OB_WNH + (long)DOUT*DX)

__device__ __align__(256) __half g_b[B_TOTAL];

#define OI_DEG 0
#define OI_OFF 10016
#define OI_CUR 20032
#define OI_CSR 30048
#define OI_LS  190048
#define OI_LD  200048
#define I_TOTAL 210064
__device__ __align__(256) int g_i[I_TOTAL];

// ---------------- fp16 split helpers ----------------
__device__ __forceinline__ void split4h(float4 v, uint2& h, uint2& l) {
    __half2 h0 = __floats2half2_rn(v.x, v.y);
    __half2 h1 = __floats2half2_rn(v.z, v.w);
    float2 f0 = __half22float2(h0);
    float2 f1 = __half22float2(h1);
    __half2 l0 = __floats2half2_rn(v.x - f0.x, v.y - f0.y);
    __half2 l1 = __floats2half2_rn(v.z - f1.x, v.w - f1.y);
    h = make_uint2(*(uint32_t*)&h0, *(uint32_t*)&h1);
    l = make_uint2(*(uint32_t*)&l0, *(uint32_t*)&l1);
}

__device__ __forceinline__ uint2 cvt4h(float4 v) {
    __half2 h0 = __floats2half2_rn(v.x, v.y);
    __half2 h1 = __floats2half2_rn(v.z, v.w);
    return make_uint2(*(uint32_t*)&h0, *(uint32_t*)&h1);
}

// ---------------- small utility kernels ----------------
__global__ void k_init(int* deg, int* ls, int* ld) {
    int i = blockIdx.x * blockDim.x + threadIdx.x;
    if (i < NN) { deg[i] = 0; ls[i] = -1; ld[i] = -1; }
}

__global__ void k_deg(const int* __restrict__ dst, int* deg) {
    int e = blockIdx.x * blockDim.x + threadIdx.x;
    if (e < NE) atomicAdd(&deg[dst[e]], 1);
}

__global__ void k_scan(const int* __restrict__ deg, int* off, int* cur) {
    __shared__ int s[1024];
    __shared__ int carry;
    int tid = threadIdx.x;
    if (tid == 0) carry = 0;
    __syncthreads();
    for (int base = 0; base < NN; base += 1024) {
        int i = base + tid;
        int v = (i < NN) ? deg[i] : 0;
        s[tid] = v;
        __syncthreads();
        for (int o = 1; o < 1024; o <<= 1) {
            int t = (tid >= o) ? s[tid - o] : 0;
            __syncthreads();
            s[tid] += t;
            __syncthreads();
        }
        int excl = s[tid] - v;
        int c0 = carry;
        if (i < NN) { off[i] = c0 + excl; cur[i] = c0 + excl; }
        __syncthreads();
        if (tid == 0) carry = c0 + s[1023];
        __syncthreads();
    }
    if (tid == 0) off[NN] = carry;
}

__global__ void k_fill(const int* __restrict__ src, const int* __restrict__ dst,
                       int* cur, int* csr) {
    int e = blockIdx.x * blockDim.x + threadIdx.x;
    if (e < NE) {
        int slot = atomicAdd(&cur[dst[e]], 1);
        csr[slot] = src[e];
    }
}

__global__ void k_lastidx(const int* __restrict__ ps, const int* __restrict__ pd,
                          int* ls, int* ld) {
    int i = blockIdx.x * blockDim.x + threadIdx.x;
    if (i < NP) { atomicMax(&ls[ps[i]], i); atomicMax(&ld[pd[i]], i); }
}

// neighbor max + optional self-copy, emitting hi/lo fp16 planes
__global__ void k_agg_b(const float* __restrict__ X, int D, const int* __restrict__ off,
                        const int* __restrict__ csr, __half* __restrict__ oh,
                        __half* __restrict__ ol, int ldo, int copyself) {
    int n = blockIdx.x;
    int s = off[n], e = off[n + 1];
    int nv = D >> 2;
    const float4* X4 = (const float4*)X;
    for (int c = threadIdx.x; c < nv; c += blockDim.x) {
        float4 m = make_float4(0.f, 0.f, 0.f, 0.f);
        if (e > s) {
            m = __ldg(&X4[(long)csr[s] * nv + c]);
            for (int i = s + 1; i < e; i++) {
                float4 v = __ldg(&X4[(long)csr[i] * nv + c]);
                m.x = fmaxf(m.x, v.x); m.y = fmaxf(m.y, v.y);
                m.z = fmaxf(m.z, v.z); m.w = fmaxf(m.w, v.w);
            }
        }
        uint2 h, l;
        split4h(m, h, l);
        *(uint2*)(oh + (long)n * ldo + 4 * c) = h;
        *(uint2*)(ol + (long)n * ldo + 4 * c) = l;
        if (copyself) {
            float4 sv = __ldg(&X4[(long)n * nv + c]);
            split4h(sv, h, l);
            *(uint2*)(oh + (long)n * ldo + D + 4 * c) = h;
            *(uint2*)(ol + (long)n * ldo + D + 4 * c) = l;
        }
    }
}

// concat two fp32 weights into hi/lo fp16 planes
__global__ void k_cat_b(const float* __restrict__ A, const float* __restrict__ B,
                        __half* __restrict__ dh, __half* __restrict__ dl,
                        int rows, int ka, int kb) {
    int kc = ka + kb;
    int cq = kc >> 2;
    int total = rows * cq;
    for (int idx = blockIdx.x * blockDim.x + threadIdx.x; idx < total;
         idx += gridDim.x * blockDim.x) {
        int r = idx / cq, c = (idx % cq) * 4;
        float4 v = (c < ka) ? *(const float4*)(A + (long)r * ka + c)
                            : *(const float4*)(B + (long)r * kb + (c - ka));
        uint2 h, l;
        split4h(v, h, l);
        *(uint2*)(dh + (long)r * kc + c) = h;
        *(uint2*)(dl + (long)r * kc + c) = l;
    }
}

// fp32 matrix -> single fp16 plane
__global__ void k_cvt_h(const float* __restrict__ W, __half* __restrict__ dh,
                        int total4) {
    for (int idx = blockIdx.x * blockDim.x + threadIdx.x; idx < total4;
         idx += gridDim.x * blockDim.x) {
        ((uint2*)dh)[idx] = cvt4h(((const float4*)W)[idx]);
    }
}

// Bcat[4096,1024] single fp16 plane from Wp[2048,2048]
__global__ void k_bcat_h(const float* __restrict__ Wp, __half* __restrict__ dh) {
    int total = 4096 * (DX >> 2);
    for (int idx = blockIdx.x * blockDim.x + threadIdx.x; idx < total;
         idx += gridDim.x * blockDim.x) {
        int n = idx >> 8, k = (idx & 255) * 4;
        const float* src = (n < 2048) ? Wp + (long)n * DZ + k
                                      : Wp + (long)(n - 2048) * DZ + 1024 + k;
        *(uint2*)(dh + (long)n * DX + k) = cvt4h(*(const float4*)src);
    }
}

__global__ void k_wpe(const float* __restrict__ Wpc, const float* __restrict__ bpc,
                      const float* __restrict__ We, const float* __restrict__ be,
                      float* wpe, float* bpe) {
    for (int idx = blockIdx.x * blockDim.x + threadIdx.x; idx < 42 * DZ;
         idx += gridDim.x * blockDim.x) {
        int r = idx / DZ, k = idx % DZ;
        wpe[idx] = (r < 40) ? Wpc[(long)r * DZ + k] : We[(long)(r - 40) * DZ + k];
        if (idx < 42) bpe[idx] = (idx < 40) ? bpc[idx] : be[idx - 40];
    }
}

// ---------------- BN ----------------
__global__ void k_bnsum(const float* __restrict__ H, int M, int C,
                        float* __restrict__ part) {
    int c = blockIdx.x * blockDim.x + threadIdx.x;
    int r0 = blockIdx.y * CHROWS;
    int r1 = min(r0 + CHROWS, M);
    float s = 0.f, q = 0.f;
    for (int r = r0; r < r1; r++) {
        float v = H[(long)r * C + c];
        s += v; q += v * v;
    }
    part[((long)blockIdx.y * C + c) * 2 + 0] = s;
    part[((long)blockIdx.y * C + c) * 2 + 1] = q;
}

__global__ void k_bnfin(const float* __restrict__ part, const float* __restrict__ g,
                        const float* __restrict__ b, float* scale, float* shift,
                        int M, int C) {
    int c = blockIdx.x * blockDim.x + threadIdx.x;
    if (c >= C) return;
    float s = 0.f, q = 0.f;
    for (int ch = 0; ch < NCHUNK; ch++) {
        s += part[((long)ch * C + c) * 2 + 0];
        q += part[((long)ch * C + c) * 2 + 1];
    }
    float mu = s / (float)M;
    float var = q / (float)M - mu * mu;
    float sc = g[c] * rsqrtf(var + EPSV);
    scale[c] = sc;
    shift[c] = b[c] - mu * sc;
}

// BN apply (layer1): fp32 out + fp16 hi/lo planes at column offset coff
__global__ void k_bnapply_b(const float* __restrict__ H, const float* __restrict__ scale,
                            const float* __restrict__ shift, float* __restrict__ out,
                            __half* __restrict__ o2h, __half* __restrict__ o2l,
                            int M, int C, int ldo2, int coff) {
    int cq = C >> 2;
    int total = M * cq;
    for (int idx = blockIdx.x * blockDim.x + threadIdx.x; idx < total;
         idx += gridDim.x * blockDim.x) {
        int r = idx / cq, c4 = idx % cq;
        float4 v = ((const float4*)H)[idx];
        float4 sc = ((const float4*)scale)[c4];
        float4 sh = ((const float4*)shift)[c4];
        v.x = v.x * sc.x + sh.x;
        v.y = v.y * sc.y + sh.y;
        v.z = v.z * sc.z + sh.z;
        v.w = v.w * sc.w + sh.w;
        ((float4*)out)[idx] = v;
        uint2 h, l;
        split4h(v, h, l);
        *(uint2*)(o2h + (long)r * ldo2 + coff + 4 * c4) = h;
        *(uint2*)(o2l + (long)r * ldo2 + coff + 4 * c4) = l;
    }
}

// fused: BN apply (layer2, from out_gnn) + build x (fp32 output + fp16 planes)
__global__ void k_bnbuildx(const float* __restrict__ gnn, const float* __restrict__ scale,
                           const float* __restrict__ shift,
                           const float* __restrict__ h1c, const float* __restrict__ h2c,
                           const int* __restrict__ ls, const int* __restrict__ ld,
                           float* __restrict__ xout,
                           __half* __restrict__ xh, __half* __restrict__ xl) {
    int total = NN * (DOUT / 4);
    for (int idx = blockIdx.x * blockDim.x + threadIdx.x; idx < total;
         idx += gridDim.x * blockDim.x) {
        int n = idx >> 7;
        int c4 = idx & 127;
        float4 sec = ((const float4*)(gnn + (long)n * DOUT))[c4];
        float4 sc = ((const float4*)scale)[c4];
        float4 sh = ((const float4*)shift)[c4];
        sec.x = sec.x * sc.x + sh.x;
        sec.y = sec.y * sc.y + sh.y;
        sec.z = sec.z * sc.z + sh.z;
        sec.w = sec.w * sc.w + sh.w;
        float4 fir;
        int li = ld[n];
        if (li >= 0) fir = ((const float4*)(h2c + (long)li * DOUT))[c4];
        else {
            int si = ls[n];
            fir = (si >= 0) ? ((const float4*)(h1c + (long)si * DOUT))[c4] : sec;
        }
        ((float4*)(xout + (long)n * DX))[c4] = fir;
        ((float4*)(xout + (long)n * DX + DOUT))[c4] = sec;
        uint2 h, l;
        split4h(fir, h, l);
        *(uint2*)(xh + (long)n * DX + 4 * c4) = h;
        *(uint2*)(xl + (long)n * DX + 4 * c4) = l;
        split4h(sec, h, l);
        *(uint2*)(xh + (long)n * DX + DOUT + 4 * c4) = h;
        *(uint2*)(xl + (long)n * DX + DOUT + 4 * c4) = l;
    }
}

// ================= fp16 split tensor-core GEMM =================
// C[M,N] = A[M,K] @ B[N,K]^T (+bias). N % 128 == 0, K % 16 == 0.
// TERMS=3: Ah*Bh + Ah*Bl + Al*Bh (weights 2-plane).
// TERMS=2: Ah*Bh + Al*Bh (exact A x fp16 weights).
#define SPAD2 24

#define MMA_F16(d, a, b)                                                       \
    asm volatile(                                                              \
        "mma.sync.aligned.m16n8k16.row.col.f32.f16.f16.f32 "                   \
        "{%0,%1,%2,%3}, {%4,%5,%6,%7}, {%8,%9}, {%0,%1,%2,%3};"                \
        : "+f"(d[0]), "+f"(d[1]), "+f"(d[2]), "+f"(d[3])                       \
        : "r"(a[0]), "r"(a[1]), "r"(a[2]), "r"(a[3]), "r"(b[0]), "r"(b[1]))

template <int TERMS>
__global__ void __launch_bounds__(256)
k_gemm_bb(const __half* __restrict__ Ah, const __half* __restrict__ Al,
          const __half* __restrict__ Bh, const __half* __restrict__ Bl,
          const float* __restrict__ bias, float* __restrict__ C,
          int M, int N, int K, int ldc) {
    __shared__ __align__(16) __half sA[2][2][128][SPAD2];
    __shared__ __align__(16) __half sB[2][2][128][SPAD2];

    int tid = threadIdx.x;
    int wid = tid >> 5, lane = tid & 31;
    int wm = wid >> 2, wn = wid & 3;
    int lrow = lane >> 2, lcol = (lane & 3) << 1;

    int arow = tid >> 1;
    int ahalf = (tid & 1) << 3;
    long gm = (long)blockIdx.y * 128 + arow;
    long gn = (long)blockIdx.x * 128 + arow;
    bool okm = gm < M;
    bool okn = gn < N;
    const __half* Aph = Ah + gm * K + ahalf;
    const __half* Apl = Al + gm * K + ahalf;
    const __half* Bph = Bh + gn * K + ahalf;
    const __half* Bpl = (TERMS == 3) ? (Bl + gn * K + ahalf) : nullptr;
    uint4 zu = make_uint4(0, 0, 0, 0);

    float acc[4][4][4];
#pragma unroll
    for (int mi = 0; mi < 4; mi++)
#pragma unroll
        for (int ni = 0; ni < 4; ni++)
#pragma unroll
            for (int r = 0; r < 4; r++) acc[mi][ni][r] = 0.f;

    {
        uint4 vah = okm ? *(const uint4*)Aph : zu;
        uint4 val = okm ? *(const uint4*)Apl : zu;
        uint4 vbh = okn ? *(const uint4*)Bph : zu;
        *(uint4*)&sA[0][0][arow][ahalf] = vah;
        *(uint4*)&sA[0][1][arow][ahalf] = val;
        *(uint4*)&sB[0][0][arow][ahalf] = vbh;
        if (TERMS == 3) {
            uint4 vbl = okn ? *(const uint4*)Bpl : zu;
            *(uint4*)&sB[0][1][arow][ahalf] = vbl;
        }
    }
    __syncthreads();

    int nk = K >> 4;
    for (int kt = 0; kt < nk; kt++) {
        int buf = kt & 1;
        uint4 vah, val, vbh, vbl;
        bool more = (kt + 1) < nk;
        if (more) {
            int k0 = (kt + 1) << 4;
            vah = okm ? *(const uint4*)(Aph + k0) : zu;
            val = okm ? *(const uint4*)(Apl + k0) : zu;
            vbh = okn ? *(const uint4*)(Bph + k0) : zu;
            if (TERMS == 3) vbl = okn ? *(const uint4*)(Bpl + k0) : zu;
        }

        uint32_t ah[4][4], al[4][4], bh[4][2], bl[4][2];
#pragma unroll
        for (int mi = 0; mi < 4; mi++) {
            int r0 = wm * 64 + mi * 16 + lrow;
            ah[mi][0] = *(const uint32_t*)&sA[buf][0][r0][lcol];
            ah[mi][1] = *(const uint32_t*)&sA[buf][0][r0 + 8][lcol];
            ah[mi][2] = *(const uint32_t*)&sA[buf][0][r0][lcol + 8];
            ah[mi][3] = *(const uint32_t*)&sA[buf][0][r0 + 8][lcol + 8];
            al[mi][0] = *(const uint32_t*)&sA[buf][1][r0][lcol];
            al[mi][1] = *(const uint32_t*)&sA[buf][1][r0 + 8][lcol];
            al[mi][2] = *(const uint32_t*)&sA[buf][1][r0][lcol + 8];
            al[mi][3] = *(const uint32_t*)&sA[buf][1][r0 + 8][lcol + 8];
        }
#pragma unroll
        for (int ni = 0; ni < 4; ni++) {
            int r0 = wn * 32 + ni * 8 + lrow;
            bh[ni][0] = *(const uint32_t*)&sB[buf][0][r0][lcol];
            bh[ni][1] = *(const uint32_t*)&sB[buf][0][r0][lcol + 8];
            if (TERMS == 3) {
                bl[ni][0] = *(const uint32_t*)&sB[buf][1][r0][lcol];
                bl[ni][1] = *(const uint32_t*)&sB[buf][1][r0][lcol + 8];
            }
        }
#pragma unroll
        for (int mi = 0; mi < 4; mi++)
#pragma unroll
            for (int ni = 0; ni < 4; ni++) {
                MMA_F16(acc[mi][ni], ah[mi], bh[ni]);
                if (TERMS == 3) MMA_F16(acc[mi][ni], ah[mi], bl[ni]);
                MMA_F16(acc[mi][ni], al[mi], bh[ni]);
            }

        if (more) {
            int nb = buf ^ 1;
            *(uint4*)&sA[nb][0][arow][ahalf] = vah;
            *(uint4*)&sA[nb][1][arow][ahalf] = val;
            *(uint4*)&sB[nb][0][arow][ahalf] = vbh;
            if (TERMS == 3) *(uint4*)&sB[nb][1][arow][ahalf] = vbl;
        }
        __syncthreads();
    }

    int mbase = blockIdx.y * 128 + wm * 64 + lrow;
    int nbase = blockIdx.x * 128 + wn * 32 + lcol;
#pragma unroll
    for (int mi = 0; mi < 4; mi++) {
        int m0 = mbase + mi * 16;
#pragma unroll
        for (int ni = 0; ni < 4; ni++) {
            int n0 = nbase + ni * 8;
            float b0v = bias ? bias[n0] : 0.f;
            float b1v = bias ? bias[n0 + 1] : 0.f;
            if (m0 < M) {
                C[(long)m0 * ldc + n0] = acc[mi][ni][0] + b0v;
                C[(long)m0 * ldc + n0 + 1] = acc[mi][ni][1] + b1v;
            }
            if (m0 + 8 < M) {
                C[(long)(m0 + 8) * ldc + n0] = acc[mi][ni][2] + b0v;
                C[(long)(m0 + 8) * ldc + n0 + 1] = acc[mi][ni][3] + b1v;
            }
        }
    }
}

// ---------------- skinny-N GEMM: 128 x <=48 tile, BK=16 ----------------
// if pc != nullptr: split-write cols [0,40) -> C (ld 40), cols 40,41 -> pc (ld 2)
__global__ void __launch_bounds__(256)
k_gemm_sk(const float* __restrict__ A, const float* __restrict__ B,
          const float* __restrict__ bias, float* __restrict__ C,
          float* __restrict__ pc, int M, int N, int K, int ldc) {
    __shared__ float As[16][128];
    __shared__ float Bs[16][48];
    int tid = threadIdx.x;
    int tr = tid >> 4;
    int tc = tid & 15;
    int arow = tid >> 1;
    int acol = (tid & 1) << 3;
    long gm = (long)blockIdx.y * 128 + arow;
    bool okm = gm < M;
    const float* Ap = A + gm * K + acol;
    int bn = tid >> 2;
    int bk = (tid & 3) << 2;
    bool okb = (tid < 192) && (bn < N);
    const float* Bp = B + (long)bn * K + bk;
    float4 z4 = make_float4(0.f, 0.f, 0.f, 0.f);

    float acc[8][3];
#pragma unroll
    for (int i = 0; i < 8; i++)
#pragma unroll
        for (int j = 0; j < 3; j++) acc[i][j] = 0.f;

    for (int k0 = 0; k0 < K; k0 += 16) {
        float4 a0 = okm ? *(const float4*)(Ap + k0) : z4;
        float4 a1 = okm ? *(const float4*)(Ap + k0 + 4) : z4;
        float4 bvv = okb ? *(const float4*)(Bp + k0) : z4;
        __syncthreads();
        As[acol + 0][arow] = a0.x; As[acol + 1][arow] = a0.y;
        As[acol + 2][arow] = a0.z; As[acol + 3][arow] = a0.w;
        As[acol + 4][arow] = a1.x; As[acol + 5][arow] = a1.y;
        As[acol + 6][arow] = a1.z; As[acol + 7][arow] = a1.w;
        if (tid < 192) {
            Bs[bk + 0][bn] = bvv.x; Bs[bk + 1][bn] = bvv.y;
            Bs[bk + 2][bn] = bvv.z; Bs[bk + 3][bn] = bvv.w;
        }
        __syncthreads();
#pragma unroll
        for (int k = 0; k < 16; k++) {
            float4 r0 = *(const float4*)&As[k][tr * 8];
            float4 r1 = *(const float4*)&As[k][tr * 8 + 4];
            float ra[8] = {r0.x, r0.y, r0.z, r0.w, r1.x, r1.y, r1.z, r1.w};
            float b0 = Bs[k][tc * 3 + 0];
            float b1 = Bs[k][tc * 3 + 1];
            float b2 = Bs[k][tc * 3 + 2];
#pragma unroll
            for (int i = 0; i < 8; i++) {
                acc[i][0] += ra[i] * b0;
                acc[i][1] += ra[i] * b1;
                acc[i][2] += ra[i] * b2;
            }
        }
    }
    int mb = blockIdx.y * 128 + tr * 8;
    int nb = tc * 3;
#pragma unroll
    for (int i = 0; i < 8; i++) {
        int m = mb + i;
        if (m < M) {
#pragma unroll
            for (int j = 0; j < 3; j++) {
                int n = nb + j;
                if (n < N) {
                    float v = acc[i][j] + bias[n];
                    if (pc) {
                        if (n < 40) C[(long)m * 40 + n] = v;
                        else pc[(long)m * 2 + (n - 40)] = v;
                    } else {
                        C[(long)m * ldc + n] = v;
                    }
                }
            }
        }
    }
}

// ---------------- reductions / norms ----------------
__device__ __forceinline__ float blk_sum(float v, float* sm) {
    __syncthreads();
    int lane = threadIdx.x & 31, w = threadIdx.x >> 5;
#pragma unroll
    for (int o = 16; o; o >>= 1) v += __shfl_down_sync(0xffffffffu, v, o);
    if (lane == 0) sm[w] = v;
    __syncthreads();
    if (w == 0) {
        int nw = (blockDim.x + 31) >> 5;
        float t = (lane < nw) ? sm[lane] : 0.f;
#pragma unroll
        for (int o = 16; o; o >>= 1) t += __shfl_down_sync(0xffffffffu, t, o);
        if (lane == 0) sm[0] = t;
    }
    __syncthreads();
    return sm[0];
}

__device__ __forceinline__ float4 f4add(float4 a, float4 b) {
    return make_float4(a.x + b.x, a.y + b.y, a.z + b.z, a.w + b.w);
}

__global__ void __launch_bounds__(256)
k_pairln_g(const float* __restrict__ U, const int* __restrict__ ps,
           const int* __restrict__ pd, const float* __restrict__ bp,
           const float* __restrict__ g, const float* __restrict__ b,
           float* __restrict__ Z2) {
    __shared__ float sm[32];
    int p = blockIdx.x;
    long bs = (long)ps[p] * 1024;
    long bd = (long)pd[p] * 1024 + 512;
    int t = threadIdx.x;
    const float4* U4 = (const float4*)U;
    const float4* bp4 = (const float4*)bp;
    float4 v0 = f4add(f4add(U4[bs + t], U4[bd + t]), bp4[t]);
    float4 v1 = f4add(f4add(U4[bs + t + 256], U4[bd + t + 256]), bp4[t + 256]);
    float s = v0.x + v0.y + v0.z + v0.w + v1.x + v1.y + v1.z + v1.w;
    float mu = blk_sum(s, sm) * (1.0f / DZ);
    float q = (v0.x - mu) * (v0.x - mu) + (v0.y - mu) * (v0.y - mu) +
              (v0.z - mu) * (v0.z - mu) + (v0.w - mu) * (v0.w - mu) +
              (v1.x - mu) * (v1.x - mu) + (v1.y - mu) * (v1.y - mu) +
              (v1.z - mu) * (v1.z - mu) + (v1.w - mu) * (v1.w - mu);
    float var = blk_sum(q, sm) * (1.0f / DZ);
    float rs = rsqrtf(var + EPSV);
    const float4* g4 = (const float4*)g;
    const float4* b4 = (const float4*)b;
    float4* o = (float4*)(Z2 + (long)p * DZ);
    float4 gg = g4[t], bb = b4[t], w;
    w.x = fmaxf((v0.x - mu) * rs * gg.x + bb.x, 0.f);
    w.y = fmaxf((v0.y - mu) * rs * gg.y + bb.y, 0.f);
    w.z = fmaxf((v0.z - mu) * rs * gg.z + bb.z, 0.f);
    w.w = fmaxf((v0.w - mu) * rs * gg.w + bb.w, 0.f);
    o[t] = w;
    gg = g4[t + 256]; bb = b4[t + 256];
    w.x = fmaxf((v1.x - mu) * rs * gg.x + bb.x, 0.f);
    w.y = fmaxf((v1.y - mu) * rs * gg.y + bb.y, 0.f);
    w.z = fmaxf((v1.z - mu) * rs * gg.z + bb.z, 0.f);
    w.w = fmaxf((v1.w - mu) * rs * gg.w + bb.w, 0.f);
    o[t + 256] = w;
}

__global__ void __launch_bounds__(128)
k_nodeln(const float* __restrict__ T, const float* __restrict__ g,
         const float* __restrict__ b, float* __restrict__ O) {
    __shared__ float sm[32];
    long r = blockIdx.x;
    const float4* row = (const float4*)(T + r * DOUT);
    int t = threadIdx.x;
    float4 v = row[t];
    float s = v.x + v.y + v.z + v.w;
    float mu = blk_sum(s, sm) * (1.0f / DOUT);
    float q = (v.x - mu) * (v.x - mu) + (v.y - mu) * (v.y - mu) +
              (v.z - mu) * (v.z - mu) + (v.w - mu) * (v.w - mu);
    float var = blk_sum(q, sm) * (1.0f / DOUT);
    float rs = rsqrtf(var + EPSV);
    float4 gg = ((const float4*)g)[t], bb = ((const float4*)b)[t], w;
    w.x = fmaxf((v.x - mu) * rs * gg.x + bb.x, 0.f);
    w.y = fmaxf((v.y - mu) * rs * gg.y + bb.y, 0.f);
    w.z = fmaxf((v.z - mu) * rs * gg.z + bb.z, 0.f);
    w.w = fmaxf((v.w - mu) * rs * gg.w + bb.w, 0.f);
    ((float4*)(O + r * DOUT))[t] = w;
}

// ---------------- host ----------------
extern "C" void kernel_launch(void* const* d_in, const int* in_sizes, int n_in,
                              void* d_out, int out_size) {
    const float* x_feat = (const float*)d_in[0];
    const int*   eidx   = (const int*)d_in[1];
    const int*   pidx   = (const int*)d_in[2];
    const float* h1c = (const float*)d_in[3];
    const float* h2c = (const float*)d_in[4];
    const float* W1l = (const float*)d_in[5];
    const float* b1l = (const float*)d_in[6];
    const float* W1r = (const float*)d_in[7];
    const float* bn1g = (const float*)d_in[8];
    const float* bn1b = (const float*)d_in[9];
    const float* W2l = (const float*)d_in[10];
    const float* b2l = (const float*)d_in[11];
    const float* W2r = (const float*)d_in[12];
    const float* bng = (const float*)d_in[13];
    const float* bnb = (const float*)d_in[14];
    const float* Wp  = (const float*)d_in[15];
    const float* bp  = (const float*)d_in[16];
    const float* plng = (const float*)d_in[17];
    const float* plnb = (const float*)d_in[18];
    const float* Wpc = (const float*)d_in[19];
    const float* bpc = (const float*)d_in[20];
    const float* We  = (const float*)d_in[21];
    const float* be  = (const float*)d_in[22];
    const float* Wnm = (const float*)d_in[23];
    const float* bnm = (const float*)d_in[24];
    const float* nlng = (const float*)d_in[25];
    const float* nlnb = (const float*)d_in[26];
    const float* Wnc = (const float*)d_in[27];
    const float* bnc = (const float*)d_in[28];

    float* out = (float*)d_out;
    float* out_node = out;
    float* out_pl   = out + (long)NN * NC;
    float* out_pc   = out_pl + (long)NP * NC;
    float* out_x    = out_pc + (long)NP * 2;
    float* out_gnn  = out_x + (long)NN * DX;

    float* F; int* I; __half* Bb;
    cudaGetSymbolAddress((void**)&F, g_f);
    cudaGetSymbolAddress((void**)&I, g_i);
    cudaGetSymbolAddress((void**)&Bb, g_b);
    float* h    = F + OF_H;
    float* hbn  = F + OF_HBN;
    float* U    = F + OF_U;
    float* z2   = F + OF_Z2;
    float* wpe  = F + OF_WPE;
    float* bpe  = F + OF_BPE;
    float* tbuf = F + OF_T;
    float* x1r  = F + OF_X1R;
    float* part = F + OF_PART;
    float* sc1  = F + OF_SC1;
    float* sh1  = F + OF_SH1;
    float* sc2  = F + OF_SC2;
    float* sh2  = F + OF_SH2;
    __half* a1h = Bb + OB_A1H;
    __half* a1l = Bb + OB_A1L;
    __half* a2h = Bb + OB_A2H;
    __half* a2l = Bb + OB_A2L;
    __half* xh  = Bb + OB_XH;
    __half* xl  = Bb + OB_XL;
    __half* w1h = Bb + OB_W1H;
    __half* w1l = Bb + OB_W1L;
    __half* w2h = Bb + OB_W2H;
    __half* w2l = Bb + OB_W2L;
    __half* bch = Bb + OB_BCH;
    __half* wnh = Bb + OB_WNH;
    int* deg = I + OI_DEG;
    int* off = I + OI_OFF;
    int* cur = I + OI_CUR;
    int* csr = I + OI_CSR;
    int* ls  = I + OI_LS;
    int* ld  = I + OI_LD;
    const int* esrc = eidx;
    const int* edst = eidx + NE;
    const int* psrc = pidx;
    const int* pdst = pidx + NP;

    // CSR build + scatter-last-index
    k_init<<<(NN + 255) / 256, 256>>>(deg, ls, ld);
    k_deg<<<(NE + 255) / 256, 256>>>(edst, deg);
    k_scan<<<1, 1024>>>(deg, off, cur);
    k_fill<<<(NE + 255) / 256, 256>>>(esrc, edst, cur, csr);
    k_lastidx<<<(NP + 255) / 256, 256>>>(psrc, pdst, ls, ld);

    // weight preprocessing
    k_cat_b<<<256, 256>>>(W1l, W1r, w1h, w1l, DH, DIN, DIN);
    k_cat_b<<<512, 256>>>(W2l, W2r, w2h, w2l, DOUT, DH, DH);
    k_wpe<<<336, 256>>>(Wpc, bpc, We, be, wpe, bpe);
    k_bcat_h<<<1024, 256>>>(Wp, bch);
    k_cvt_h<<<256, 256>>>(Wnm, wnh, DOUT * DX / 4);

    // layer 1 (3-term fp16 split)
    k_agg_b<<<NN, 64>>>(x_feat, DIN, off, csr, a1h, a1l, DH, 1);
    {
        dim3 g(DH / 128, (NN + 127) / 128);
        k_gemm_bb<3><<<g, 256>>>(a1h, a1l, w1h, w1l, b1l, h, NN, DH, DH, DH);
    }
    k_bnsum<<<dim3(DH / 256, NCHUNK), 256>>>(h, NN, DH, part);
    k_bnfin<<<2, 256>>>(part, bn1g, bn1b, sc1, sh1, NN, DH);
    k_bnapply_b<<<2048, 256>>>(h, sc1, sh1, hbn, a2h, a2l, NN, DH, DX, DH);

    // layer 2 (3-term)
    k_agg_b<<<NN, 128>>>(hbn, DH, off, csr, a2h, a2l, DX, 0);
    {
        dim3 g(DOUT / 128, (NN + 127) / 128);
        k_gemm_bb<3><<<g, 256>>>(a2h, a2l, w2h, w2l, b2l, out_gnn, NN, DOUT, DX, DOUT);
    }
    k_bnsum<<<dim3(DOUT / 256, NCHUNK), 256>>>(out_gnn, NN, DOUT, part);
    k_bnfin<<<2, 256>>>(part, bng, bnb, sc2, sh2, NN, DOUT);

    // fused BN apply + build x (fp32 output + fp16 planes)
    k_bnbuildx<<<2048, 256>>>(out_gnn, sc2, sh2, h1c, h2c, ls, ld, out_x, xh, xl);

    // pair branch: U = x @ bcat^T (2-term: exact x, fp16 weights)
    {
        dim3 g(4096 / 128, (NN + 127) / 128);
        k_gemm_bb<2><<<g, 256>>>(xh, xl, bch, nullptr, nullptr, U, NN, 4096, DX, 4096);
    }
    k_pairln_g<<<NP, 256>>>(U, psrc, pdst, bp, plng, plnb, z2);
    {
        dim3 g(1, (NP + 127) / 128);
        k_gemm_sk<<<g, 256>>>(z2, wpe, bpe, out_pl, out_pc, NP, 42, DZ, 42);
    }

    // node branch (2-term)
    {
        dim3 g(DOUT / 128, (NN + 127) / 128);
        k_gemm_bb<2><<<g, 256>>>(xh, xl, wnh, nullptr, bnm, tbuf, NN, DOUT, DX, DOUT);
    }
    k_nodeln<<<NN, 128>>>(tbuf, nlng, nlnb, x1r);
    {
        dim3 g(1, (NN + 127) / 128);
        k_gemm_sk<<<g, 256>>>(x1r, Wnc, bnc, out_node, nullptr, NN, NC, DOUT, NC);
    }
}

// round 7
// speedup vs baseline: 4.7821x; 1.1598x over previous
#include <cuda_runtime.h>
#include <cuda_fp16.h>
#include <cstdint>

#define NN 10000
#define NE 160000
#define NP 20000
#define DIN 256
#define DH  512
#define DOUT 512
#define DX  1024
#define DZ  2048
#define NC  40
#define EPSV 1e-5f
#define NCHUNK 40
#define CHROWS 250

// ---------------- static scratch (fp32) ----------------
#define OF_H    0L
#define OF_HBN  (OF_H   + (long)NN*DH)
#define OF_BPE  (OF_HBN + (long)NN*DH)
#define OF_T    (OF_BPE + 64L)
#define OF_X1R  (OF_T   + (long)NN*DOUT)
#define OF_PART (OF_X1R + (long)NN*DOUT)
#define OF_SC1  (OF_PART + 41984L)
#define OF_SH1  (OF_SC1 + 512L)
#define OF_SC2  (OF_SH1 + 512L)
#define OF_SH2  (OF_SC2 + 512L)
#define F_TOTAL (OF_SH2 + 512L)

__device__ __align__(256) float g_f[F_TOTAL];

// ---------------- static scratch (fp16) ----------------
#define OB_A1H  0L
#define OB_A1L  (OB_A1H + (long)NN*DH)
#define OB_A2H  (OB_A1L + (long)NN*DH)
#define OB_A2L  (OB_A2H + (long)NN*DX)
#define OB_XH   (OB_A2L + (long)NN*DX)
#define OB_XL   (OB_XH  + (long)NN*DX)
#define OB_W1H  (OB_XL  + (long)NN*DX)
#define OB_W2H  (OB_W1H + (long)DH*DH)
#define OB_BCH  (OB_W2H + (long)DOUT*DX)
#define OB_WNH  (OB_BCH + 4096L*DX)
#define OB_U    (OB_WNH + (long)DOUT*DX)
#define OB_Z2H  (OB_U   + (long)NN*4096)
#define OB_Z2L  (OB_Z2H + (long)NP*DZ)
#define OB_WPEH (OB_Z2L + (long)NP*DZ)
#define B_TOTAL (OB_WPEH + 48L*DZ)

__device__ __align__(256) __half g_b[B_TOTAL];

#define OI_DEG 0
#define OI_OFF 10016
#define OI_CUR 20032
#define OI_CSR 30048
#define OI_LS  190048
#define OI_LD  200048
#define I_TOTAL 210064
__device__ __align__(256) int g_i[I_TOTAL];

// ---------------- fp16 helpers ----------------
__device__ __forceinline__ void split4h(float4 v, uint2& h, uint2& l) {
    __half2 h0 = __floats2half2_rn(v.x, v.y);
    __half2 h1 = __floats2half2_rn(v.z, v.w);
    float2 f0 = __half22float2(h0);
    float2 f1 = __half22float2(h1);
    __half2 l0 = __floats2half2_rn(v.x - f0.x, v.y - f0.y);
    __half2 l1 = __floats2half2_rn(v.z - f1.x, v.w - f1.y);
    h = make_uint2(*(uint32_t*)&h0, *(uint32_t*)&h1);
    l = make_uint2(*(uint32_t*)&l0, *(uint32_t*)&l1);
}

__device__ __forceinline__ uint2 cvt4h(float4 v) {
    __half2 h0 = __floats2half2_rn(v.x, v.y);
    __half2 h1 = __floats2half2_rn(v.z, v.w);
    return make_uint2(*(uint32_t*)&h0, *(uint32_t*)&h1);
}

__device__ __forceinline__ float4 h4tof4(uint2 u) {
    float2 f0 = __half22float2(*(__half2*)&u.x);
    float2 f1 = __half22float2(*(__half2*)&u.y);
    return make_float4(f0.x, f0.y, f1.x, f1.y);
}

// ---------------- small utility kernels ----------------
__global__ void k_init(int* deg, int* ls, int* ld) {
    int i = blockIdx.x * blockDim.x + threadIdx.x;
    if (i < NN) { deg[i] = 0; ls[i] = -1; ld[i] = -1; }
}

__global__ void k_deg(const int* __restrict__ dst, int* deg) {
    int e = blockIdx.x * blockDim.x + threadIdx.x;
    if (e < NE) atomicAdd(&deg[dst[e]], 1);
}

__global__ void k_scan(const int* __restrict__ deg, int* off, int* cur) {
    __shared__ int s[1024];
    __shared__ int carry;
    int tid = threadIdx.x;
    if (tid == 0) carry = 0;
    __syncthreads();
    for (int base = 0; base < NN; base += 1024) {
        int i = base + tid;
        int v = (i < NN) ? deg[i] : 0;
        s[tid] = v;
        __syncthreads();
        for (int o = 1; o < 1024; o <<= 1) {
            int t = (tid >= o) ? s[tid - o] : 0;
            __syncthreads();
            s[tid] += t;
            __syncthreads();
        }
        int excl = s[tid] - v;
        int c0 = carry;
        if (i < NN) { off[i] = c0 + excl; cur[i] = c0 + excl; }
        __syncthreads();
        if (tid == 0) carry = c0 + s[1023];
        __syncthreads();
    }
    if (tid == 0) off[NN] = carry;
}

__global__ void k_fill(const int* __restrict__ src, const int* __restrict__ dst,
                       int* cur, int* csr) {
    int e = blockIdx.x * blockDim.x + threadIdx.x;
    if (e < NE) {
        int slot = atomicAdd(&cur[dst[e]], 1);
        csr[slot] = src[e];
    }
}

__global__ void k_lastidx(const int* __restrict__ ps, const int* __restrict__ pd,
                          int* ls, int* ld) {
    int i = blockIdx.x * blockDim.x + threadIdx.x;
    if (i < NP) { atomicMax(&ls[ps[i]], i); atomicMax(&ld[pd[i]], i); }
}

__global__ void k_agg_b(const float* __restrict__ X, int D, const int* __restrict__ off,
                        const int* __restrict__ csr, __half* __restrict__ oh,
                        __half* __restrict__ ol, int ldo, int copyself) {
    int n = blockIdx.x;
    int s = off[n], e = off[n + 1];
    int nv = D >> 2;
    const float4* X4 = (const float4*)X;
    for (int c = threadIdx.x; c < nv; c += blockDim.x) {
        float4 m = make_float4(0.f, 0.f, 0.f, 0.f);
        if (e > s) {
            m = __ldg(&X4[(long)csr[s] * nv + c]);
            for (int i = s + 1; i < e; i++) {
                float4 v = __ldg(&X4[(long)csr[i] * nv + c]);
                m.x = fmaxf(m.x, v.x); m.y = fmaxf(m.y, v.y);
                m.z = fmaxf(m.z, v.z); m.w = fmaxf(m.w, v.w);
            }
        }
        uint2 h, l;
        split4h(m, h, l);
        *(uint2*)(oh + (long)n * ldo + 4 * c) = h;
        *(uint2*)(ol + (long)n * ldo + 4 * c) = l;
        if (copyself) {
            float4 sv = __ldg(&X4[(long)n * nv + c]);
            split4h(sv, h, l);
            *(uint2*)(oh + (long)n * ldo + D + 4 * c) = h;
            *(uint2*)(ol + (long)n * ldo + D + 4 * c) = l;
        }
    }
}

// concat two fp32 weights into single fp16 hi plane
__global__ void k_cat_h2(const float* __restrict__ A, const float* __restrict__ B,
                         __half* __restrict__ dh, int rows, int ka, int kb) {
    int kc = ka + kb;
    int cq = kc >> 2;
    int total = rows * cq;
    for (int idx = blockIdx.x * blockDim.x + threadIdx.x; idx < total;
         idx += gridDim.x * blockDim.x) {
        int r = idx / cq, c = (idx % cq) * 4;
        float4 v = (c < ka) ? *(const float4*)(A + (long)r * ka + c)
                            : *(const float4*)(B + (long)r * kb + (c - ka));
        *(uint2*)(dh + (long)r * kc + c) = cvt4h(v);
    }
}

__global__ void k_cvt_h(const float* __restrict__ W, __half* __restrict__ dh,
                        int total4) {
    for (int idx = blockIdx.x * blockDim.x + threadIdx.x; idx < total4;
         idx += gridDim.x * blockDim.x) {
        ((uint2*)dh)[idx] = cvt4h(((const float4*)W)[idx]);
    }
}

__global__ void k_bcat_h(const float* __restrict__ Wp, __half* __restrict__ dh) {
    int total = 4096 * (DX >> 2);
    for (int idx = blockIdx.x * blockDim.x + threadIdx.x; idx < total;
         idx += gridDim.x * blockDim.x) {
        int n = idx >> 8, k = (idx & 255) * 4;
        const float* src = (n < 2048) ? Wp + (long)n * DZ + k
                                      : Wp + (long)(n - 2048) * DZ + 1024 + k;
        *(uint2*)(dh + (long)n * DX + k) = cvt4h(*(const float4*)src);
    }
}

// wpe: fp16 hi plane [42,2048] + fp32 bias [42]
__global__ void k_wpe(const float* __restrict__ Wpc, const float* __restrict__ bpc,
                      const float* __restrict__ We, const float* __restrict__ be,
                      __half* wpeh, float* bpe) {
    for (int idx = blockIdx.x * blockDim.x + threadIdx.x; idx < 42 * DZ;
         idx += gridDim.x * blockDim.x) {
        int r = idx / DZ, k = idx % DZ;
        float v = (r < 40) ? Wpc[(long)r * DZ + k] : We[(long)(r - 40) * DZ + k];
        wpeh[idx] = __float2half_rn(v);
        if (idx < 42) bpe[idx] = (idx < 40) ? bpc[idx] : be[idx - 40];
    }
}

// ---------------- BN ----------------
__global__ void k_bnsum(const float* __restrict__ H, int M, int C,
                        float* __restrict__ part) {
    int c = blockIdx.x * blockDim.x + threadIdx.x;
    int r0 = blockIdx.y * CHROWS;
    int r1 = min(r0 + CHROWS, M);
    float s = 0.f, q = 0.f;
    for (int r = r0; r < r1; r++) {
        float v = H[(long)r * C + c];
        s += v; q += v * v;
    }
    part[((long)blockIdx.y * C + c) * 2 + 0] = s;
    part[((long)blockIdx.y * C + c) * 2 + 1] = q;
}

__global__ void k_bnfin(const float* __restrict__ part, const float* __restrict__ g,
                        const float* __restrict__ b, float* scale, float* shift,
                        int M, int C) {
    int c = blockIdx.x * blockDim.x + threadIdx.x;
    if (c >= C) return;
    float s = 0.f, q = 0.f;
    for (int ch = 0; ch < NCHUNK; ch++) {
        s += part[((long)ch * C + c) * 2 + 0];
        q += part[((long)ch * C + c) * 2 + 1];
    }
    float mu = s / (float)M;
    float var = q / (float)M - mu * mu;
    float sc = g[c] * rsqrtf(var + EPSV);
    scale[c] = sc;
    shift[c] = b[c] - mu * sc;
}

__global__ void k_bnapply_b(const float* __restrict__ H, const float* __restrict__ scale,
                            const float* __restrict__ shift, float* __restrict__ out,
                            __half* __restrict__ o2h, __half* __restrict__ o2l,
                            int M, int C, int ldo2, int coff) {
    int cq = C >> 2;
    int total = M * cq;
    for (int idx = blockIdx.x * blockDim.x + threadIdx.x; idx < total;
         idx += gridDim.x * blockDim.x) {
        int r = idx / cq, c4 = idx % cq;
        float4 v = ((const float4*)H)[idx];
        float4 sc = ((const float4*)scale)[c4];
        float4 sh = ((const float4*)shift)[c4];
        v.x = v.x * sc.x + sh.x;
        v.y = v.y * sc.y + sh.y;
        v.z = v.z * sc.z + sh.z;
        v.w = v.w * sc.w + sh.w;
        ((float4*)out)[idx] = v;
        uint2 h, l;
        split4h(v, h, l);
        *(uint2*)(o2h + (long)r * ldo2 + coff + 4 * c4) = h;
        *(uint2*)(o2l + (long)r * ldo2 + coff + 4 * c4) = l;
    }
}

// fused: BN apply (layer2) + build x (fp32 output + fp16 planes)
__global__ void k_bnbuildx(const float* __restrict__ gnn, const float* __restrict__ scale,
                           const float* __restrict__ shift,
                           const float* __restrict__ h1c, const float* __restrict__ h2c,
                           const int* __restrict__ ls, const int* __restrict__ ld,
                           float* __restrict__ xout,
                           __half* __restrict__ xh, __half* __restrict__ xl) {
    int total = NN * (DOUT / 4);
    for (int idx = blockIdx.x * blockDim.x + threadIdx.x; idx < total;
         idx += gridDim.x * blockDim.x) {
        int n = idx >> 7;
        int c4 = idx & 127;
        float4 sec = ((const float4*)(gnn + (long)n * DOUT))[c4];
        float4 sc = ((const float4*)scale)[c4];
        float4 sh = ((const float4*)shift)[c4];
        sec.x = sec.x * sc.x + sh.x;
        sec.y = sec.y * sc.y + sh.y;
        sec.z = sec.z * sc.z + sh.z;
        sec.w = sec.w * sc.w + sh.w;
        float4 fir;
        int li = ld[n];
        if (li >= 0) fir = ((const float4*)(h2c + (long)li * DOUT))[c4];
        else {
            int si = ls[n];
            fir = (si >= 0) ? ((const float4*)(h1c + (long)si * DOUT))[c4] : sec;
        }
        ((float4*)(xout + (long)n * DX))[c4] = fir;
        ((float4*)(xout + (long)n * DX + DOUT))[c4] = sec;
        uint2 h, l;
        split4h(fir, h, l);
        *(uint2*)(xh + (long)n * DX + 4 * c4) = h;
        *(uint2*)(xl + (long)n * DX + 4 * c4) = l;
        split4h(sec, h, l);
        *(uint2*)(xh + (long)n * DX + DOUT + 4 * c4) = h;
        *(uint2*)(xl + (long)n * DX + DOUT + 4 * c4) = l;
    }
}

// ================= fp16 split tensor-core GEMM =================
// TERMS=3: Ah*Bh + Ah*Bl + Al*Bh.  TERMS=2: Ah*Bh + Al*Bh.
// HOUT=1: write fp16 (no bias).  HOUT=0: fp32 + bias.
#define SPAD2 24

#define MMA_F16(d, a, b)                                                       \
    asm volatile(                                                              \
        "mma.sync.aligned.m16n8k16.row.col.f32.f16.f16.f32 "                   \
        "{%0,%1,%2,%3}, {%4,%5,%6,%7}, {%8,%9}, {%0,%1,%2,%3};"                \
        : "+f"(d[0]), "+f"(d[1]), "+f"(d[2]), "+f"(d[3])                       \
        : "r"(a[0]), "r"(a[1]), "r"(a[2]), "r"(a[3]), "r"(b[0]), "r"(b[1]))

template <int TERMS, int HOUT>
__global__ void __launch_bounds__(256)
k_gemm_bb(const __half* __restrict__ Ah, const __half* __restrict__ Al,
          const __half* __restrict__ Bh, const __half* __restrict__ Bl,
          const float* __restrict__ bias, void* __restrict__ Cv,
          int M, int N, int K, int ldc) {
    __shared__ __align__(16) __half sA[2][2][128][SPAD2];
    __shared__ __align__(16) __half sB[2][2][128][SPAD2];

    int tid = threadIdx.x;
    int wid = tid >> 5, lane = tid & 31;
    int wm = wid >> 2, wn = wid & 3;
    int lrow = lane >> 2, lcol = (lane & 3) << 1;

    int arow = tid >> 1;
    int ahalf = (tid & 1) << 3;
    long gm = (long)blockIdx.y * 128 + arow;
    long gn = (long)blockIdx.x * 128 + arow;
    bool okm = gm < M;
    bool okn = gn < N;
    const __half* Aph = Ah + gm * K + ahalf;
    const __half* Apl = Al + gm * K + ahalf;
    const __half* Bph = Bh + gn * K + ahalf;
    const __half* Bpl = (TERMS == 3) ? (Bl + gn * K + ahalf) : nullptr;
    uint4 zu = make_uint4(0, 0, 0, 0);

    float acc[4][4][4];
#pragma unroll
    for (int mi = 0; mi < 4; mi++)
#pragma unroll
        for (int ni = 0; ni < 4; ni++)
#pragma unroll
            for (int r = 0; r < 4; r++) acc[mi][ni][r] = 0.f;

    {
        uint4 vah = okm ? *(const uint4*)Aph : zu;
        uint4 val = okm ? *(const uint4*)Apl : zu;
        uint4 vbh = okn ? *(const uint4*)Bph : zu;
        *(uint4*)&sA[0][0][arow][ahalf] = vah;
        *(uint4*)&sA[0][1][arow][ahalf] = val;
        *(uint4*)&sB[0][0][arow][ahalf] = vbh;
        if (TERMS == 3) {
            uint4 vbl = okn ? *(const uint4*)Bpl : zu;
            *(uint4*)&sB[0][1][arow][ahalf] = vbl;
        }
    }
    __syncthreads();

    int nk = K >> 4;
    for (int kt = 0; kt < nk; kt++) {
        int buf = kt & 1;
        uint4 vah, val, vbh, vbl;
        bool more = (kt + 1) < nk;
        if (more) {
            int k0 = (kt + 1) << 4;
            vah = okm ? *(const uint4*)(Aph + k0) : zu;
            val = okm ? *(const uint4*)(Apl + k0) : zu;
            vbh = okn ? *(const uint4*)(Bph + k0) : zu;
            if (TERMS == 3) vbl = okn ? *(const uint4*)(Bpl + k0) : zu;
        }

        uint32_t ah[4][4], al[4][4], bh[4][2], bl[4][2];
#pragma unroll
        for (int mi = 0; mi < 4; mi++) {
            int r0 = wm * 64 + mi * 16 + lrow;
            ah[mi][0] = *(const uint32_t*)&sA[buf][0][r0][lcol];
            ah[mi][1] = *(const uint32_t*)&sA[buf][0][r0 + 8][lcol];
            ah[mi][2] = *(const uint32_t*)&sA[buf][0][r0][lcol + 8];
            ah[mi][3] = *(const uint32_t*)&sA[buf][0][r0 + 8][lcol + 8];
            al[mi][0] = *(const uint32_t*)&sA[buf][1][r0][lcol];
            al[mi][1] = *(const uint32_t*)&sA[buf][1][r0 + 8][lcol];
            al[mi][2] = *(const uint32_t*)&sA[buf][1][r0][lcol + 8];
            al[mi][3] = *(const uint32_t*)&sA[buf][1][r0 + 8][lcol + 8];
        }
#pragma unroll
        for (int ni = 0; ni < 4; ni++) {
            int r0 = wn * 32 + ni * 8 + lrow;
            bh[ni][0] = *(const uint32_t*)&sB[buf][0][r0][lcol];
            bh[ni][1] = *(const uint32_t*)&sB[buf][0][r0][lcol + 8];
            if (TERMS == 3) {
                bl[ni][0] = *(const uint32_t*)&sB[buf][1][r0][lcol];
                bl[ni][1] = *(const uint32_t*)&sB[buf][1][r0][lcol + 8];
            }
        }
#pragma unroll
        for (int mi = 0; mi < 4; mi++)
#pragma unroll
            for (int ni = 0; ni < 4; ni++) {
                MMA_F16(acc[mi][ni], ah[mi], bh[ni]);
                if (TERMS == 3) MMA_F16(acc[mi][ni], ah[mi], bl[ni]);
                MMA_F16(acc[mi][ni], al[mi], bh[ni]);
            }

        if (more) {
            int nb = buf ^ 1;
            *(uint4*)&sA[nb][0][arow][ahalf] = vah;
            *(uint4*)&sA[nb][1][arow][ahalf] = val;
            *(uint4*)&sB[nb][0][arow][ahalf] = vbh;
            if (TERMS == 3) *(uint4*)&sB[nb][1][arow][ahalf] = vbl;
        }
        __syncthreads();
    }

    int mbase = blockIdx.y * 128 + wm * 64 + lrow;
    int nbase = blockIdx.x * 128 + wn * 32 + lcol;
#pragma unroll
    for (int mi = 0; mi < 4; mi++) {
        int m0 = mbase + mi * 16;
#pragma unroll
        for (int ni = 0; ni < 4; ni++) {
            int n0 = nbase + ni * 8;
            if (HOUT) {
                __half* Ch = (__half*)Cv;
                if (m0 < M) {
                    __half2 p = __floats2half2_rn(acc[mi][ni][0], acc[mi][ni][1]);
                    *(__half2*)(Ch + (long)m0 * ldc + n0) = p;
                }
                if (m0 + 8 < M) {
                    __half2 p = __floats2half2_rn(acc[mi][ni][2], acc[mi][ni][3]);
                    *(__half2*)(Ch + (long)(m0 + 8) * ldc + n0) = p;
                }
            } else {
                float* Cf = (float*)Cv;
                float b0v = bias ? bias[n0] : 0.f;
                float b1v = bias ? bias[n0 + 1] : 0.f;
                if (m0 < M) {
                    Cf[(long)m0 * ldc + n0] = acc[mi][ni][0] + b0v;
                    Cf[(long)m0 * ldc + n0 + 1] = acc[mi][ni][1] + b1v;
                }
                if (m0 + 8 < M) {
                    Cf[(long)(m0 + 8) * ldc + n0] = acc[mi][ni][2] + b0v;
                    Cf[(long)(m0 + 8) * ldc + n0 + 1] = acc[mi][ni][3] + b1v;
                }
            }
        }
    }
}

// ============ heads GEMM: 128x64 tile, N<=64, 2-term, split-write ============
__global__ void __launch_bounds__(256)
k_gemm_h64(const __half* __restrict__ Ah, const __half* __restrict__ Al,
           const __half* __restrict__ Bh, const float* __restrict__ bias,
           float* __restrict__ pl, float* __restrict__ pc, int M, int N, int K) {
    __shared__ __align__(16) __half sA[2][2][128][SPAD2];
    __shared__ __align__(16) __half sB[2][64][SPAD2];

    int tid = threadIdx.x;
    int wid = tid >> 5, lane = tid & 31;
    int wm = wid >> 1, wn = wid & 1;          // 4 x 2 warp grid, warp tile 32x32
    int lrow = lane >> 2, lcol = (lane & 3) << 1;

    int arow = tid >> 1;
    int ahalf = (tid & 1) << 3;
    long gm = (long)blockIdx.y * 128 + arow;
    bool okm = gm < M;
    const __half* Aph = Ah + gm * K + ahalf;
    const __half* Apl = Al + gm * K + ahalf;
    int brow = (tid & 127) >> 1;
    int bhalf2 = (tid & 1) << 3;
    bool bload = tid < 128;
    bool okb = bload && (brow < N);
    const __half* Bph = Bh + (long)brow * K + bhalf2;
    uint4 zu = make_uint4(0, 0, 0, 0);

    float acc[2][4][4];
#pragma unroll
    for (int mi = 0; mi < 2; mi++)
#pragma unroll
        for (int ni = 0; ni < 4; ni++)
#pragma unroll
            for (int r = 0; r < 4; r++) acc[mi][ni][r] = 0.f;

    {
        uint4 vah = okm ? *(const uint4*)Aph : zu;
        uint4 val = okm ? *(const uint4*)Apl : zu;
        *(uint4*)&sA[0][0][arow][ahalf] = vah;
        *(uint4*)&sA[0][1][arow][ahalf] = val;
        if (bload) {
            uint4 vbh = okb ? *(const uint4*)Bph : zu;
            *(uint4*)&sB[0][brow][bhalf2] = vbh;
        }
    }
    __syncthreads();

    int nk = K >> 4;
    for (int kt = 0; kt < nk; kt++) {
        int buf = kt & 1;
        uint4 vah, val, vbh;
        bool more = (kt + 1) < nk;
        if (more) {
            int k0 = (kt + 1) << 4;
            vah = okm ? *(const uint4*)(Aph + k0) : zu;
            val = okm ? *(const uint4*)(Apl + k0) : zu;
            if (bload) vbh = okb ? *(const uint4*)(Bph + k0) : zu;
        }

        uint32_t ah[2][4], al[2][4], bh[4][2];
#pragma unroll
        for (int mi = 0; mi < 2; mi++) {
            int r0 = wm * 32 + mi * 16 + lrow;
            ah[mi][0] = *(const uint32_t*)&sA[buf][0][r0][lcol];
            ah[mi][1] = *(const uint32_t*)&sA[buf][0][r0 + 8][lcol];
            ah[mi][2] = *(const uint32_t*)&sA[buf][0][r0][lcol + 8];
            ah[mi][3] = *(const uint32_t*)&sA[buf][0][r0 + 8][lcol + 8];
            al[mi][0] = *(const uint32_t*)&sA[buf][1][r0][lcol];
            al[mi][1] = *(const uint32_t*)&sA[buf][1][r0 + 8][lcol];
            al[mi][2] = *(const uint32_t*)&sA[buf][1][r0][lcol + 8];
            al[mi][3] = *(const uint32_t*)&sA[buf][1][r0 + 8][lcol + 8];
        }
#pragma unroll
        for (int ni = 0; ni < 4; ni++) {
            int r0 = wn * 32 + ni * 8 + lrow;
            bh[ni][0] = *(const uint32_t*)&sB[buf][r0][lcol];
            bh[ni][1] = *(const uint32_t*)&sB[buf][r0][lcol + 8];
        }
#pragma unroll
        for (int mi = 0; mi < 2; mi++)
#pragma unroll
            for (int ni = 0; ni < 4; ni++) {
                MMA_F16(acc[mi][ni], ah[mi], bh[ni]);
                MMA_F16(acc[mi][ni], al[mi], bh[ni]);
            }

        if (more) {
            int nb = buf ^ 1;
            *(uint4*)&sA[nb][0][arow][ahalf] = vah;
            *(uint4*)&sA[nb][1][arow][ahalf] = val;
            if (bload) *(uint4*)&sB[nb][brow][bhalf2] = vbh;
        }
        __syncthreads();
    }

    int mbase = blockIdx.y * 128 + wm * 32 + lrow;
    int nbase = wn * 32 + lcol;
#pragma unroll
    for (int mi = 0; mi < 2; mi++) {
        int m0 = mbase + mi * 16;
#pragma unroll
        for (int ni = 0; ni < 4; ni++) {
            int n0 = nbase + ni * 8;
#pragma unroll
            for (int r = 0; r < 4; r++) {
                int m = m0 + (r >> 1) * 8;
                int n = n0 + (r & 1);
                if (m < M && n < N) {
                    float v = acc[mi][ni][r] + bias[n];
                    if (n < 40) pl[(long)m * 40 + n] = v;
                    else pc[(long)m * 2 + (n - 40)] = v;
                }
            }
        }
    }
}

// ---------------- skinny-N SIMT GEMM (node head) ----------------
__global__ void __launch_bounds__(256)
k_gemm_sk(const float* __restrict__ A, const float* __restrict__ B,
          const float* __restrict__ bias, float* __restrict__ C,
          int M, int N, int K, int ldc) {
    __shared__ float As[16][128];
    __shared__ float Bs[16][48];
    int tid = threadIdx.x;
    int tr = tid >> 4;
    int tc = tid & 15;
    int arow = tid >> 1;
    int acol = (tid & 1) << 3;
    long gm = (long)blockIdx.y * 128 + arow;
    bool okm = gm < M;
    const float* Ap = A + gm * K + acol;
    int bn = tid >> 2;
    int bk = (tid & 3) << 2;
    bool okb = (tid < 192) && (bn < N);
    const float* Bp = B + (long)bn * K + bk;
    float4 z4 = make_float4(0.f, 0.f, 0.f, 0.f);

    float acc[8][3];
#pragma unroll
    for (int i = 0; i < 8; i++)
#pragma unroll
        for (int j = 0; j < 3; j++) acc[i][j] = 0.f;

    for (int k0 = 0; k0 < K; k0 += 16) {
        float4 a0 = okm ? *(const float4*)(Ap + k0) : z4;
        float4 a1 = okm ? *(const float4*)(Ap + k0 + 4) : z4;
        float4 bvv = okb ? *(const float4*)(Bp + k0) : z4;
        __syncthreads();
        As[acol + 0][arow] = a0.x; As[acol + 1][arow] = a0.y;
        As[acol + 2][arow] = a0.z; As[acol + 3][arow] = a0.w;
        As[acol + 4][arow] = a1.x; As[acol + 5][arow] = a1.y;
        As[acol + 6][arow] = a1.z; As[acol + 7][arow] = a1.w;
        if (tid < 192) {
            Bs[bk + 0][bn] = bvv.x; Bs[bk + 1][bn] = bvv.y;
            Bs[bk + 2][bn] = bvv.z; Bs[bk + 3][bn] = bvv.w;
        }
        __syncthreads();
#pragma unroll
        for (int k = 0; k < 16; k++) {
            float4 r0 = *(const float4*)&As[k][tr * 8];
            float4 r1 = *(const float4*)&As[k][tr * 8 + 4];
            float ra[8] = {r0.x, r0.y, r0.z, r0.w, r1.x, r1.y, r1.z, r1.w};
            float b0 = Bs[k][tc * 3 + 0];
            float b1 = Bs[k][tc * 3 + 1];
            float b2 = Bs[k][tc * 3 + 2];
#pragma unroll
            for (int i = 0; i < 8; i++) {
                acc[i][0] += ra[i] * b0;
                acc[i][1] += ra[i] * b1;
                acc[i][2] += ra[i] * b2;
            }
        }
    }
    int mb = blockIdx.y * 128 + tr * 8;
    int nb = tc * 3;
#pragma unroll
    for (int i = 0; i < 8; i++) {
        int m = mb + i;
        if (m < M) {
#pragma unroll
            for (int j = 0; j < 3; j++) {
                int n = nb + j;
                if (n < N) C[(long)m * ldc + n] = acc[i][j] + bias[n];
            }
        }
    }
}

// ---------------- reductions / norms ----------------
__device__ __forceinline__ float blk_sum(float v, float* sm) {
    __syncthreads();
    int lane = threadIdx.x & 31, w = threadIdx.x >> 5;
#pragma unroll
    for (int o = 16; o; o >>= 1) v += __shfl_down_sync(0xffffffffu, v, o);
    if (lane == 0) sm[w] = v;
    __syncthreads();
    if (w == 0) {
        int nw = (blockDim.x + 31) >> 5;
        float t = (lane < nw) ? sm[lane] : 0.f;
#pragma unroll
        for (int o = 16; o; o >>= 1) t += __shfl_down_sync(0xffffffffu, t, o);
        if (lane == 0) sm[0] = t;
    }
    __syncthreads();
    return sm[0];
}

// fused: zw = U16[src,0:2048] + U16[dst,2048:4096] + bp ; LN ; ReLU -> z2 hi/lo
__global__ void __launch_bounds__(256)
k_pairln_g(const __half* __restrict__ U, const int* __restrict__ ps,
           const int* __restrict__ pd, const float* __restrict__ bp,
           const float* __restrict__ g, const float* __restrict__ b,
           __half* __restrict__ z2h, __half* __restrict__ z2l) {
    __shared__ float sm[32];
    int p = blockIdx.x;
    int t = threadIdx.x;
    const __half* su = U + (long)ps[p] * 4096;
    const __half* du = U + (long)pd[p] * 4096 + 2048;
    const float4* bp4 = (const float4*)bp;
    float4 s0 = h4tof4(*(const uint2*)(su + 4 * t));
    float4 d0 = h4tof4(*(const uint2*)(du + 4 * t));
    float4 s1 = h4tof4(*(const uint2*)(su + 1024 + 4 * t));
    float4 d1 = h4tof4(*(const uint2*)(du + 1024 + 4 * t));
    float4 bb0 = bp4[t], bb1 = bp4[t + 256];
    float4 v0 = make_float4(s0.x + d0.x + bb0.x, s0.y + d0.y + bb0.y,
                            s0.z + d0.z + bb0.z, s0.w + d0.w + bb0.w);
    float4 v1 = make_float4(s1.x + d1.x + bb1.x, s1.y + d1.y + bb1.y,
                            s1.z + d1.z + bb1.z, s1.w + d1.w + bb1.w);
    float s = v0.x + v0.y + v0.z + v0.w + v1.x + v1.y + v1.z + v1.w;
    float mu = blk_sum(s, sm) * (1.0f / DZ);
    float q = (v0.x - mu) * (v0.x - mu) + (v0.y - mu) * (v0.y - mu) +
              (v0.z - mu) * (v0.z - mu) + (v0.w - mu) * (v0.w - mu) +
              (v1.x - mu) * (v1.x - mu) + (v1.y - mu) * (v1.y - mu) +
              (v1.z - mu) * (v1.z - mu) + (v1.w - mu) * (v1.w - mu);
    float var = blk_sum(q, sm) * (1.0f / DZ);
    float rs = rsqrtf(var + EPSV);
    const float4* g4 = (const float4*)g;
    const float4* b4 = (const float4*)b;
    float4 gg = g4[t], bv = b4[t], w;
    w.x = fmaxf((v0.x - mu) * rs * gg.x + bv.x, 0.f);
    w.y = fmaxf((v0.y - mu) * rs * gg.y + bv.y, 0.f);
    w.z = fmaxf((v0.z - mu) * rs * gg.z + bv.z, 0.f);
    w.w = fmaxf((v0.w - mu) * rs * gg.w + bv.w, 0.f);
    uint2 h, l;
    split4h(w, h, l);
    *(uint2*)(z2h + (long)p * DZ + 4 * t) = h;
    *(uint2*)(z2l + (long)p * DZ + 4 * t) = l;
    gg = g4[t + 256]; bv = b4[t + 256];
    w.x = fmaxf((v1.x - mu) * rs * gg.x + bv.x, 0.f);
    w.y = fmaxf((v1.y - mu) * rs * gg.y + bv.y, 0.f);
    w.z = fmaxf((v1.z - mu) * rs * gg.z + bv.z, 0.f);
    w.w = fmaxf((v1.w - mu) * rs * gg.w + bv.w, 0.f);
    split4h(w, h, l);
    *(uint2*)(z2h + (long)p * DZ + 1024 + 4 * t) = h;
    *(uint2*)(z2l + (long)p * DZ + 1024 + 4 * t) = l;
}

__global__ void __launch_bounds__(128)
k_nodeln(const float* __restrict__ T, const float* __restrict__ g,
         const float* __restrict__ b, float* __restrict__ O) {
    __shared__ float sm[32];
    long r = blockIdx.x;
    const float4* row = (const float4*)(T + r * DOUT);
    int t = threadIdx.x;
    float4 v = row[t];
    float s = v.x + v.y + v.z + v.w;
    float mu = blk_sum(s, sm) * (1.0f / DOUT);
    float q = (v.x - mu) * (v.x - mu) + (v.y - mu) * (v.y - mu) +
              (v.z - mu) * (v.z - mu) + (v.w - mu) * (v.w - mu);
    float var = blk_sum(q, sm) * (1.0f / DOUT);
    float rs = rsqrtf(var + EPSV);
    float4 gg = ((const float4*)g)[t], bb = ((const float4*)b)[t], w;
    w.x = fmaxf((v.x - mu) * rs * gg.x + bb.x, 0.f);
    w.y = fmaxf((v.y - mu) * rs * gg.y + bb.y, 0.f);
    w.z = fmaxf((v.z - mu) * rs * gg.z + bb.z, 0.f);
    w.w = fmaxf((v.w - mu) * rs * gg.w + bb.w, 0.f);
    ((float4*)(O + r * DOUT))[t] = w;
}

// ---------------- host ----------------
extern "C" void kernel_launch(void* const* d_in, const int* in_sizes, int n_in,
                              void* d_out, int out_size) {
    const float* x_feat = (const float*)d_in[0];
    const int*   eidx   = (const int*)d_in[1];
    const int*   pidx   = (const int*)d_in[2];
    const float* h1c = (const float*)d_in[3];
    const float* h2c = (const float*)d_in[4];
    const float* W1l = (const float*)d_in[5];
    const float* b1l = (const float*)d_in[6];
    const float* W1r = (const float*)d_in[7];
    const float* bn1g = (const float*)d_in[8];
    const float* bn1b = (const float*)d_in[9];
    const float* W2l = (const float*)d_in[10];
    const float* b2l = (const float*)d_in[11];
    const float* W2r = (const float*)d_in[12];
    const float* bng = (const float*)d_in[13];
    const float* bnb = (const float*)d_in[14];
    const float* Wp  = (const float*)d_in[15];
    const float* bp  = (const float*)d_in[16];
    const float* plng = (const float*)d_in[17];
    const float* plnb = (const float*)d_in[18];
    const float* Wpc = (const float*)d_in[19];
    const float* bpc = (const float*)d_in[20];
    const float* We  = (const float*)d_in[21];
    const float* be  = (const float*)d_in[22];
    const float* Wnm = (const float*)d_in[23];
    const float* bnm = (const float*)d_in[24];
    const float* nlng = (const float*)d_in[25];
    const float* nlnb = (const float*)d_in[26];
    const float* Wnc = (const float*)d_in[27];
    const float* bnc = (const float*)d_in[28];

    float* out = (float*)d_out;
    float* out_node = out;
    float* out_pl   = out + (long)NN * NC;
    float* out_pc   = out_pl + (long)NP * NC;
    float* out_x    = out_pc + (long)NP * 2;
    float* out_gnn  = out_x + (long)NN * DX;

    float* F; int* I; __half* Bb;
    cudaGetSymbolAddress((void**)&F, g_f);
    cudaGetSymbolAddress((void**)&I, g_i);
    cudaGetSymbolAddress((void**)&Bb, g_b);
    float* h    = F + OF_H;
    float* hbn  = F + OF_HBN;
    float* bpe  = F + OF_BPE;
    float* tbuf = F + OF_T;
    float* x1r  = F + OF_X1R;
    float* part = F + OF_PART;
    float* sc1  = F + OF_SC1;
    float* sh1  = F + OF_SH1;
    float* sc2  = F + OF_SC2;
    float* sh2  = F + OF_SH2;
    __half* a1h = Bb + OB_A1H;
    __half* a1l = Bb + OB_A1L;
    __half* a2h = Bb + OB_A2H;
    __half* a2l = Bb + OB_A2L;
    __half* xh  = Bb + OB_XH;
    __half* xl  = Bb + OB_XL;
    __half* w1h = Bb + OB_W1H;
    __half* w2h = Bb + OB_W2H;
    __half* bch = Bb + OB_BCH;
    __half* wnh = Bb + OB_WNH;
    __half* U16 = Bb + OB_U;
    __half* z2h = Bb + OB_Z2H;
    __half* z2l = Bb + OB_Z2L;
    __half* wpeh = Bb + OB_WPEH;
    int* deg = I + OI_DEG;
    int* off = I + OI_OFF;
    int* cur = I + OI_CUR;
    int* csr = I + OI_CSR;
    int* ls  = I + OI_LS;
    int* ld  = I + OI_LD;
    const int* esrc = eidx;
    const int* edst = eidx + NE;
    const int* psrc = pidx;
    const int* pdst = pidx + NP;

    // CSR build + scatter-last-index
    k_init<<<(NN + 255) / 256, 256>>>(deg, ls, ld);
    k_deg<<<(NE + 255) / 256, 256>>>(edst, deg);
    k_scan<<<1, 1024>>>(deg, off, cur);
    k_fill<<<(NE + 255) / 256, 256>>>(esrc, edst, cur, csr);
    k_lastidx<<<(NP + 255) / 256, 256>>>(psrc, pdst, ls, ld);

    // weight preprocessing (fp16 hi planes only)
    k_cat_h2<<<256, 256>>>(W1l, W1r, w1h, DH, DIN, DIN);
    k_cat_h2<<<512, 256>>>(W2l, W2r, w2h, DOUT, DH, DH);
    k_wpe<<<336, 256>>>(Wpc, bpc, We, be, wpeh, bpe);
    k_bcat_h<<<1024, 256>>>(Wp, bch);
    k_cvt_h<<<256, 256>>>(Wnm, wnh, DOUT * DX / 4);

    // layer 1 (2-term: exact activations x fp16 weights)
    k_agg_b<<<NN, 64>>>(x_feat, DIN, off, csr, a1h, a1l, DH, 1);
    {
        dim3 g(DH / 128, (NN + 127) / 128);
        k_gemm_bb<2, 0><<<g, 256>>>(a1h, a1l, w1h, nullptr, b1l, h, NN, DH, DH, DH);
    }
    k_bnsum<<<dim3(DH / 256, NCHUNK), 256>>>(h, NN, DH, part);
    k_bnfin<<<2, 256>>>(part, bn1g, bn1b, sc1, sh1, NN, DH);
    k_bnapply_b<<<2048, 256>>>(h, sc1, sh1, hbn, a2h, a2l, NN, DH, DX, DH);

    // layer 2 (2-term)
    k_agg_b<<<NN, 128>>>(hbn, DH, off, csr, a2h, a2l, DX, 0);
    {
        dim3 g(DOUT / 128, (NN + 127) / 128);
        k_gemm_bb<2, 0><<<g, 256>>>(a2h, a2l, w2h, nullptr, b2l, out_gnn, NN, DOUT, DX, DOUT);
    }
    k_bnsum<<<dim3(DOUT / 256, NCHUNK), 256>>>(out_gnn, NN, DOUT, part);
    k_bnfin<<<2, 256>>>(part, bng, bnb, sc2, sh2, NN, DOUT);

    // fused BN apply + build x
    k_bnbuildx<<<2048, 256>>>(out_gnn, sc2, sh2, h1c, h2c, ls, ld, out_x, xh, xl);

    // pair branch: U16 = x @ bcat^T (2-term, fp16 output)
    {
        dim3 g(4096 / 128, (NN + 127) / 128);
        k_gemm_bb<2, 1><<<g, 256>>>(xh, xl, bch, nullptr, nullptr, U16, NN, 4096, DX, 4096);
    }
    k_pairln_g<<<NP, 256>>>(U16, psrc, pdst, bp, plng, plnb, z2h, z2l);
    // heads: fp16 MMA, split-write to out_pl/out_pc
    {
        dim3 g(1, (NP + 127) / 128);
        k_gemm_h64<<<g, 256>>>(z2h, z2l, wpeh, bpe, out_pl, out_pc, NP, 42, DZ);
    }

    // node branch (2-term)
    {
        dim3 g(DOUT / 128, (NN + 127) / 128);
        k_gemm_bb<2, 0><<<g, 256>>>(xh, xl, wnh, nullptr, bnm, tbuf, NN, DOUT, DX, DOUT);
    }
    k_nodeln<<<NN, 128>>>(tbuf, nlng, nlnb, x1r);
    {
        dim3 g(1, (NN + 127) / 128);
        k_gemm_sk<<<g, 256>>>(x1r, Wnc, bnc, out_node, NN, NC, DOUT, NC);
    }
}

// round 8
// speedup vs baseline: 5.9420x; 1.2426x over previous
#include <cuda_runtime.h>
#include <cuda_fp16.h>
#include <cstdint>

#define NN 10000
#define NE 160000
#define NP 20000
#define DIN 256
#define DH  512
#define DOUT 512
#define DX  1024
#define DZ  2048
#define NC  40
#define EPSV 1e-5f
#define NCHUNK 40
#define CHROWS 250

// ---------------- static scratch (fp32) ----------------
#define OF_H    0L
#define OF_HBN  (OF_H   + (long)NN*DH)
#define OF_BPE  (OF_HBN + (long)NN*DH)
#define OF_T    (OF_BPE + 64L)
#define OF_X1R  (OF_T   + (long)NN*DOUT)
#define OF_PART (OF_X1R + (long)NN*DOUT)
#define OF_SC1  (OF_PART + 41984L)
#define OF_SH1  (OF_SC1 + 512L)
#define OF_SC2  (OF_SH1 + 512L)
#define OF_SH2  (OF_SC2 + 512L)
#define F_TOTAL (OF_SH2 + 512L)

__device__ __align__(256) float g_f[F_TOTAL];

// ---------------- static scratch (fp16) ----------------
#define OB_A1H  0L
#define OB_A1L  (OB_A1H + (long)NN*DH)
#define OB_A2H  (OB_A1L + (long)NN*DH)
#define OB_A2L  (OB_A2H + (long)NN*DX)
#define OB_XH   (OB_A2L + (long)NN*DX)
#define OB_XL   (OB_XH  + (long)NN*DX)
#define OB_W1H  (OB_XL  + (long)NN*DX)
#define OB_W2H  (OB_W1H + (long)DH*DH)
#define OB_BCH  (OB_W2H + (long)DOUT*DX)
#define OB_WNH  (OB_BCH + 4096L*DX)
#define OB_U    (OB_WNH + (long)DOUT*DX)
#define OB_Z2H  (OB_U   + (long)NN*4096)
#define OB_Z2L  (OB_Z2H + (long)NP*DZ)
#define OB_WPEH (OB_Z2L + (long)NP*DZ)
#define B_TOTAL (OB_WPEH + 48L*DZ)

__device__ __align__(256) __half g_b[B_TOTAL];

#define OI_DEG 0
#define OI_OFF 10016
#define OI_CUR 20032
#define OI_CSR 30048
#define OI_LS  190048
#define OI_LD  200048
#define I_TOTAL 210064
__device__ __align__(256) int g_i[I_TOTAL];

// ---------------- fp16 helpers ----------------
__device__ __forceinline__ void split4h(float4 v, uint2& h, uint2& l) {
    __half2 h0 = __floats2half2_rn(v.x, v.y);
    __half2 h1 = __floats2half2_rn(v.z, v.w);
    float2 f0 = __half22float2(h0);
    float2 f1 = __half22float2(h1);
    __half2 l0 = __floats2half2_rn(v.x - f0.x, v.y - f0.y);
    __half2 l1 = __floats2half2_rn(v.z - f1.x, v.w - f1.y);
    h = make_uint2(*(uint32_t*)&h0, *(uint32_t*)&h1);
    l = make_uint2(*(uint32_t*)&l0, *(uint32_t*)&l1);
}

__device__ __forceinline__ uint2 cvt4h(float4 v) {
    __half2 h0 = __floats2half2_rn(v.x, v.y);
    __half2 h1 = __floats2half2_rn(v.z, v.w);
    return make_uint2(*(uint32_t*)&h0, *(uint32_t*)&h1);
}

__device__ __forceinline__ float4 h4tof4(uint2 u) {
    float2 f0 = __half22float2(*(__half2*)&u.x);
    float2 f1 = __half22float2(*(__half2*)&u.y);
    return make_float4(f0.x, f0.y, f1.x, f1.y);
}

// ---------------- small utility kernels ----------------
__global__ void k_init(int* deg, int* ls, int* ld) {
    int i = blockIdx.x * blockDim.x + threadIdx.x;
    if (i < NN) { deg[i] = 0; ls[i] = -1; ld[i] = -1; }
}

__global__ void k_deg(const int* __restrict__ dst, int* deg) {
    int e = blockIdx.x * blockDim.x + threadIdx.x;
    if (e < NE) atomicAdd(&deg[dst[e]], 1);
}

__global__ void k_scan(const int* __restrict__ deg, int* off, int* cur) {
    __shared__ int s[1024];
    __shared__ int carry;
    int tid = threadIdx.x;
    if (tid == 0) carry = 0;
    __syncthreads();
    for (int base = 0; base < NN; base += 1024) {
        int i = base + tid;
        int v = (i < NN) ? deg[i] : 0;
        s[tid] = v;
        __syncthreads();
        for (int o = 1; o < 1024; o <<= 1) {
            int t = (tid >= o) ? s[tid - o] : 0;
            __syncthreads();
            s[tid] += t;
            __syncthreads();
        }
        int excl = s[tid] - v;
        int c0 = carry;
        if (i < NN) { off[i] = c0 + excl; cur[i] = c0 + excl; }
        __syncthreads();
        if (tid == 0) carry = c0 + s[1023];
        __syncthreads();
    }
    if (tid == 0) off[NN] = carry;
}

__global__ void k_fill(const int* __restrict__ src, const int* __restrict__ dst,
                       int* cur, int* csr) {
    int e = blockIdx.x * blockDim.x + threadIdx.x;
    if (e < NE) {
        int slot = atomicAdd(&cur[dst[e]], 1);
        csr[slot] = src[e];
    }
}

__global__ void k_lastidx(const int* __restrict__ ps, const int* __restrict__ pd,
                          int* ls, int* ld) {
    int i = blockIdx.x * blockDim.x + threadIdx.x;
    if (i < NP) { atomicMax(&ls[ps[i]], i); atomicMax(&ld[pd[i]], i); }
}

__global__ void k_agg_b(const float* __restrict__ X, int D, const int* __restrict__ off,
                        const int* __restrict__ csr, __half* __restrict__ oh,
                        __half* __restrict__ ol, int ldo, int copyself) {
    int n = blockIdx.x;
    int s = off[n], e = off[n + 1];
    int nv = D >> 2;
    const float4* X4 = (const float4*)X;
    for (int c = threadIdx.x; c < nv; c += blockDim.x) {
        float4 m = make_float4(0.f, 0.f, 0.f, 0.f);
        if (e > s) {
            m = __ldg(&X4[(long)csr[s] * nv + c]);
            for (int i = s + 1; i < e; i++) {
                float4 v = __ldg(&X4[(long)csr[i] * nv + c]);
                m.x = fmaxf(m.x, v.x); m.y = fmaxf(m.y, v.y);
                m.z = fmaxf(m.z, v.z); m.w = fmaxf(m.w, v.w);
            }
        }
        uint2 h, l;
        split4h(m, h, l);
        *(uint2*)(oh + (long)n * ldo + 4 * c) = h;
        *(uint2*)(ol + (long)n * ldo + 4 * c) = l;
        if (copyself) {
            float4 sv = __ldg(&X4[(long)n * nv + c]);
            split4h(sv, h, l);
            *(uint2*)(oh + (long)n * ldo + D + 4 * c) = h;
            *(uint2*)(ol + (long)n * ldo + D + 4 * c) = l;
        }
    }
}

// concat two fp32 weights into single fp16 hi plane
__global__ void k_cat_h2(const float* __restrict__ A, const float* __restrict__ B,
                         __half* __restrict__ dh, int rows, int ka, int kb) {
    int kc = ka + kb;
    int cq = kc >> 2;
    int total = rows * cq;
    for (int idx = blockIdx.x * blockDim.x + threadIdx.x; idx < total;
         idx += gridDim.x * blockDim.x) {
        int r = idx / cq, c = (idx % cq) * 4;
        float4 v = (c < ka) ? *(const float4*)(A + (long)r * ka + c)
                            : *(const float4*)(B + (long)r * kb + (c - ka));
        *(uint2*)(dh + (long)r * kc + c) = cvt4h(v);
    }
}

__global__ void k_cvt_h(const float* __restrict__ W, __half* __restrict__ dh,
                        int total4) {
    for (int idx = blockIdx.x * blockDim.x + threadIdx.x; idx < total4;
         idx += gridDim.x * blockDim.x) {
        ((uint2*)dh)[idx] = cvt4h(((const float4*)W)[idx]);
    }
}

__global__ void k_bcat_h(const float* __restrict__ Wp, __half* __restrict__ dh) {
    int total = 4096 * (DX >> 2);
    for (int idx = blockIdx.x * blockDim.x + threadIdx.x; idx < total;
         idx += gridDim.x * blockDim.x) {
        int n = idx >> 8, k = (idx & 255) * 4;
        const float* src = (n < 2048) ? Wp + (long)n * DZ + k
                                      : Wp + (long)(n - 2048) * DZ + 1024 + k;
        *(uint2*)(dh + (long)n * DX + k) = cvt4h(*(const float4*)src);
    }
}

__global__ void k_wpe(const float* __restrict__ Wpc, const float* __restrict__ bpc,
                      const float* __restrict__ We, const float* __restrict__ be,
                      __half* wpeh, float* bpe) {
    for (int idx = blockIdx.x * blockDim.x + threadIdx.x; idx < 42 * DZ;
         idx += gridDim.x * blockDim.x) {
        int r = idx / DZ, k = idx % DZ;
        float v = (r < 40) ? Wpc[(long)r * DZ + k] : We[(long)(r - 40) * DZ + k];
        wpeh[idx] = __float2half_rn(v);
        if (idx < 42) bpe[idx] = (idx < 40) ? bpc[idx] : be[idx - 40];
    }
}

// ---------------- BN ----------------
__global__ void k_bnsum(const float* __restrict__ H, int M, int C,
                        float* __restrict__ part) {
    int c = blockIdx.x * blockDim.x + threadIdx.x;
    int r0 = blockIdx.y * CHROWS;
    int r1 = min(r0 + CHROWS, M);
    float s = 0.f, q = 0.f;
    for (int r = r0; r < r1; r++) {
        float v = H[(long)r * C + c];
        s += v; q += v * v;
    }
    part[((long)blockIdx.y * C + c) * 2 + 0] = s;
    part[((long)blockIdx.y * C + c) * 2 + 1] = q;
}

__global__ void k_bnfin(const float* __restrict__ part, const float* __restrict__ g,
                        const float* __restrict__ b, float* scale, float* shift,
                        int M, int C) {
    int c = blockIdx.x * blockDim.x + threadIdx.x;
    if (c >= C) return;
    float s = 0.f, q = 0.f;
    for (int ch = 0; ch < NCHUNK; ch++) {
        s += part[((long)ch * C + c) * 2 + 0];
        q += part[((long)ch * C + c) * 2 + 1];
    }
    float mu = s / (float)M;
    float var = q / (float)M - mu * mu;
    float sc = g[c] * rsqrtf(var + EPSV);
    scale[c] = sc;
    shift[c] = b[c] - mu * sc;
}

__global__ void k_bnapply_b(const float* __restrict__ H, const float* __restrict__ scale,
                            const float* __restrict__ shift, float* __restrict__ out,
                            __half* __restrict__ o2h, __half* __restrict__ o2l,
                            int M, int C, int ldo2, int coff) {
    int cq = C >> 2;
    int total = M * cq;
    for (int idx = blockIdx.x * blockDim.x + threadIdx.x; idx < total;
         idx += gridDim.x * blockDim.x) {
        int r = idx / cq, c4 = idx % cq;
        float4 v = ((const float4*)H)[idx];
        float4 sc = ((const float4*)scale)[c4];
        float4 sh = ((const float4*)shift)[c4];
        v.x = v.x * sc.x + sh.x;
        v.y = v.y * sc.y + sh.y;
        v.z = v.z * sc.z + sh.z;
        v.w = v.w * sc.w + sh.w;
        ((float4*)out)[idx] = v;
        uint2 h, l;
        split4h(v, h, l);
        *(uint2*)(o2h + (long)r * ldo2 + coff + 4 * c4) = h;
        *(uint2*)(o2l + (long)r * ldo2 + coff + 4 * c4) = l;
    }
}

// fused: BN apply (layer2) + build x (fp32 output + fp16 planes)
__global__ void k_bnbuildx(const float* __restrict__ gnn, const float* __restrict__ scale,
                           const float* __restrict__ shift,
                           const float* __restrict__ h1c, const float* __restrict__ h2c,
                           const int* __restrict__ ls, const int* __restrict__ ld,
                           float* __restrict__ xout,
                           __half* __restrict__ xh, __half* __restrict__ xl) {
    int total = NN * (DOUT / 4);
    for (int idx = blockIdx.x * blockDim.x + threadIdx.x; idx < total;
         idx += gridDim.x * blockDim.x) {
        int n = idx >> 7;
        int c4 = idx & 127;
        float4 sec = ((const float4*)(gnn + (long)n * DOUT))[c4];
        float4 sc = ((const float4*)scale)[c4];
        float4 sh = ((const float4*)shift)[c4];
        sec.x = sec.x * sc.x + sh.x;
        sec.y = sec.y * sc.y + sh.y;
        sec.z = sec.z * sc.z + sh.z;
        sec.w = sec.w * sc.w + sh.w;
        float4 fir;
        int li = ld[n];
        if (li >= 0) fir = ((const float4*)(h2c + (long)li * DOUT))[c4];
        else {
            int si = ls[n];
            fir = (si >= 0) ? ((const float4*)(h1c + (long)si * DOUT))[c4] : sec;
        }
        ((float4*)(xout + (long)n * DX))[c4] = fir;
        ((float4*)(xout + (long)n * DX + DOUT))[c4] = sec;
        uint2 h, l;
        split4h(fir, h, l);
        *(uint2*)(xh + (long)n * DX + 4 * c4) = h;
        *(uint2*)(xl + (long)n * DX + 4 * c4) = l;
        split4h(sec, h, l);
        *(uint2*)(xh + (long)n * DX + DOUT + 4 * c4) = h;
        *(uint2*)(xl + (long)n * DX + DOUT + 4 * c4) = l;
    }
}

// ================= fp16 split tensor-core GEMM =================
// TERMS=3: Ah*Bh + Ah*Bl + Al*Bh.  TERMS=2: Ah*Bh + Al*Bh.  TERMS=1: Ah*Bh.
// HOUT=1: write fp16 (no bias).  HOUT=0: fp32 + bias.
#define SPAD2 24

#define MMA_F16(d, a, b)                                                       \
    asm volatile(                                                              \
        "mma.sync.aligned.m16n8k16.row.col.f32.f16.f16.f32 "                   \
        "{%0,%1,%2,%3}, {%4,%5,%6,%7}, {%8,%9}, {%0,%1,%2,%3};"                \
        : "+f"(d[0]), "+f"(d[1]), "+f"(d[2]), "+f"(d[3])                       \
        : "r"(a[0]), "r"(a[1]), "r"(a[2]), "r"(a[3]), "r"(b[0]), "r"(b[1]))

template <int TERMS, int HOUT>
__global__ void __launch_bounds__(256)
k_gemm_bb(const __half* __restrict__ Ah, const __half* __restrict__ Al,
          const __half* __restrict__ Bh, const __half* __restrict__ Bl,
          const float* __restrict__ bias, void* __restrict__ Cv,
          int M, int N, int K, int ldc) {
    __shared__ __align__(16) __half sA[2][2][128][SPAD2];
    __shared__ __align__(16) __half sB[2][2][128][SPAD2];

    int tid = threadIdx.x;
    int wid = tid >> 5, lane = tid & 31;
    int wm = wid >> 2, wn = wid & 3;
    int lrow = lane >> 2, lcol = (lane & 3) << 1;

    int arow = tid >> 1;
    int ahalf = (tid & 1) << 3;
    long gm = (long)blockIdx.y * 128 + arow;
    long gn = (long)blockIdx.x * 128 + arow;
    bool okm = gm < M;
    bool okn = gn < N;
    const __half* Aph = Ah + gm * K + ahalf;
    const __half* Apl = (TERMS >= 2) ? (Al + gm * K + ahalf) : nullptr;
    const __half* Bph = Bh + gn * K + ahalf;
    const __half* Bpl = (TERMS == 3) ? (Bl + gn * K + ahalf) : nullptr;
    uint4 zu = make_uint4(0, 0, 0, 0);

    float acc[4][4][4];
#pragma unroll
    for (int mi = 0; mi < 4; mi++)
#pragma unroll
        for (int ni = 0; ni < 4; ni++)
#pragma unroll
            for (int r = 0; r < 4; r++) acc[mi][ni][r] = 0.f;

    {
        uint4 vah = okm ? *(const uint4*)Aph : zu;
        uint4 vbh = okn ? *(const uint4*)Bph : zu;
        *(uint4*)&sA[0][0][arow][ahalf] = vah;
        *(uint4*)&sB[0][0][arow][ahalf] = vbh;
        if (TERMS >= 2) {
            uint4 val = okm ? *(const uint4*)Apl : zu;
            *(uint4*)&sA[0][1][arow][ahalf] = val;
        }
        if (TERMS == 3) {
            uint4 vbl = okn ? *(const uint4*)Bpl : zu;
            *(uint4*)&sB[0][1][arow][ahalf] = vbl;
        }
    }
    __syncthreads();

    int nk = K >> 4;
    for (int kt = 0; kt < nk; kt++) {
        int buf = kt & 1;
        uint4 vah, val, vbh, vbl;
        bool more = (kt + 1) < nk;
        if (more) {
            int k0 = (kt + 1) << 4;
            vah = okm ? *(const uint4*)(Aph + k0) : zu;
            vbh = okn ? *(const uint4*)(Bph + k0) : zu;
            if (TERMS >= 2) val = okm ? *(const uint4*)(Apl + k0) : zu;
            if (TERMS == 3) vbl = okn ? *(const uint4*)(Bpl + k0) : zu;
        }

        uint32_t ah[4][4], al[4][4], bh[4][2], bl[4][2];
#pragma unroll
        for (int mi = 0; mi < 4; mi++) {
            int r0 = wm * 64 + mi * 16 + lrow;
            ah[mi][0] = *(const uint32_t*)&sA[buf][0][r0][lcol];
            ah[mi][1] = *(const uint32_t*)&sA[buf][0][r0 + 8][lcol];
            ah[mi][2] = *(const uint32_t*)&sA[buf][0][r0][lcol + 8];
            ah[mi][3] = *(const uint32_t*)&sA[buf][0][r0 + 8][lcol + 8];
            if (TERMS >= 2) {
                al[mi][0] = *(const uint32_t*)&sA[buf][1][r0][lcol];
                al[mi][1] = *(const uint32_t*)&sA[buf][1][r0 + 8][lcol];
                al[mi][2] = *(const uint32_t*)&sA[buf][1][r0][lcol + 8];
                al[mi][3] = *(const uint32_t*)&sA[buf][1][r0 + 8][lcol + 8];
            }
        }
#pragma unroll
        for (int ni = 0; ni < 4; ni++) {
            int r0 = wn * 32 + ni * 8 + lrow;
            bh[ni][0] = *(const uint32_t*)&sB[buf][0][r0][lcol];
            bh[ni][1] = *(const uint32_t*)&sB[buf][0][r0][lcol + 8];
            if (TERMS == 3) {
                bl[ni][0] = *(const uint32_t*)&sB[buf][1][r0][lcol];
                bl[ni][1] = *(const uint32_t*)&sB[buf][1][r0][lcol + 8];
            }
        }
#pragma unroll
        for (int mi = 0; mi < 4; mi++)
#pragma unroll
            for (int ni = 0; ni < 4; ni++) {
                MMA_F16(acc[mi][ni], ah[mi], bh[ni]);
                if (TERMS == 3) MMA_F16(acc[mi][ni], ah[mi], bl[ni]);
                if (TERMS >= 2) MMA_F16(acc[mi][ni], al[mi], bh[ni]);
            }

        if (more) {
            int nb = buf ^ 1;
            *(uint4*)&sA[nb][0][arow][ahalf] = vah;
            *(uint4*)&sB[nb][0][arow][ahalf] = vbh;
            if (TERMS >= 2) *(uint4*)&sA[nb][1][arow][ahalf] = val;
            if (TERMS == 3) *(uint4*)&sB[nb][1][arow][ahalf] = vbl;
        }
        __syncthreads();
    }

    int mbase = blockIdx.y * 128 + wm * 64 + lrow;
    int nbase = blockIdx.x * 128 + wn * 32 + lcol;
#pragma unroll
    for (int mi = 0; mi < 4; mi++) {
        int m0 = mbase + mi * 16;
#pragma unroll
        for (int ni = 0; ni < 4; ni++) {
            int n0 = nbase + ni * 8;
            if (HOUT) {
                __half* Ch = (__half*)Cv;
                if (m0 < M) {
                    __half2 p = __floats2half2_rn(acc[mi][ni][0], acc[mi][ni][1]);
                    *(__half2*)(Ch + (long)m0 * ldc + n0) = p;
                }
                if (m0 + 8 < M) {
                    __half2 p = __floats2half2_rn(acc[mi][ni][2], acc[mi][ni][3]);
                    *(__half2*)(Ch + (long)(m0 + 8) * ldc + n0) = p;
                }
            } else {
                float* Cf = (float*)Cv;
                float b0v = bias ? bias[n0] : 0.f;
                float b1v = bias ? bias[n0 + 1] : 0.f;
                if (m0 < M) {
                    Cf[(long)m0 * ldc + n0] = acc[mi][ni][0] + b0v;
                    Cf[(long)m0 * ldc + n0 + 1] = acc[mi][ni][1] + b1v;
                }
                if (m0 + 8 < M) {
                    Cf[(long)(m0 + 8) * ldc + n0] = acc[mi][ni][2] + b0v;
                    Cf[(long)(m0 + 8) * ldc + n0 + 1] = acc[mi][ni][3] + b1v;
                }
            }
        }
    }
}

// ============ heads GEMM: 128x64 tile, N<=64, 2-term, split-write ============
__global__ void __launch_bounds__(256)
k_gemm_h64(const __half* __restrict__ Ah, const __half* __restrict__ Al,
           const __half* __restrict__ Bh, const float* __restrict__ bias,
           float* __restrict__ pl, float* __restrict__ pc, int M, int N, int K) {
    __shared__ __align__(16) __half sA[2][2][128][SPAD2];
    __shared__ __align__(16) __half sB[2][64][SPAD2];

    int tid = threadIdx.x;
    int wid = tid >> 5, lane = tid & 31;
    int wm = wid >> 1, wn = wid & 1;
    int lrow = lane >> 2, lcol = (lane & 3) << 1;

    int arow = tid >> 1;
    int ahalf = (tid & 1) << 3;
    long gm = (long)blockIdx.y * 128 + arow;
    bool okm = gm < M;
    const __half* Aph = Ah + gm * K + ahalf;
    const __half* Apl = Al + gm * K + ahalf;
    int brow = (tid & 127) >> 1;
    int bhalf2 = (tid & 1) << 3;
    bool bload = tid < 128;
    bool okb = bload && (brow < N);
    const __half* Bph = Bh + (long)brow * K + bhalf2;
    uint4 zu = make_uint4(0, 0, 0, 0);

    float acc[2][4][4];
#pragma unroll
    for (int mi = 0; mi < 2; mi++)
#pragma unroll
        for (int ni = 0; ni < 4; ni++)
#pragma unroll
            for (int r = 0; r < 4; r++) acc[mi][ni][r] = 0.f;

    {
        uint4 vah = okm ? *(const uint4*)Aph : zu;
        uint4 val = okm ? *(const uint4*)Apl : zu;
        *(uint4*)&sA[0][0][arow][ahalf] = vah;
        *(uint4*)&sA[0][1][arow][ahalf] = val;
        if (bload) {
            uint4 vbh = okb ? *(const uint4*)Bph : zu;
            *(uint4*)&sB[0][brow][bhalf2] = vbh;
        }
    }
    __syncthreads();

    int nk = K >> 4;
    for (int kt = 0; kt < nk; kt++) {
        int buf = kt & 1;
        uint4 vah, val, vbh;
        bool more = (kt + 1) < nk;
        if (more) {
            int k0 = (kt + 1) << 4;
            vah = okm ? *(const uint4*)(Aph + k0) : zu;
            val = okm ? *(const uint4*)(Apl + k0) : zu;
            if (bload) vbh = okb ? *(const uint4*)(Bph + k0) : zu;
        }

        uint32_t ah[2][4], al[2][4], bh[4][2];
#pragma unroll
        for (int mi = 0; mi < 2; mi++) {
            int r0 = wm * 32 + mi * 16 + lrow;
            ah[mi][0] = *(const uint32_t*)&sA[buf][0][r0][lcol];
            ah[mi][1] = *(const uint32_t*)&sA[buf][0][r0 + 8][lcol];
            ah[mi][2] = *(const uint32_t*)&sA[buf][0][r0][lcol + 8];
            ah[mi][3] = *(const uint32_t*)&sA[buf][0][r0 + 8][lcol + 8];
            al[mi][0] = *(const uint32_t*)&sA[buf][1][r0][lcol];
            al[mi][1] = *(const uint32_t*)&sA[buf][1][r0 + 8][lcol];
            al[mi][2] = *(const uint32_t*)&sA[buf][1][r0][lcol + 8];
            al[mi][3] = *(const uint32_t*)&sA[buf][1][r0 + 8][lcol + 8];
        }
#pragma unroll
        for (int ni = 0; ni < 4; ni++) {
            int r0 = wn * 32 + ni * 8 + lrow;
            bh[ni][0] = *(const uint32_t*)&sB[buf][r0][lcol];
            bh[ni][1] = *(const uint32_t*)&sB[buf][r0][lcol + 8];
        }
#pragma unroll
        for (int mi = 0; mi < 2; mi++)
#pragma unroll
            for (int ni = 0; ni < 4; ni++) {
                MMA_F16(acc[mi][ni], ah[mi], bh[ni]);
                MMA_F16(acc[mi][ni], al[mi], bh[ni]);
            }

        if (more) {
            int nb = buf ^ 1;
            *(uint4*)&sA[nb][0][arow][ahalf] = vah;
            *(uint4*)&sA[nb][1][arow][ahalf] = val;
            if (bload) *(uint4*)&sB[nb][brow][bhalf2] = vbh;
        }
        __syncthreads();
    }

    int mbase = blockIdx.y * 128 + wm * 32 + lrow;
    int nbase = wn * 32 + lcol;
#pragma unroll
    for (int mi = 0; mi < 2; mi++) {
        int m0 = mbase + mi * 16;
#pragma unroll
        for (int ni = 0; ni < 4; ni++) {
            int n0 = nbase + ni * 8;
#pragma unroll
            for (int r = 0; r < 4; r++) {
                int m = m0 + (r >> 1) * 8;
                int n = n0 + (r & 1);
                if (m < M && n < N) {
                    float v = acc[mi][ni][r] + bias[n];
                    if (n < 40) pl[(long)m * 40 + n] = v;
                    else pc[(long)m * 2 + (n - 40)] = v;
                }
            }
        }
    }
}

// ---------------- skinny-N SIMT GEMM (node head) ----------------
__global__ void __launch_bounds__(256)
k_gemm_sk(const float* __restrict__ A, const float* __restrict__ B,
          const float* __restrict__ bias, float* __restrict__ C,
          int M, int N, int K, int ldc) {
    __shared__ float As[16][128];
    __shared__ float Bs[16][48];
    int tid = threadIdx.x;
    int tr = tid >> 4;
    int tc = tid & 15;
    int arow = tid >> 1;
    int acol = (tid & 1) << 3;
    long gm = (long)blockIdx.y * 128 + arow;
    bool okm = gm < M;
    const float* Ap = A + gm * K + acol;
    int bn = tid >> 2;
    int bk = (tid & 3) << 2;
    bool okb = (tid < 192) && (bn < N);
    const float* Bp = B + (long)bn * K + bk;
    float4 z4 = make_float4(0.f, 0.f, 0.f, 0.f);

    float acc[8][3];
#pragma unroll
    for (int i = 0; i < 8; i++)
#pragma unroll
        for (int j = 0; j < 3; j++) acc[i][j] = 0.f;

    for (int k0 = 0; k0 < K; k0 += 16) {
        float4 a0 = okm ? *(const float4*)(Ap + k0) : z4;
        float4 a1 = okm ? *(const float4*)(Ap + k0 + 4) : z4;
        float4 bvv = okb ? *(const float4*)(Bp + k0) : z4;
        __syncthreads();
        As[acol + 0][arow] = a0.x; As[acol + 1][arow] = a0.y;
        As[acol + 2][arow] = a0.z; As[acol + 3][arow] = a0.w;
        As[acol + 4][arow] = a1.x; As[acol + 5][arow] = a1.y;
        As[acol + 6][arow] = a1.z; As[acol + 7][arow] = a1.w;
        if (tid < 192) {
            Bs[bk + 0][bn] = bvv.x; Bs[bk + 1][bn] = bvv.y;
            Bs[bk + 2][bn] = bvv.z; Bs[bk + 3][bn] = bvv.w;
        }
        __syncthreads();
#pragma unroll
        for (int k = 0; k < 16; k++) {
            float4 r0 = *(const float4*)&As[k][tr * 8];
            float4 r1 = *(const float4*)&As[k][tr * 8 + 4];
            float ra[8] = {r0.x, r0.y, r0.z, r0.w, r1.x, r1.y, r1.z, r1.w};
            float b0 = Bs[k][tc * 3 + 0];
            float b1 = Bs[k][tc * 3 + 1];
            float b2 = Bs[k][tc * 3 + 2];
#pragma unroll
            for (int i = 0; i < 8; i++) {
                acc[i][0] += ra[i] * b0;
                acc[i][1] += ra[i] * b1;
                acc[i][2] += ra[i] * b2;
            }
        }
    }
    int mb = blockIdx.y * 128 + tr * 8;
    int nb = tc * 3;
#pragma unroll
    for (int i = 0; i < 8; i++) {
        int m = mb + i;
        if (m < M) {
#pragma unroll
            for (int j = 0; j < 3; j++) {
                int n = nb + j;
                if (n < N) C[(long)m * ldc + n] = acc[i][j] + bias[n];
            }
        }
    }
}

// ---------------- reductions / norms ----------------
__device__ __forceinline__ float blk_sum(float v, float* sm) {
    __syncthreads();
    int lane = threadIdx.x & 31, w = threadIdx.x >> 5;
#pragma unroll
    for (int o = 16; o; o >>= 1) v += __shfl_down_sync(0xffffffffu, v, o);
    if (lane == 0) sm[w] = v;
    __syncthreads();
    if (w == 0) {
        int nw = (blockDim.x + 31) >> 5;
        float t = (lane < nw) ? sm[lane] : 0.f;
#pragma unroll
        for (int o = 16; o; o >>= 1) t += __shfl_down_sync(0xffffffffu, t, o);
        if (lane == 0) sm[0] = t;
    }
    __syncthreads();
    return sm[0];
}

// fused: zw = U16[src,0:2048] + U16[dst,2048:4096] + bp ; LN ; ReLU -> z2 hi/lo
__global__ void __launch_bounds__(256)
k_pairln_g(const __half* __restrict__ U, const int* __restrict__ ps,
           const int* __restrict__ pd, const float* __restrict__ bp,
           const float* __restrict__ g, const float* __restrict__ b,
           __half* __restrict__ z2h, __half* __restrict__ z2l) {
    __shared__ float sm[32];
    int p = blockIdx.x;
    int t = threadIdx.x;
    const __half* su = U + (long)ps[p] * 4096;
    const __half* du = U + (long)pd[p] * 4096 + 2048;
    const float4* bp4 = (const float4*)bp;
    float4 s0 = h4tof4(*(const uint2*)(su + 4 * t));
    float4 d0 = h4tof4(*(const uint2*)(du + 4 * t));
    float4 s1 = h4tof4(*(const uint2*)(su + 1024 + 4 * t));
    float4 d1 = h4tof4(*(const uint2*)(du + 1024 + 4 * t));
    float4 bb0 = bp4[t], bb1 = bp4[t + 256];
    float4 v0 = make_float4(s0.x + d0.x + bb0.x, s0.y + d0.y + bb0.y,
                            s0.z + d0.z + bb0.z, s0.w + d0.w + bb0.w);
    float4 v1 = make_float4(s1.x + d1.x + bb1.x, s1.y + d1.y + bb1.y,
                            s1.z + d1.z + bb1.z, s1.w + d1.w + bb1.w);
    float s = v0.x + v0.y + v0.z + v0.w + v1.x + v1.y + v1.z + v1.w;
    float mu = blk_sum(s, sm) * (1.0f / DZ);
    float q = (v0.x - mu) * (v0.x - mu) + (v0.y - mu) * (v0.y - mu) +
              (v0.z - mu) * (v0.z - mu) + (v0.w - mu) * (v0.w - mu) +
              (v1.x - mu) * (v1.x - mu) + (v1.y - mu) * (v1.y - mu) +
              (v1.z - mu) * (v1.z - mu) + (v1.w - mu) * (v1.w - mu);
    float var = blk_sum(q, sm) * (1.0f / DZ);
    float rs = rsqrtf(var + EPSV);
    const float4* g4 = (const float4*)g;
    const float4* b4 = (const float4*)b;
    float4 gg = g4[t], bv = b4[t], w;
    w.x = fmaxf((v0.x - mu) * rs * gg.x + bv.x, 0.f);
    w.y = fmaxf((v0.y - mu) * rs * gg.y + bv.y, 0.f);
    w.z = fmaxf((v0.z - mu) * rs * gg.z + bv.z, 0.f);
    w.w = fmaxf((v0.w - mu) * rs * gg.w + bv.w, 0.f);
    uint2 h, l;
    split4h(w, h, l);
    *(uint2*)(z2h + (long)p * DZ + 4 * t) = h;
    *(uint2*)(z2l + (long)p * DZ + 4 * t) = l;
    gg = g4[t + 256]; bv = b4[t + 256];
    w.x = fmaxf((v1.x - mu) * rs * gg.x + bv.x, 0.f);
    w.y = fmaxf((v1.y - mu) * rs * gg.y + bv.y, 0.f);
    w.z = fmaxf((v1.z - mu) * rs * gg.z + bv.z, 0.f);
    w.w = fmaxf((v1.w - mu) * rs * gg.w + bv.w, 0.f);
    split4h(w, h, l);
    *(uint2*)(z2h + (long)p * DZ + 1024 + 4 * t) = h;
    *(uint2*)(z2l + (long)p * DZ + 1024 + 4 * t) = l;
}

__global__ void __launch_bounds__(128)
k_nodeln(const float* __restrict__ T, const float* __restrict__ g,
         const float* __restrict__ b, float* __restrict__ O) {
    __shared__ float sm[32];
    long r = blockIdx.x;
    const float4* row = (const float4*)(T + r * DOUT);
    int t = threadIdx.x;
    float4 v = row[t];
    float s = v.x + v.y + v.z + v.w;
    float mu = blk_sum(s, sm) * (1.0f / DOUT);
    float q = (v.x - mu) * (v.x - mu) + (v.y - mu) * (v.y - mu) +
              (v.z - mu) * (v.z - mu) + (v.w - mu) * (v.w - mu);
    float var = blk_sum(q, sm) * (1.0f / DOUT);
    float rs = rsqrtf(var + EPSV);
    float4 gg = ((const float4*)g)[t], bb = ((const float4*)b)[t], w;
    w.x = fmaxf((v.x - mu) * rs * gg.x + bb.x, 0.f);
    w.y = fmaxf((v.y - mu) * rs * gg.y + bb.y, 0.f);
    w.z = fmaxf((v.z - mu) * rs * gg.z + bb.z, 0.f);
    w.w = fmaxf((v.w - mu) * rs * gg.w + bb.w, 0.f);
    ((float4*)(O + r * DOUT))[t] = w;
}

// ---------------- host ----------------
extern "C" void kernel_launch(void* const* d_in, const int* in_sizes, int n_in,
                              void* d_out, int out_size) {
    const float* x_feat = (const float*)d_in[0];
    const int*   eidx   = (const int*)d_in[1];
    const int*   pidx   = (const int*)d_in[2];
    const float* h1c = (const float*)d_in[3];
    const float* h2c = (const float*)d_in[4];
    const float* W1l = (const float*)d_in[5];
    const float* b1l = (const float*)d_in[6];
    const float* W1r = (const float*)d_in[7];
    const float* bn1g = (const float*)d_in[8];
    const float* bn1b = (const float*)d_in[9];
    const float* W2l = (const float*)d_in[10];
    const float* b2l = (const float*)d_in[11];
    const float* W2r = (const float*)d_in[12];
    const float* bng = (const float*)d_in[13];
    const float* bnb = (const float*)d_in[14];
    const float* Wp  = (const float*)d_in[15];
    const float* bp  = (const float*)d_in[16];
    const float* plng = (const float*)d_in[17];
    const float* plnb = (const float*)d_in[18];
    const float* Wpc = (const float*)d_in[19];
    const float* bpc = (const float*)d_in[20];
    const float* We  = (const float*)d_in[21];
    const float* be  = (const float*)d_in[22];
    const float* Wnm = (const float*)d_in[23];
    const float* bnm = (const float*)d_in[24];
    const float* nlng = (const float*)d_in[25];
    const float* nlnb = (const float*)d_in[26];
    const float* Wnc = (const float*)d_in[27];
    const float* bnc = (const float*)d_in[28];

    float* out = (float*)d_out;
    float* out_node = out;
    float* out_pl   = out + (long)NN * NC;
    float* out_pc   = out_pl + (long)NP * NC;
    float* out_x    = out_pc + (long)NP * 2;
    float* out_gnn  = out_x + (long)NN * DX;

    float* F; int* I; __half* Bb;
    cudaGetSymbolAddress((void**)&F, g_f);
    cudaGetSymbolAddress((void**)&I, g_i);
    cudaGetSymbolAddress((void**)&Bb, g_b);
    float* h    = F + OF_H;
    float* hbn  = F + OF_HBN;
    float* bpe  = F + OF_BPE;
    float* tbuf = F + OF_T;
    float* x1r  = F + OF_X1R;
    float* part = F + OF_PART;
    float* sc1  = F + OF_SC1;
    float* sh1  = F + OF_SH1;
    float* sc2  = F + OF_SC2;
    float* sh2  = F + OF_SH2;
    __half* a1h = Bb + OB_A1H;
    __half* a1l = Bb + OB_A1L;
    __half* a2h = Bb + OB_A2H;
    __half* a2l = Bb + OB_A2L;
    __half* xh  = Bb + OB_XH;
    __half* xl  = Bb + OB_XL;
    __half* w1h = Bb + OB_W1H;
    __half* w2h = Bb + OB_W2H;
    __half* bch = Bb + OB_BCH;
    __half* wnh = Bb + OB_WNH;
    __half* U16 = Bb + OB_U;
    __half* z2h = Bb + OB_Z2H;
    __half* z2l = Bb + OB_Z2L;
    __half* wpeh = Bb + OB_WPEH;
    int* deg = I + OI_DEG;
    int* off = I + OI_OFF;
    int* cur = I + OI_CUR;
    int* csr = I + OI_CSR;
    int* ls  = I + OI_LS;
    int* ld  = I + OI_LD;
    const int* esrc = eidx;
    const int* edst = eidx + NE;
    const int* psrc = pidx;
    const int* pdst = pidx + NP;

    // CSR build + scatter-last-index
    k_init<<<(NN + 255) / 256, 256>>>(deg, ls, ld);
    k_deg<<<(NE + 255) / 256, 256>>>(edst, deg);
    k_scan<<<1, 1024>>>(deg, off, cur);
    k_fill<<<(NE + 255) / 256, 256>>>(esrc, edst, cur, csr);
    k_lastidx<<<(NP + 255) / 256, 256>>>(psrc, pdst, ls, ld);

    // weight preprocessing (fp16 hi planes only)
    k_cat_h2<<<256, 256>>>(W1l, W1r, w1h, DH, DIN, DIN);
    k_cat_h2<<<512, 256>>>(W2l, W2r, w2h, DOUT, DH, DH);
    k_wpe<<<336, 256>>>(Wpc, bpc, We, be, wpeh, bpe);
    k_bcat_h<<<1024, 256>>>(Wp, bch);
    k_cvt_h<<<256, 256>>>(Wnm, wnh, DOUT * DX / 4);

    // layer 1 (2-term: exact activations x fp16 weights)
    k_agg_b<<<NN, 64>>>(x_feat, DIN, off, csr, a1h, a1l, DH, 1);
    {
        dim3 g(DH / 128, (NN + 127) / 128);
        k_gemm_bb<2, 0><<<g, 256>>>(a1h, a1l, w1h, nullptr, b1l, h, NN, DH, DH, DH);
    }
    k_bnsum<<<dim3(DH / 256, NCHUNK), 256>>>(h, NN, DH, part);
    k_bnfin<<<2, 256>>>(part, bn1g, bn1b, sc1, sh1, NN, DH);
    k_bnapply_b<<<2048, 256>>>(h, sc1, sh1, hbn, a2h, a2l, NN, DH, DX, DH);

    // layer 2 (2-term)
    k_agg_b<<<NN, 128>>>(hbn, DH, off, csr, a2h, a2l, DX, 0);
    {
        dim3 g(DOUT / 128, (NN + 127) / 128);
        k_gemm_bb<2, 0><<<g, 256>>>(a2h, a2l, w2h, nullptr, b2l, out_gnn, NN, DOUT, DX, DOUT);
    }
    k_bnsum<<<dim3(DOUT / 256, NCHUNK), 256>>>(out_gnn, NN, DOUT, part);
    k_bnfin<<<2, 256>>>(part, bng, bnb, sc2, sh2, NN, DOUT);

    // fused BN apply + build x
    k_bnbuildx<<<2048, 256>>>(out_gnn, sc2, sh2, h1c, h2c, ls, ld, out_x, xh, xl);

    // pair branch: U16 = x @ bcat^T (1-term pure fp16, fp16 output)
    {
        dim3 g(4096 / 128, (NN + 127) / 128);
        k_gemm_bb<1, 1><<<g, 256>>>(xh, nullptr, bch, nullptr, nullptr, U16,
                                    NN, 4096, DX, 4096);
    }
    k_pairln_g<<<NP, 256>>>(U16, psrc, pdst, bp, plng, plnb, z2h, z2l);
    // heads: fp16 MMA (2-term), split-write to out_pl/out_pc
    {
        dim3 g(1, (NP + 127) / 128);
        k_gemm_h64<<<g, 256>>>(z2h, z2l, wpeh, bpe, out_pl, out_pc, NP, 42, DZ);
    }

    // node branch (1-term)
    {
        dim3 g(DOUT / 128, (NN + 127) / 128);
        k_gemm_bb<1, 0><<<g, 256>>>(xh, nullptr, wnh, nullptr, bnm, tbuf,
                                    NN, DOUT, DX, DOUT);
    }
    k_nodeln<<<NN, 128>>>(tbuf, nlng, nlnb, x1r);
    {
        dim3 g(1, (NN + 127) / 128);
        k_gemm_sk<<<g, 256>>>(x1r, Wnc, bnc, out_node, NN, NC, DOUT, NC);
    }
}